// round 7
// baseline (speedup 1.0000x reference)
#include <cuda_runtime.h>
#include <cuda_bf16.h>
#include <cstdint>
#include <math.h>

#define DM   1024
#define NH   16
#define HD   64
#define SEQ  2048
#define NB   4
#define MTOT (NB * SEQ)   // 8192

// ---------------- scratch (device globals: allocation-free rule) ------------
__device__ __nv_bfloat16 g_qh[(size_t)NB * NH * SEQ * HD];
__device__ __nv_bfloat16 g_ql[(size_t)NB * NH * SEQ * HD];
__device__ __nv_bfloat16 g_kh[(size_t)NB * NH * SEQ * HD];
__device__ __nv_bfloat16 g_kl[(size_t)NB * NH * SEQ * HD];
__device__ __nv_bfloat16 g_vh[(size_t)NB * NH * SEQ * HD];
__device__ __nv_bfloat16 g_vl[(size_t)NB * NH * SEQ * HD];

__device__ __nv_bfloat16 g_ah[(size_t)3 * MTOT * DM];
__device__ __nv_bfloat16 g_al[(size_t)3 * MTOT * DM];
__device__ __nv_bfloat16 g_wh[(size_t)4 * DM * DM];
__device__ __nv_bfloat16 g_wl[(size_t)4 * DM * DM];
__device__ __nv_bfloat16 g_aoh[(size_t)MTOT * DM];
__device__ __nv_bfloat16 g_aol[(size_t)MTOT * DM];

// ============================ helpers =======================================
__device__ __forceinline__ uint32_t smem_u32(const void* p) {
    uint32_t a;
    asm("{ .reg .u64 t; cvta.to.shared.u64 t, %1; cvt.u32.u64 %0, t; }"
        : "=r"(a) : "l"(p));
    return a;
}
__device__ __forceinline__ void cp_async16(uint32_t s, const void* g) {
    asm volatile("cp.async.cg.shared.global [%0], [%1], 16;" :: "r"(s), "l"(g));
}
__device__ __forceinline__ void cp_commit() {
    asm volatile("cp.async.commit_group;");
}
__device__ __forceinline__ void cp_wait1() {
    asm volatile("cp.async.wait_group 1;");
}
__device__ __forceinline__ void cp_wait0() {
    asm volatile("cp.async.wait_group 0;");
}
__device__ __forceinline__ void ldsm4(uint32_t* r, uint32_t addr) {
    asm volatile("ldmatrix.sync.aligned.m8n8.x4.shared.b16 {%0,%1,%2,%3}, [%4];"
                 : "=r"(r[0]), "=r"(r[1]), "=r"(r[2]), "=r"(r[3]) : "r"(addr));
}
__device__ __forceinline__ void mma_bf16(float* d, const uint32_t* a,
                                         const uint32_t* b) {
    asm volatile(
        "mma.sync.aligned.m16n8k16.row.col.f32.bf16.bf16.f32 "
        "{%0,%1,%2,%3},{%4,%5,%6,%7},{%8,%9},{%0,%1,%2,%3};"
        : "+f"(d[0]), "+f"(d[1]), "+f"(d[2]), "+f"(d[3])
        : "r"(a[0]), "r"(a[1]), "r"(a[2]), "r"(a[3]), "r"(b[0]), "r"(b[1]));
}
// FMA-pipe exp2 (no MUFU). |err| ~3e-6 rel.
__device__ __forceinline__ float fexp2(float x) {
    x = fmaxf(x, -125.0f);
    int i = __float2int_rn(x);
    float f = x - (float)i;
    float p = 0.0013333558f;
    p = fmaf(p, f, 0.0096181291f);
    p = fmaf(p, f, 0.0555041087f);
    p = fmaf(p, f, 0.2402265070f);
    p = fmaf(p, f, 0.6931471806f);
    p = fmaf(p, f, 1.0f);
    return p * __int_as_float((i + 127) << 23);
}
#define LOG2E 1.4426950408889634f

__device__ __forceinline__ void split1(float x, __nv_bfloat16& h, __nv_bfloat16& l) {
    h = __float2bfloat16(x);
    l = __float2bfloat16(x - __bfloat162float(h));
}
__device__ __forceinline__ void split_pack(float a, float b, uint32_t& hw, uint32_t& lw) {
    __nv_bfloat16 ha, la, hb, lb;
    split1(a, ha, la);
    split1(b, hb, lb);
    __nv_bfloat162 h2(ha, hb), l2(la, lb);
    hw = *reinterpret_cast<uint32_t*>(&h2);
    lw = *reinterpret_cast<uint32_t*>(&l2);
}

// ====================== bf16x3 HMMA GEMM: 128x128x32, 512 thr ===============
// 16 warps as 4x4; warp tile 32x32. C = A * B^T, B stored [N,K].
#define ST_STRIDE 80
#define OP_BYTES (128 * ST_STRIDE)
#define STAGE_BYTES (4 * OP_BYTES)
#define GEMM_SMEM (2 * STAGE_BYTES)

__device__ __forceinline__ void load_stage_gemm(
    char* sm, int stage, const __nv_bfloat16* __restrict__ Ah,
    const __nv_bfloat16* __restrict__ Al, const __nv_bfloat16* __restrict__ Bh,
    const __nv_bfloat16* __restrict__ Bl, int row0, int col0, int k0, int tid) {
    const __nv_bfloat16* srcs[4] = {Ah, Al, Bh, Bl};
    uint32_t sbase = smem_u32(sm) + stage * STAGE_BYTES;
#pragma unroll
    for (int l = 0; l < 4; l++) {
        int f = tid + l * 512;                 // 0..2047
        int op = f >> 9, rem = f & 511;
        int row = rem >> 2, kc = rem & 3;
        int rb = (op < 2) ? row0 : col0;
        const __nv_bfloat16* g = srcs[op] + (size_t)(rb + row) * DM + k0 + kc * 8;
        cp_async16(sbase + op * OP_BYTES + row * ST_STRIDE + kc * 16, g);
    }
}

// MODE 0: fp32 out [M,DM].  MODE 1: bf16 hi/lo out, BHTD scatter, with scale.
template <int MODE>
__device__ __forceinline__ void gemm_body(const __nv_bfloat16* __restrict__ Ah,
                                          const __nv_bfloat16* __restrict__ Al,
                                          const __nv_bfloat16* __restrict__ Bh,
                                          const __nv_bfloat16* __restrict__ Bl,
                                          float* __restrict__ Cf,
                                          __nv_bfloat16* __restrict__ Chi,
                                          __nv_bfloat16* __restrict__ Clo,
                                          float scale, int row0, int col0) {
    extern __shared__ char sm[];
    const uint32_t sb = smem_u32(sm);
    const int tid = threadIdx.x;
    const int lane = tid & 31;
    const int w = tid >> 5;          // 0..15
    const int wm = w & 3;            // 4 m-warps (32 rows each)
    const int wn = w >> 2;           // 4 n-warps (32 cols each)

    float acc[2][4][4];
#pragma unroll
    for (int mi = 0; mi < 2; mi++)
#pragma unroll
        for (int ni = 0; ni < 4; ni++)
#pragma unroll
            for (int e = 0; e < 4; e++) acc[mi][ni][e] = 0.f;

    const int a_off = (wm * 32 + (lane & 15)) * ST_STRIDE + (lane >> 4) * 16;
    const int b_off = (wn * 32 + (lane & 7) + ((lane >> 4) << 3)) * ST_STRIDE +
                      ((lane >> 3) & 1) * 16;

    load_stage_gemm(sm, 0, Ah, Al, Bh, Bl, row0, col0, 0, tid);
    cp_commit();
    load_stage_gemm(sm, 1, Ah, Al, Bh, Bl, row0, col0, 32, tid);
    cp_commit();

    const int NIT = DM / 32;
    for (int i = 0; i < NIT; i++) {
        cp_wait1();
        __syncthreads();
        const int s = i & 1;
        const uint32_t sbase = sb + s * STAGE_BYTES;
#pragma unroll
        for (int ks = 0; ks < 2; ks++) {
            uint32_t ah[2][4], al[2][4], bh[8], bl[8];
            const uint32_t abase = sbase + a_off + ks * 32;
            const uint32_t bbase = sbase + 2 * OP_BYTES + b_off + ks * 32;
#pragma unroll
            for (int mi = 0; mi < 2; mi++) {
                ldsm4(ah[mi], abase + mi * 16 * ST_STRIDE);
                ldsm4(al[mi], abase + mi * 16 * ST_STRIDE + OP_BYTES);
            }
#pragma unroll
            for (int p = 0; p < 2; p++) {
                ldsm4(&bh[p * 4], bbase + p * 16 * ST_STRIDE);
                ldsm4(&bl[p * 4], bbase + p * 16 * ST_STRIDE + OP_BYTES);
            }
#pragma unroll
            for (int mi = 0; mi < 2; mi++)
#pragma unroll
                for (int ni = 0; ni < 4; ni++) {
                    const uint32_t* fh = &bh[(ni >> 1) * 4 + (ni & 1) * 2];
                    const uint32_t* fl = &bl[(ni >> 1) * 4 + (ni & 1) * 2];
                    mma_bf16(acc[mi][ni], ah[mi], fh);
                    mma_bf16(acc[mi][ni], ah[mi], fl);
                    mma_bf16(acc[mi][ni], al[mi], fh);
                }
        }
        __syncthreads();
        if (i + 2 < NIT)
            load_stage_gemm(sm, s, Ah, Al, Bh, Bl, row0, col0, (i + 2) * 32, tid);
        cp_commit();
    }

    const int grp = lane >> 2;
    const int tig = lane & 3;
#pragma unroll
    for (int mi = 0; mi < 2; mi++) {
#pragma unroll
        for (int ni = 0; ni < 4; ni++) {
            int col = col0 + wn * 32 + ni * 8 + tig * 2;
            int rlo = row0 + wm * 32 + mi * 16 + grp;
            int rhi = rlo + 8;
            if (MODE == 0) {
                *reinterpret_cast<float2*>(Cf + (size_t)rlo * DM + col) =
                    make_float2(acc[mi][ni][0], acc[mi][ni][1]);
                *reinterpret_cast<float2*>(Cf + (size_t)rhi * DM + col) =
                    make_float2(acc[mi][ni][2], acc[mi][ni][3]);
            } else {
                int h = col >> 6, dh = col & (HD - 1);
                int b0 = rlo >> 11, t0 = rlo & (SEQ - 1);
                int b1 = rhi >> 11, t1 = rhi & (SEQ - 1);
                size_t i0 = (((size_t)(b0 * NH + h)) * SEQ + t0) * HD + dh;
                size_t i1 = (((size_t)(b1 * NH + h)) * SEQ + t1) * HD + dh;
                uint32_t hw, lw;
                split_pack(acc[mi][ni][0] * scale, acc[mi][ni][1] * scale, hw, lw);
                *reinterpret_cast<uint32_t*>(Chi + i0) = hw;
                *reinterpret_cast<uint32_t*>(Clo + i0) = lw;
                split_pack(acc[mi][ni][2] * scale, acc[mi][ni][3] * scale, hw, lw);
                *reinterpret_cast<uint32_t*>(Chi + i1) = hw;
                *reinterpret_cast<uint32_t*>(Clo + i1) = lw;
            }
        }
    }
}

__global__ void __launch_bounds__(512)
gemm_qkv_kernel() {
    int z = blockIdx.z;
    const __nv_bfloat16* Ah = g_ah + (size_t)z * MTOT * DM;
    const __nv_bfloat16* Al = g_al + (size_t)z * MTOT * DM;
    const __nv_bfloat16* Bh = g_wh + (size_t)z * DM * DM;
    const __nv_bfloat16* Bl = g_wl + (size_t)z * DM * DM;
    __nv_bfloat16* Chi = (z == 0) ? g_qh : (z == 1) ? g_kh : g_vh;
    __nv_bfloat16* Clo = (z == 0) ? g_ql : (z == 1) ? g_kl : g_vl;
    float scale = (z == 0) ? 0.125f : 1.0f;
    gemm_body<1>(Ah, Al, Bh, Bl, nullptr, Chi, Clo, scale,
                 blockIdx.y * 128, blockIdx.x * 128);
}

__global__ void __launch_bounds__(512)
gemm_o_kernel(float* __restrict__ out) {
    gemm_body<0>(g_aoh, g_aol, g_wh + (size_t)3 * DM * DM,
                 g_wl + (size_t)3 * DM * DM, out, nullptr, nullptr, 1.0f,
                 blockIdx.y * 128, blockIdx.x * 128);
}

// ====================== split / transpose kernels ===========================
__global__ void __launch_bounds__(256)
split_act_kernel(const float* __restrict__ q, const float* __restrict__ k,
                 const float* __restrict__ v) {
    int z = blockIdx.z;
    const float* src = (z == 0) ? q : (z == 1) ? k : v;
    __nv_bfloat16* hi = g_ah + (size_t)z * MTOT * DM;
    __nv_bfloat16* lo = g_al + (size_t)z * MTOT * DM;
    size_t i4 = (size_t)blockIdx.x * 256 + threadIdx.x;
    float4 x = reinterpret_cast<const float4*>(src)[i4];
    uint32_t h0, l0, h1, l1;
    split_pack(x.x, x.y, h0, l0);
    split_pack(x.z, x.w, h1, l1);
    uint32_t* hp = reinterpret_cast<uint32_t*>(hi + i4 * 4);
    uint32_t* lp = reinterpret_cast<uint32_t*>(lo + i4 * 4);
    hp[0] = h0; hp[1] = h1;
    lp[0] = l0; lp[1] = l1;
}

__global__ void __launch_bounds__(256)
split_w_kernel(const float* __restrict__ Wq, const float* __restrict__ Wk,
               const float* __restrict__ Wv, const float* __restrict__ Wo) {
    __shared__ float tile[32][33];
    int z = blockIdx.z;
    const float* W = (z == 0) ? Wq : (z == 1) ? Wk : (z == 2) ? Wv : Wo;
    __nv_bfloat16* th = g_wh + (size_t)z * DM * DM;
    __nv_bfloat16* tl = g_wl + (size_t)z * DM * DM;
    int tx = threadIdx.x & 31, ty = threadIdx.x >> 5;
    int k0 = blockIdx.y * 32, n0 = blockIdx.x * 32;
#pragma unroll
    for (int i = 0; i < 4; i++)
        tile[ty + i * 8][tx] = W[(size_t)(k0 + ty + i * 8) * DM + n0 + tx];
    __syncthreads();
#pragma unroll
    for (int i = 0; i < 4; i++) {
        int n = n0 + ty + i * 8;
        int k = k0 + tx;
        __nv_bfloat16 h, l;
        split1(tile[tx][ty + i * 8], h, l);
        th[(size_t)n * DM + k] = h;
        tl[(size_t)n * DM + k] = l;
    }
}

// ====================== tensorized flash attention ==========================
// Br=64 per CTA (4 warps x 16 rows), 128 threads, 2 CTAs/SM. Bc=64 per iter.
#define FSTR 144
#define FOP  (64 * FSTR)              // 9216
#define FSTAGE (4 * FOP)              // Kh,Kl,Vth,Vtl
#define FBIAS_OFF (2 * FSTAGE)        // 73728
#define FLASH_SMEM (FBIAS_OFF + 2 * 64 * 4)

__global__ void __launch_bounds__(128, 2)
flash_kernel(const int* __restrict__ qpm, const int* __restrict__ kpm) {
    extern __shared__ char sm[];
    const uint32_t sb = smem_u32(sm);
    float* biasp = reinterpret_cast<float*>(sm + FBIAS_OFF);

    const int tid = threadIdx.x;
    const int lane = tid & 31;
    const int w = tid >> 5;                      // 0..3
    const int grp = lane >> 2;
    const int tig = lane & 3;

    const int qt = gridDim.x - 1 - blockIdx.x;   // heavy tiles first
    const int bh = blockIdx.y;
    const int b = bh >> 4;
    const int h = bh & (NH - 1);
    const size_t base = (size_t)bh * SEQ * HD;
    const int qrow0 = qt * 64;
    const int nit = qt + 1;

    // ---- load Q fragments (hi, lo), rows w*16.., pre-scaled by 1/8 ----
    uint32_t qfh[4][4], qfl[4][4];
    const int a_off = (w * 16 + (lane & 15)) * FSTR + (lane >> 4) * 16;
    {
#pragma unroll
        for (int pass = 0; pass < 2; pass++) {
            const __nv_bfloat16* src = pass == 0 ? g_qh : g_ql;
#pragma unroll
            for (int l = 0; l < 4; l++) {
                int f = tid + l * 128;           // 512 chunks: 64 rows x 8
                int row = f >> 3, c = f & 7;
                uint4 v = *reinterpret_cast<const uint4*>(
                    src + base + (size_t)(qrow0 + row) * HD + c * 8);
                *reinterpret_cast<uint4*>(sm + row * FSTR + c * 16) = v;
            }
            __syncthreads();
#pragma unroll
            for (int kd = 0; kd < 4; kd++) {
                if (pass == 0) ldsm4(qfh[kd], sb + a_off + kd * 32);
                else           ldsm4(qfl[kd], sb + a_off + kd * 32);
            }
            __syncthreads();
        }
    }

    // ---- state ----
    float o[8][4];
#pragma unroll
    for (int ni = 0; ni < 8; ni++)
#pragma unroll
        for (int e = 0; e < 4; e++) o[ni][e] = 0.f;
    float m0 = -1e30f, m1 = -1e30f, l0 = 0.f, l1 = 0.f;

    // V ldg mapping: kv0 = (tid&31)*2, dh0 = (tid>>5)*16
    const int vkv = (tid & 31) * 2;
    const int vdh = (tid >> 5) * 16;
    uint4 pvh[4], pvl[4];   // [row kv0 d0..7][row kv0 d8..15][row kv0+1 d0..7][...]

    // prefetch iter 0
    {
        const __nv_bfloat16* ph = g_vh + base + (size_t)vkv * HD + vdh;
        pvh[0] = *reinterpret_cast<const uint4*>(ph);
        pvh[1] = *reinterpret_cast<const uint4*>(ph + 8);
        pvh[2] = *reinterpret_cast<const uint4*>(ph + HD);
        pvh[3] = *reinterpret_cast<const uint4*>(ph + HD + 8);
        const __nv_bfloat16* pl = g_vl + base + (size_t)vkv * HD + vdh;
        pvl[0] = *reinterpret_cast<const uint4*>(pl);
        pvl[1] = *reinterpret_cast<const uint4*>(pl + 8);
        pvl[2] = *reinterpret_cast<const uint4*>(pl + HD);
        pvl[3] = *reinterpret_cast<const uint4*>(pl + HD + 8);
#pragma unroll
        for (int l = 0; l < 8; l++) {
            int f = tid + l * 128;               // 1024 chunks (2 ops)
            int op = f >> 9, rem = f & 511;
            int row = rem >> 3, c = rem & 7;
            const __nv_bfloat16* g =
                (op ? g_kl : g_kh) + base + (size_t)row * HD + c * 8;
            cp_async16(sb + op * FOP + row * FSTR + c * 16, g);
        }
        cp_commit();
    }

    const int b_off = ((lane & 7) + ((lane >> 4) << 3)) * FSTR +
                      ((lane >> 3) & 1) * 16;

    for (int it = 0; it < nit; it++) {
        const int s = it & 1;
        const int krow0 = it * 64;
        const uint32_t stg = sb + s * FSTAGE;

        // STS prefetched V (transposed) into this stage
        {
            const __nv_bfloat16* h0 = reinterpret_cast<const __nv_bfloat16*>(&pvh[0]);
            const __nv_bfloat16* h1 = reinterpret_cast<const __nv_bfloat16*>(&pvh[2]);
            const __nv_bfloat16* q0 = reinterpret_cast<const __nv_bfloat16*>(&pvl[0]);
            const __nv_bfloat16* q1 = reinterpret_cast<const __nv_bfloat16*>(&pvl[2]);
#pragma unroll
            for (int j = 0; j < 16; j++) {
                uint32_t wh = (uint32_t)*reinterpret_cast<const uint16_t*>(h0 + j) |
                              ((uint32_t)*reinterpret_cast<const uint16_t*>(h1 + j) << 16);
                uint32_t wl = (uint32_t)*reinterpret_cast<const uint16_t*>(q0 + j) |
                              ((uint32_t)*reinterpret_cast<const uint16_t*>(q1 + j) << 16);
                uint32_t off = (vdh + j) * FSTR + vkv * 2;
                *reinterpret_cast<uint32_t*>(sm + s * FSTAGE + 2 * FOP + off) = wh;
                *reinterpret_cast<uint32_t*>(sm + s * FSTAGE + 3 * FOP + off) = wl;
            }
        }
        if (tid < 64)
            biasp[s * 64 + tid] =
                (kpm[b * SEQ + krow0 + tid] != 0) ? 0.f : -1e30f;

        // prefetch next iter
        if (it + 1 < nit) {
            const int nk0 = (it + 1) * 64;
            const __nv_bfloat16* ph = g_vh + base + (size_t)(nk0 + vkv) * HD + vdh;
            pvh[0] = *reinterpret_cast<const uint4*>(ph);
            pvh[1] = *reinterpret_cast<const uint4*>(ph + 8);
            pvh[2] = *reinterpret_cast<const uint4*>(ph + HD);
            pvh[3] = *reinterpret_cast<const uint4*>(ph + HD + 8);
            const __nv_bfloat16* pl = g_vl + base + (size_t)(nk0 + vkv) * HD + vdh;
            pvl[0] = *reinterpret_cast<const uint4*>(pl);
            pvl[1] = *reinterpret_cast<const uint4*>(pl + 8);
            pvl[2] = *reinterpret_cast<const uint4*>(pl + HD);
            pvl[3] = *reinterpret_cast<const uint4*>(pl + HD + 8);
#pragma unroll
            for (int l = 0; l < 8; l++) {
                int f = tid + l * 128;
                int op = f >> 9, rem = f & 511;
                int row = rem >> 3, c = rem & 7;
                const __nv_bfloat16* g = (op ? g_kl : g_kh) + base +
                                         (size_t)(nk0 + row) * HD + c * 8;
                cp_async16(sb + (s ^ 1) * FSTAGE + op * FOP + row * FSTR + c * 16, g);
            }
            cp_commit();
            cp_wait1();
        } else {
            cp_wait0();
        }
        __syncthreads();

        // ---- S = Q K^T (hi/lo x3) ----
        float sc[8][4];
#pragma unroll
        for (int ni = 0; ni < 8; ni++)
#pragma unroll
            for (int e = 0; e < 4; e++) sc[ni][e] = 0.f;

#pragma unroll
        for (int kd = 0; kd < 4; kd++) {
            uint32_t kh[4][4], kl[4][4];
#pragma unroll
            for (int g = 0; g < 4; g++) {
                ldsm4(kh[g], stg + b_off + kd * 32 + g * 16 * FSTR);
                ldsm4(kl[g], stg + FOP + b_off + kd * 32 + g * 16 * FSTR);
            }
#pragma unroll
            for (int ni = 0; ni < 8; ni++) {
                const int g = ni >> 1, sel = (ni & 1) * 2;
                mma_bf16(sc[ni], qfh[kd], &kh[g][sel]);
                mma_bf16(sc[ni], qfh[kd], &kl[g][sel]);
                mma_bf16(sc[ni], qfl[kd], &kh[g][sel]);
            }
        }

        // ---- bias + causal mask ----
#pragma unroll
        for (int ni = 0; ni < 8; ni++) {
            float2 bb = *reinterpret_cast<float2*>(&biasp[s * 64 + ni * 8 + 2 * tig]);
            sc[ni][0] += bb.x; sc[ni][1] += bb.y;
            sc[ni][2] += bb.x; sc[ni][3] += bb.y;
        }
        if (krow0 + 63 > qrow0) {
            const int r0 = qrow0 + w * 16 + grp;
            const int r1 = r0 + 8;
#pragma unroll
            for (int ni = 0; ni < 8; ni++) {
                int c0 = krow0 + ni * 8 + 2 * tig;
                if (c0 > r0) sc[ni][0] = -1e30f;
                if (c0 + 1 > r0) sc[ni][1] = -1e30f;
                if (c0 > r1) sc[ni][2] = -1e30f;
                if (c0 + 1 > r1) sc[ni][3] = -1e30f;
            }
        }

        // ---- online softmax ----
        float mx0 = -1e30f, mx1 = -1e30f;
#pragma unroll
        for (int ni = 0; ni < 8; ni++) {
            mx0 = fmaxf(mx0, fmaxf(sc[ni][0], sc[ni][1]));
            mx1 = fmaxf(mx1, fmaxf(sc[ni][2], sc[ni][3]));
        }
        mx0 = fmaxf(mx0, __shfl_xor_sync(0xffffffffu, mx0, 1));
        mx0 = fmaxf(mx0, __shfl_xor_sync(0xffffffffu, mx0, 2));
        mx1 = fmaxf(mx1, __shfl_xor_sync(0xffffffffu, mx1, 1));
        mx1 = fmaxf(mx1, __shfl_xor_sync(0xffffffffu, mx1, 2));
        float mn0 = fmaxf(m0, mx0), mn1 = fmaxf(m1, mx1);
        float cr0 = fexp2((m0 - mn0) * LOG2E);
        float cr1 = fexp2((m1 - mn1) * LOG2E);
        m0 = mn0; m1 = mn1;

        uint32_t ph[8][2], pl[8][2];
        float rs0 = 0.f, rs1 = 0.f;
#pragma unroll
        for (int ni = 0; ni < 8; ni++) {
            float p0 = fexp2((sc[ni][0] - mn0) * LOG2E);
            float p1 = fexp2((sc[ni][1] - mn0) * LOG2E);
            float p2 = fexp2((sc[ni][2] - mn1) * LOG2E);
            float p3 = fexp2((sc[ni][3] - mn1) * LOG2E);
            rs0 += p0 + p1; rs1 += p2 + p3;
            split_pack(p0, p1, ph[ni][0], pl[ni][0]);
            split_pack(p2, p3, ph[ni][1], pl[ni][1]);
        }
        rs0 += __shfl_xor_sync(0xffffffffu, rs0, 1);
        rs0 += __shfl_xor_sync(0xffffffffu, rs0, 2);
        rs1 += __shfl_xor_sync(0xffffffffu, rs1, 1);
        rs1 += __shfl_xor_sync(0xffffffffu, rs1, 2);
        l0 = l0 * cr0 + rs0;
        l1 = l1 * cr1 + rs1;
#pragma unroll
        for (int ni = 0; ni < 8; ni++) {
            o[ni][0] *= cr0; o[ni][1] *= cr0;
            o[ni][2] *= cr1; o[ni][3] *= cr1;
        }

        // ---- O += P V (hi/lo x3), Vt stored [dh][kv] ----
#pragma unroll
        for (int kc = 0; kc < 4; kc++) {
            uint32_t vh[4][4], vl[4][4];
#pragma unroll
            for (int g = 0; g < 4; g++) {
                ldsm4(vh[g], stg + 2 * FOP + b_off + kc * 32 + g * 16 * FSTR);
                ldsm4(vl[g], stg + 3 * FOP + b_off + kc * 32 + g * 16 * FSTR);
            }
            uint32_t ah[4] = {ph[2 * kc][0], ph[2 * kc][1],
                              ph[2 * kc + 1][0], ph[2 * kc + 1][1]};
            uint32_t al[4] = {pl[2 * kc][0], pl[2 * kc][1],
                              pl[2 * kc + 1][0], pl[2 * kc + 1][1]};
#pragma unroll
            for (int ni = 0; ni < 8; ni++) {
                const int g = ni >> 1, sel = (ni & 1) * 2;
                mma_bf16(o[ni], ah, &vh[g][sel]);
                mma_bf16(o[ni], ah, &vl[g][sel]);
                mma_bf16(o[ni], al, &vh[g][sel]);
            }
        }
        __syncthreads();
    }

    // ---- epilogue: /l, query padding, write bf16 hi/lo to [B*T, D] ----
    const int r0 = qrow0 + w * 16 + grp;
    const int r1 = r0 + 8;
    float f0 = (l0 > 0.f ? 1.0f / l0 : 0.f) * (float)qpm[b * SEQ + r0];
    float f1 = (l1 > 0.f ? 1.0f / l1 : 0.f) * (float)qpm[b * SEQ + r1];
#pragma unroll
    for (int ni = 0; ni < 8; ni++) {
        int col = h * HD + ni * 8 + 2 * tig;
        uint32_t hw, lw;
        split_pack(o[ni][0] * f0, o[ni][1] * f0, hw, lw);
        size_t i0 = (size_t)(b * SEQ + r0) * DM + col;
        *reinterpret_cast<uint32_t*>(g_aoh + i0) = hw;
        *reinterpret_cast<uint32_t*>(g_aol + i0) = lw;
        split_pack(o[ni][2] * f1, o[ni][3] * f1, hw, lw);
        size_t i1 = (size_t)(b * SEQ + r1) * DM + col;
        *reinterpret_cast<uint32_t*>(g_aoh + i1) = hw;
        *reinterpret_cast<uint32_t*>(g_aol + i1) = lw;
    }
}

// ---------------- launch -----------------------------------------------------
extern "C" void kernel_launch(void* const* d_in, const int* in_sizes, int n_in,
                              void* d_out, int out_size) {
    const float* q   = (const float*)d_in[0];
    const float* k   = (const float*)d_in[1];
    const float* v   = (const float*)d_in[2];
    const int*   qpm = (const int*)d_in[3];
    const int*   kpm = (const int*)d_in[4];
    const float* Wq  = (const float*)d_in[5];
    const float* Wk  = (const float*)d_in[6];
    const float* Wv  = (const float*)d_in[7];
    const float* Wo  = (const float*)d_in[8];
    float* out = (float*)d_out;

    dim3 gs((MTOT * DM) / (256 * 4), 1, 3);
    split_act_kernel<<<gs, 256>>>(q, k, v);
    split_w_kernel<<<dim3(32, 32, 4), 256>>>(Wq, Wk, Wv, Wo);

    cudaFuncSetAttribute(gemm_qkv_kernel,
                         cudaFuncAttributeMaxDynamicSharedMemorySize, GEMM_SMEM);
    cudaFuncSetAttribute(gemm_o_kernel,
                         cudaFuncAttributeMaxDynamicSharedMemorySize, GEMM_SMEM);
    gemm_qkv_kernel<<<dim3(DM / 128, MTOT / 128, 3), 512, GEMM_SMEM>>>();

    cudaFuncSetAttribute(flash_kernel,
                         cudaFuncAttributeMaxDynamicSharedMemorySize, FLASH_SMEM);
    flash_kernel<<<dim3(SEQ / 64, NB * NH), 128, FLASH_SMEM>>>(qpm, kpm);

    gemm_o_kernel<<<dim3(DM / 128, MTOT / 128), 512, GEMM_SMEM>>>(out);
}

// round 8
// speedup vs baseline: 1.1132x; 1.1132x over previous
#include <cuda_runtime.h>
#include <cuda_bf16.h>
#include <cstdint>
#include <math.h>

#define DM   1024
#define NH   16
#define HD   64
#define SEQ  2048
#define NB   4
#define MTOT (NB * SEQ)   // 8192

// ---------------- scratch (device globals: allocation-free rule) ------------
__device__ __nv_bfloat16 g_qh[(size_t)NB * NH * SEQ * HD];
__device__ __nv_bfloat16 g_ql[(size_t)NB * NH * SEQ * HD];
__device__ __nv_bfloat16 g_kh[(size_t)NB * NH * SEQ * HD];
__device__ __nv_bfloat16 g_kl[(size_t)NB * NH * SEQ * HD];
__device__ __nv_bfloat16 g_vh[(size_t)NB * NH * SEQ * HD];
__device__ __nv_bfloat16 g_vl[(size_t)NB * NH * SEQ * HD];

__device__ __nv_bfloat16 g_ah[(size_t)3 * MTOT * DM];
__device__ __nv_bfloat16 g_al[(size_t)3 * MTOT * DM];
__device__ __nv_bfloat16 g_wh[(size_t)4 * DM * DM];
__device__ __nv_bfloat16 g_wl[(size_t)4 * DM * DM];
__device__ __nv_bfloat16 g_aoh[(size_t)MTOT * DM];
__device__ __nv_bfloat16 g_aol[(size_t)MTOT * DM];

// ============================ helpers =======================================
__device__ __forceinline__ uint32_t smem_u32(const void* p) {
    uint32_t a;
    asm("{ .reg .u64 t; cvta.to.shared.u64 t, %1; cvt.u32.u64 %0, t; }"
        : "=r"(a) : "l"(p));
    return a;
}
__device__ __forceinline__ void cp_async16(uint32_t s, const void* g) {
    asm volatile("cp.async.cg.shared.global [%0], [%1], 16;" :: "r"(s), "l"(g));
}
__device__ __forceinline__ void cp_commit() {
    asm volatile("cp.async.commit_group;");
}
__device__ __forceinline__ void cp_wait1() {
    asm volatile("cp.async.wait_group 1;");
}
__device__ __forceinline__ void cp_wait0() {
    asm volatile("cp.async.wait_group 0;");
}
__device__ __forceinline__ void ldsm4(uint32_t* r, uint32_t addr) {
    asm volatile("ldmatrix.sync.aligned.m8n8.x4.shared.b16 {%0,%1,%2,%3}, [%4];"
                 : "=r"(r[0]), "=r"(r[1]), "=r"(r[2]), "=r"(r[3]) : "r"(addr));
}
__device__ __forceinline__ void ldsm4t(uint32_t* r, uint32_t addr) {
    asm volatile("ldmatrix.sync.aligned.m8n8.x4.trans.shared.b16 {%0,%1,%2,%3}, [%4];"
                 : "=r"(r[0]), "=r"(r[1]), "=r"(r[2]), "=r"(r[3]) : "r"(addr));
}
__device__ __forceinline__ void mma_bf16(float* d, const uint32_t* a,
                                         const uint32_t* b) {
    asm volatile(
        "mma.sync.aligned.m16n8k16.row.col.f32.bf16.bf16.f32 "
        "{%0,%1,%2,%3},{%4,%5,%6,%7},{%8,%9},{%0,%1,%2,%3};"
        : "+f"(d[0]), "+f"(d[1]), "+f"(d[2]), "+f"(d[3])
        : "r"(a[0]), "r"(a[1]), "r"(a[2]), "r"(a[3]), "r"(b[0]), "r"(b[1]));
}
// FMA-pipe exp2 (no MUFU). |err| ~3e-6 rel.
__device__ __forceinline__ float fexp2(float x) {
    x = fmaxf(x, -125.0f);
    int i = __float2int_rn(x);
    float f = x - (float)i;
    float p = 0.0013333558f;
    p = fmaf(p, f, 0.0096181291f);
    p = fmaf(p, f, 0.0555041087f);
    p = fmaf(p, f, 0.2402265070f);
    p = fmaf(p, f, 0.6931471806f);
    p = fmaf(p, f, 1.0f);
    return p * __int_as_float((i + 127) << 23);
}
#define LOG2E 1.4426950408889634f

__device__ __forceinline__ void split1(float x, __nv_bfloat16& h, __nv_bfloat16& l) {
    h = __float2bfloat16(x);
    l = __float2bfloat16(x - __bfloat162float(h));
}
__device__ __forceinline__ void split_pack(float a, float b, uint32_t& hw, uint32_t& lw) {
    __nv_bfloat16 ha, la, hb, lb;
    split1(a, ha, la);
    split1(b, hb, lb);
    __nv_bfloat162 h2(ha, hb), l2(la, lb);
    hw = *reinterpret_cast<uint32_t*>(&h2);
    lw = *reinterpret_cast<uint32_t*>(&l2);
}

// ====================== bf16x3 HMMA GEMM: 256x128x32, 512 thr ===============
// 16 warps as 4(m) x 4(n); warp tile 64x32. C = A * B^T, B stored [N,K].
#define ST_STRIDE 80
#define A_OP_BYTES (256 * ST_STRIDE)          // 20480
#define B_OP_BYTES (128 * ST_STRIDE)          // 10240
#define STAGE_BYTES (2 * A_OP_BYTES + 2 * B_OP_BYTES)   // 61440
#define GEMM_SMEM (2 * STAGE_BYTES)           // 122880

__device__ __forceinline__ void load_stage_gemm(
    char* sm, int stage, const __nv_bfloat16* __restrict__ Ah,
    const __nv_bfloat16* __restrict__ Al, const __nv_bfloat16* __restrict__ Bh,
    const __nv_bfloat16* __restrict__ Bl, int row0, int col0, int k0, int tid) {
    uint32_t sbase = smem_u32(sm) + stage * STAGE_BYTES;
#pragma unroll
    for (int l = 0; l < 6; l++) {
        int f = tid + l * 512;                 // 0..3071 chunks of 16B
        if (f < 2048) {                        // A: hi(1024) + lo(1024)
            int op = f >> 10, rem = f & 1023;
            int row = rem >> 2, kc = rem & 3;
            const __nv_bfloat16* g =
                (op ? Al : Ah) + (size_t)(row0 + row) * DM + k0 + kc * 8;
            cp_async16(sbase + op * A_OP_BYTES + row * ST_STRIDE + kc * 16, g);
        } else {                               // B: hi(512) + lo(512)
            int gg = f - 2048;
            int op = gg >> 9, rem = gg & 511;
            int row = rem >> 2, kc = rem & 3;
            const __nv_bfloat16* g =
                (op ? Bl : Bh) + (size_t)(col0 + row) * DM + k0 + kc * 8;
            cp_async16(sbase + 2 * A_OP_BYTES + op * B_OP_BYTES +
                       row * ST_STRIDE + kc * 16, g);
        }
    }
}

// MODE 0: fp32 out [M,DM].  MODE 1: bf16 hi/lo out, BHTD scatter, with scale.
template <int MODE>
__device__ __forceinline__ void gemm_body(const __nv_bfloat16* __restrict__ Ah,
                                          const __nv_bfloat16* __restrict__ Al,
                                          const __nv_bfloat16* __restrict__ Bh,
                                          const __nv_bfloat16* __restrict__ Bl,
                                          float* __restrict__ Cf,
                                          __nv_bfloat16* __restrict__ Chi,
                                          __nv_bfloat16* __restrict__ Clo,
                                          float scale, int row0, int col0) {
    extern __shared__ char sm[];
    const uint32_t sb = smem_u32(sm);
    const int tid = threadIdx.x;
    const int lane = tid & 31;
    const int w = tid >> 5;          // 0..15
    const int wm = w & 3;            // 4 m-warps (64 rows each)
    const int wn = w >> 2;           // 4 n-warps (32 cols each)

    float acc[4][4][4];
#pragma unroll
    for (int mi = 0; mi < 4; mi++)
#pragma unroll
        for (int ni = 0; ni < 4; ni++)
#pragma unroll
            for (int e = 0; e < 4; e++) acc[mi][ni][e] = 0.f;

    const int a_off = (wm * 64 + (lane & 15)) * ST_STRIDE + (lane >> 4) * 16;
    const int b_off = (wn * 32 + (lane & 7) + ((lane >> 4) << 3)) * ST_STRIDE +
                      ((lane >> 3) & 1) * 16;

    load_stage_gemm(sm, 0, Ah, Al, Bh, Bl, row0, col0, 0, tid);
    cp_commit();
    load_stage_gemm(sm, 1, Ah, Al, Bh, Bl, row0, col0, 32, tid);
    cp_commit();

    const int NIT = DM / 32;   // 32
    for (int i = 0; i < NIT; i++) {
        cp_wait1();
        __syncthreads();
        const int s = i & 1;
        const uint32_t sbase = sb + s * STAGE_BYTES;
#pragma unroll
        for (int ks = 0; ks < 2; ks++) {
            uint32_t ah[4][4], al[4][4], bh[8], bl[8];
            const uint32_t abase = sbase + a_off + ks * 32;
            const uint32_t bbase = sbase + 2 * A_OP_BYTES + b_off + ks * 32;
#pragma unroll
            for (int mi = 0; mi < 4; mi++) {
                ldsm4(ah[mi], abase + mi * 16 * ST_STRIDE);
                ldsm4(al[mi], abase + mi * 16 * ST_STRIDE + A_OP_BYTES);
            }
#pragma unroll
            for (int p = 0; p < 2; p++) {
                ldsm4(&bh[p * 4], bbase + p * 16 * ST_STRIDE);
                ldsm4(&bl[p * 4], bbase + p * 16 * ST_STRIDE + B_OP_BYTES);
            }
#pragma unroll
            for (int mi = 0; mi < 4; mi++)
#pragma unroll
                for (int ni = 0; ni < 4; ni++) {
                    const uint32_t* fh = &bh[(ni >> 1) * 4 + (ni & 1) * 2];
                    const uint32_t* fl = &bl[(ni >> 1) * 4 + (ni & 1) * 2];
                    mma_bf16(acc[mi][ni], ah[mi], fh);
                    mma_bf16(acc[mi][ni], ah[mi], fl);
                    mma_bf16(acc[mi][ni], al[mi], fh);
                }
        }
        __syncthreads();
        if (i + 2 < NIT)
            load_stage_gemm(sm, s, Ah, Al, Bh, Bl, row0, col0, (i + 2) * 32, tid);
        cp_commit();
    }

    const int grp = lane >> 2;
    const int tig = lane & 3;
#pragma unroll
    for (int mi = 0; mi < 4; mi++) {
#pragma unroll
        for (int ni = 0; ni < 4; ni++) {
            int col = col0 + wn * 32 + ni * 8 + tig * 2;
            int rlo = row0 + wm * 64 + mi * 16 + grp;
            int rhi = rlo + 8;
            if (MODE == 0) {
                *reinterpret_cast<float2*>(Cf + (size_t)rlo * DM + col) =
                    make_float2(acc[mi][ni][0], acc[mi][ni][1]);
                *reinterpret_cast<float2*>(Cf + (size_t)rhi * DM + col) =
                    make_float2(acc[mi][ni][2], acc[mi][ni][3]);
            } else {
                int h = col >> 6, dh = col & (HD - 1);
                int b0 = rlo >> 11, t0 = rlo & (SEQ - 1);
                int b1 = rhi >> 11, t1 = rhi & (SEQ - 1);
                size_t i0 = (((size_t)(b0 * NH + h)) * SEQ + t0) * HD + dh;
                size_t i1 = (((size_t)(b1 * NH + h)) * SEQ + t1) * HD + dh;
                uint32_t hw, lw;
                split_pack(acc[mi][ni][0] * scale, acc[mi][ni][1] * scale, hw, lw);
                *reinterpret_cast<uint32_t*>(Chi + i0) = hw;
                *reinterpret_cast<uint32_t*>(Clo + i0) = lw;
                split_pack(acc[mi][ni][2] * scale, acc[mi][ni][3] * scale, hw, lw);
                *reinterpret_cast<uint32_t*>(Chi + i1) = hw;
                *reinterpret_cast<uint32_t*>(Clo + i1) = lw;
            }
        }
    }
}

__global__ void __launch_bounds__(512, 1)
gemm_qkv_kernel() {
    int z = blockIdx.z;
    const __nv_bfloat16* Ah = g_ah + (size_t)z * MTOT * DM;
    const __nv_bfloat16* Al = g_al + (size_t)z * MTOT * DM;
    const __nv_bfloat16* Bh = g_wh + (size_t)z * DM * DM;
    const __nv_bfloat16* Bl = g_wl + (size_t)z * DM * DM;
    __nv_bfloat16* Chi = (z == 0) ? g_qh : (z == 1) ? g_kh : g_vh;
    __nv_bfloat16* Clo = (z == 0) ? g_ql : (z == 1) ? g_kl : g_vl;
    float scale = (z == 0) ? 0.125f : 1.0f;
    gemm_body<1>(Ah, Al, Bh, Bl, nullptr, Chi, Clo, scale,
                 blockIdx.y * 256, blockIdx.x * 128);
}

__global__ void __launch_bounds__(512, 1)
gemm_o_kernel(float* __restrict__ out) {
    gemm_body<0>(g_aoh, g_aol, g_wh + (size_t)3 * DM * DM,
                 g_wl + (size_t)3 * DM * DM, out, nullptr, nullptr, 1.0f,
                 blockIdx.y * 256, blockIdx.x * 128);
}

// ====================== split / transpose kernels ===========================
__global__ void __launch_bounds__(256)
split_act_kernel(const float* __restrict__ q, const float* __restrict__ k,
                 const float* __restrict__ v) {
    int z = blockIdx.z;
    const float* src = (z == 0) ? q : (z == 1) ? k : v;
    __nv_bfloat16* hi = g_ah + (size_t)z * MTOT * DM;
    __nv_bfloat16* lo = g_al + (size_t)z * MTOT * DM;
    size_t i4 = (size_t)blockIdx.x * 256 + threadIdx.x;
    float4 x = reinterpret_cast<const float4*>(src)[i4];
    uint32_t h0, l0, h1, l1;
    split_pack(x.x, x.y, h0, l0);
    split_pack(x.z, x.w, h1, l1);
    uint32_t* hp = reinterpret_cast<uint32_t*>(hi + i4 * 4);
    uint32_t* lp = reinterpret_cast<uint32_t*>(lo + i4 * 4);
    hp[0] = h0; hp[1] = h1;
    lp[0] = l0; lp[1] = l1;
}

__global__ void __launch_bounds__(256)
split_w_kernel(const float* __restrict__ Wq, const float* __restrict__ Wk,
               const float* __restrict__ Wv, const float* __restrict__ Wo) {
    __shared__ float tile[32][33];
    int z = blockIdx.z;
    const float* W = (z == 0) ? Wq : (z == 1) ? Wk : (z == 2) ? Wv : Wo;
    __nv_bfloat16* th = g_wh + (size_t)z * DM * DM;
    __nv_bfloat16* tl = g_wl + (size_t)z * DM * DM;
    int tx = threadIdx.x & 31, ty = threadIdx.x >> 5;
    int k0 = blockIdx.y * 32, n0 = blockIdx.x * 32;
#pragma unroll
    for (int i = 0; i < 4; i++)
        tile[ty + i * 8][tx] = W[(size_t)(k0 + ty + i * 8) * DM + n0 + tx];
    __syncthreads();
#pragma unroll
    for (int i = 0; i < 4; i++) {
        int n = n0 + ty + i * 8;
        int k = k0 + tx;
        __nv_bfloat16 h, l;
        split1(tile[tx][ty + i * 8], h, l);
        th[(size_t)n * DM + k] = h;
        tl[(size_t)n * DM + k] = l;
    }
}

// ====================== tensorized flash attention ==========================
// Br=128 per CTA (8 warps x 16 rows), 256 threads, 2 CTAs/SM. Bc=64 per iter.
// Q resident in smem (fragments reloaded per iter); K,V hi/lo via cp.async;
// PV B-fragments via ldmatrix.trans on natural [kv][dh] layout.
#define FSTR 144
#define FOP  (64 * FSTR)              // 9216
#define FSTAGE (4 * FOP)              // 36864: Kh,Kl,Vh,Vl
#define QOFF (2 * FSTAGE)             // 73728
#define QOP  (128 * FSTR)             // 18432
#define FBIAS (QOFF + 2 * QOP)        // 110592
#define FLASH_SMEM (FBIAS + 2 * 64 * 4)   // 111104

__global__ void __launch_bounds__(256, 2)
flash_kernel(const int* __restrict__ qpm, const int* __restrict__ kpm) {
    extern __shared__ char sm[];
    const uint32_t sb = smem_u32(sm);
    float* biasp = reinterpret_cast<float*>(sm + FBIAS);

    const int tid = threadIdx.x;
    const int lane = tid & 31;
    const int w = tid >> 5;                      // 0..7
    const int grp = lane >> 2;
    const int tig = lane & 3;

    const int qt = gridDim.x - 1 - blockIdx.x;   // heavy tiles first
    const int bh = blockIdx.y;
    const int b = bh >> 4;
    const int h = bh & (NH - 1);
    const size_t base = (size_t)bh * SEQ * HD;
    const int qrow0 = qt * 128;
    const int nit = 2 * qt + 2;

    // ---- Q (hi, lo) -> resident smem ----
#pragma unroll
    for (int pass = 0; pass < 2; pass++) {
        const __nv_bfloat16* src = pass ? g_ql : g_qh;
#pragma unroll
        for (int l = 0; l < 4; l++) {
            int f = tid + l * 256;               // 1024 chunks: 128 rows x 8
            int row = f >> 3, c = f & 7;
            uint4 v = *reinterpret_cast<const uint4*>(
                src + base + (size_t)(qrow0 + row) * HD + c * 8);
            *reinterpret_cast<uint4*>(sm + QOFF + pass * QOP + row * FSTR + c * 16) = v;
        }
    }

    // ---- prefetch K/V iter 0 (Kh,Kl,Vh,Vl; 2048 chunks) ----
#pragma unroll
    for (int l = 0; l < 8; l++) {
        int f = tid + l * 256;
        int op = f >> 9, rem = f & 511;
        int row = rem >> 3, c = rem & 7;
        const __nv_bfloat16* g =
            (op == 0 ? g_kh : op == 1 ? g_kl : op == 2 ? g_vh : g_vl) +
            base + (size_t)row * HD + c * 8;
        cp_async16(sb + op * FOP + row * FSTR + c * 16, g);
    }
    cp_commit();

    // ---- state ----
    float o[8][4];
#pragma unroll
    for (int ni = 0; ni < 8; ni++)
#pragma unroll
        for (int e = 0; e < 4; e++) o[ni][e] = 0.f;
    float m0 = -1e30f, m1 = -1e30f, l0 = 0.f, l1 = 0.f;

    const int a_off = (w * 16 + (lane & 15)) * FSTR + (lane >> 4) * 16;
    const int b_off = ((lane & 7) + ((lane >> 4) << 3)) * FSTR +
                      ((lane >> 3) & 1) * 16;
    const int t_off = (lane & 15) * FSTR + ((lane >> 4) << 3) * 2;  // trans ldsm

    for (int it = 0; it < nit; it++) {
        const int s = it & 1;
        const int krow0 = it * 64;
        const uint32_t stg = sb + s * FSTAGE;

        if (tid < 64)
            biasp[s * 64 + tid] =
                (kpm[b * SEQ + krow0 + tid] != 0) ? 0.f : -1e30f;

        if (it + 1 < nit) {
            const int nk0 = (it + 1) * 64;
#pragma unroll
            for (int l = 0; l < 8; l++) {
                int f = tid + l * 256;
                int op = f >> 9, rem = f & 511;
                int row = rem >> 3, c = rem & 7;
                const __nv_bfloat16* g =
                    (op == 0 ? g_kh : op == 1 ? g_kl : op == 2 ? g_vh : g_vl) +
                    base + (size_t)(nk0 + row) * HD + c * 8;
                cp_async16(sb + (s ^ 1) * FSTAGE + op * FOP + row * FSTR + c * 16, g);
            }
            cp_commit();
            cp_wait1();
        } else {
            cp_wait0();
        }
        __syncthreads();

        // ---- S = Q K^T (hi/lo x3), Q fragments reloaded from smem ----
        float sc[8][4];
#pragma unroll
        for (int ni = 0; ni < 8; ni++)
#pragma unroll
            for (int e = 0; e < 4; e++) sc[ni][e] = 0.f;

#pragma unroll
        for (int kd = 0; kd < 4; kd++) {
            uint32_t qfh[4], qfl[4];
            ldsm4(qfh, sb + QOFF + a_off + kd * 32);
            ldsm4(qfl, sb + QOFF + QOP + a_off + kd * 32);
            uint32_t kh[4][4], kl[4][4];
#pragma unroll
            for (int g = 0; g < 4; g++) {
                ldsm4(kh[g], stg + b_off + kd * 32 + g * 16 * FSTR);
                ldsm4(kl[g], stg + FOP + b_off + kd * 32 + g * 16 * FSTR);
            }
#pragma unroll
            for (int ni = 0; ni < 8; ni++) {
                const int g = ni >> 1, sel = (ni & 1) * 2;
                mma_bf16(sc[ni], qfh, &kh[g][sel]);
                mma_bf16(sc[ni], qfh, &kl[g][sel]);
                mma_bf16(sc[ni], qfl, &kh[g][sel]);
            }
        }

        // ---- bias + causal mask ----
#pragma unroll
        for (int ni = 0; ni < 8; ni++) {
            float2 bb = *reinterpret_cast<float2*>(&biasp[s * 64 + ni * 8 + 2 * tig]);
            sc[ni][0] += bb.x; sc[ni][1] += bb.y;
            sc[ni][2] += bb.x; sc[ni][3] += bb.y;
        }
        if (krow0 + 63 > qrow0) {
            const int r0 = qrow0 + w * 16 + grp;
            const int r1 = r0 + 8;
#pragma unroll
            for (int ni = 0; ni < 8; ni++) {
                int c0 = krow0 + ni * 8 + 2 * tig;
                if (c0 > r0) sc[ni][0] = -1e30f;
                if (c0 + 1 > r0) sc[ni][1] = -1e30f;
                if (c0 > r1) sc[ni][2] = -1e30f;
                if (c0 + 1 > r1) sc[ni][3] = -1e30f;
            }
        }

        // ---- online softmax ----
        float mx0 = -1e30f, mx1 = -1e30f;
#pragma unroll
        for (int ni = 0; ni < 8; ni++) {
            mx0 = fmaxf(mx0, fmaxf(sc[ni][0], sc[ni][1]));
            mx1 = fmaxf(mx1, fmaxf(sc[ni][2], sc[ni][3]));
        }
        mx0 = fmaxf(mx0, __shfl_xor_sync(0xffffffffu, mx0, 1));
        mx0 = fmaxf(mx0, __shfl_xor_sync(0xffffffffu, mx0, 2));
        mx1 = fmaxf(mx1, __shfl_xor_sync(0xffffffffu, mx1, 1));
        mx1 = fmaxf(mx1, __shfl_xor_sync(0xffffffffu, mx1, 2));
        float mn0 = fmaxf(m0, mx0), mn1 = fmaxf(m1, mx1);
        float cr0 = fexp2((m0 - mn0) * LOG2E);
        float cr1 = fexp2((m1 - mn1) * LOG2E);
        m0 = mn0; m1 = mn1;

        uint32_t ph[8][2], pl[8][2];
        float rs0 = 0.f, rs1 = 0.f;
#pragma unroll
        for (int ni = 0; ni < 8; ni++) {
            float p0 = fexp2((sc[ni][0] - mn0) * LOG2E);
            float p1 = fexp2((sc[ni][1] - mn0) * LOG2E);
            float p2 = fexp2((sc[ni][2] - mn1) * LOG2E);
            float p3 = fexp2((sc[ni][3] - mn1) * LOG2E);
            rs0 += p0 + p1; rs1 += p2 + p3;
            split_pack(p0, p1, ph[ni][0], pl[ni][0]);
            split_pack(p2, p3, ph[ni][1], pl[ni][1]);
        }
        rs0 += __shfl_xor_sync(0xffffffffu, rs0, 1);
        rs0 += __shfl_xor_sync(0xffffffffu, rs0, 2);
        rs1 += __shfl_xor_sync(0xffffffffu, rs1, 1);
        rs1 += __shfl_xor_sync(0xffffffffu, rs1, 2);
        l0 = l0 * cr0 + rs0;
        l1 = l1 * cr1 + rs1;
#pragma unroll
        for (int ni = 0; ni < 8; ni++) {
            o[ni][0] *= cr0; o[ni][1] *= cr0;
            o[ni][2] *= cr1; o[ni][3] *= cr1;
        }

        // ---- O += P V (hi/lo x3), V in [kv][dh], B-frags via ldsm.trans ----
#pragma unroll
        for (int kc = 0; kc < 4; kc++) {
            uint32_t vh[4][4], vl[4][4];
#pragma unroll
            for (int g = 0; g < 4; g++) {
                uint32_t ta = stg + 2 * FOP + kc * 16 * FSTR + t_off + g * 32;
                ldsm4t(vh[g], ta);
                ldsm4t(vl[g], ta + FOP);
            }
            uint32_t ah[4] = {ph[2 * kc][0], ph[2 * kc][1],
                              ph[2 * kc + 1][0], ph[2 * kc + 1][1]};
            uint32_t al[4] = {pl[2 * kc][0], pl[2 * kc][1],
                              pl[2 * kc + 1][0], pl[2 * kc + 1][1]};
#pragma unroll
            for (int ni = 0; ni < 8; ni++) {
                const int g = ni >> 1, sel = (ni & 1) * 2;
                mma_bf16(o[ni], ah, &vh[g][sel]);
                mma_bf16(o[ni], ah, &vl[g][sel]);
                mma_bf16(o[ni], al, &vh[g][sel]);
            }
        }
        __syncthreads();
    }

    // ---- epilogue: /l, query padding, write bf16 hi/lo to [B*T, D] ----
    const int r0 = qrow0 + w * 16 + grp;
    const int r1 = r0 + 8;
    float f0 = (l0 > 0.f ? 1.0f / l0 : 0.f) * (float)qpm[b * SEQ + r0];
    float f1 = (l1 > 0.f ? 1.0f / l1 : 0.f) * (float)qpm[b * SEQ + r1];
#pragma unroll
    for (int ni = 0; ni < 8; ni++) {
        int col = h * HD + ni * 8 + 2 * tig;
        uint32_t hw, lw;
        split_pack(o[ni][0] * f0, o[ni][1] * f0, hw, lw);
        size_t i0 = (size_t)(b * SEQ + r0) * DM + col;
        *reinterpret_cast<uint32_t*>(g_aoh + i0) = hw;
        *reinterpret_cast<uint32_t*>(g_aol + i0) = lw;
        split_pack(o[ni][2] * f1, o[ni][3] * f1, hw, lw);
        size_t i1 = (size_t)(b * SEQ + r1) * DM + col;
        *reinterpret_cast<uint32_t*>(g_aoh + i1) = hw;
        *reinterpret_cast<uint32_t*>(g_aol + i1) = lw;
    }
}

// ---------------- launch -----------------------------------------------------
extern "C" void kernel_launch(void* const* d_in, const int* in_sizes, int n_in,
                              void* d_out, int out_size) {
    const float* q   = (const float*)d_in[0];
    const float* k   = (const float*)d_in[1];
    const float* v   = (const float*)d_in[2];
    const int*   qpm = (const int*)d_in[3];
    const int*   kpm = (const int*)d_in[4];
    const float* Wq  = (const float*)d_in[5];
    const float* Wk  = (const float*)d_in[6];
    const float* Wv  = (const float*)d_in[7];
    const float* Wo  = (const float*)d_in[8];
    float* out = (float*)d_out;

    dim3 gs((MTOT * DM) / (256 * 4), 1, 3);
    split_act_kernel<<<gs, 256>>>(q, k, v);
    split_w_kernel<<<dim3(32, 32, 4), 256>>>(Wq, Wk, Wv, Wo);

    cudaFuncSetAttribute(gemm_qkv_kernel,
                         cudaFuncAttributeMaxDynamicSharedMemorySize, GEMM_SMEM);
    cudaFuncSetAttribute(gemm_o_kernel,
                         cudaFuncAttributeMaxDynamicSharedMemorySize, GEMM_SMEM);
    gemm_qkv_kernel<<<dim3(DM / 128, MTOT / 256, 3), 512, GEMM_SMEM>>>();

    cudaFuncSetAttribute(flash_kernel,
                         cudaFuncAttributeMaxDynamicSharedMemorySize, FLASH_SMEM);
    flash_kernel<<<dim3(SEQ / 128, NB * NH), 256, FLASH_SMEM>>>(qpm, kpm);

    gemm_o_kernel<<<dim3(DM / 128, MTOT / 256), 512, GEMM_SMEM>>>(out);
}

// round 9
// speedup vs baseline: 1.2937x; 1.1622x over previous
#include <cuda_runtime.h>
#include <cuda_bf16.h>
#include <cstdint>
#include <math.h>

#define DM   1024
#define NH   16
#define HD   64
#define SEQ  2048
#define NB   4
#define MTOT (NB * SEQ)   // 8192

// ---------------- global scratch: layouts match smem staging ----------------
// Q/K/V hi/lo: [bh][t][144B] rows (72 bf16 incl pad), bulk-copyable tiles.
#define QKV_ROW 72                         // bf16 elements per padded row
__device__ __nv_bfloat16 g_qh[(size_t)NB * NH * SEQ * QKV_ROW];
__device__ __nv_bfloat16 g_ql[(size_t)NB * NH * SEQ * QKV_ROW];
__device__ __nv_bfloat16 g_kh[(size_t)NB * NH * SEQ * QKV_ROW];
__device__ __nv_bfloat16 g_kl[(size_t)NB * NH * SEQ * QKV_ROW];
__device__ __nv_bfloat16 g_vh[(size_t)NB * NH * SEQ * QKV_ROW];
__device__ __nv_bfloat16 g_vl[(size_t)NB * NH * SEQ * QKV_ROW];

// GEMM A/B operands, k-blocked: [kb (32k)][row][80B]
#define ABT ((size_t)32 * MTOT * 80)       // one activation tensor
#define WBT ((size_t)32 * DM * 80)         // one weight tensor
__device__ char g_ah[3 * ABT];
__device__ char g_al[3 * ABT];
__device__ char g_wh[4 * WBT];
__device__ char g_wl[4 * WBT];
__device__ char g_aoh[ABT];
__device__ char g_aol[ABT];

// ============================ helpers =======================================
__device__ __forceinline__ uint32_t smem_u32(const void* p) {
    uint32_t a;
    asm("{ .reg .u64 t; cvta.to.shared.u64 t, %1; cvt.u32.u64 %0, t; }"
        : "=r"(a) : "l"(p));
    return a;
}
#define MBARRIER_INIT(a, c) \
    asm volatile("mbarrier.init.shared.b64 [%0], %1;" :: "r"((uint32_t)(a)), "r"((uint32_t)(c)) : "memory")
#define MBARRIER_EXPECT_TX(a, b) \
    asm volatile("mbarrier.arrive.expect_tx.shared.b64 _, [%0], %1;" :: "r"((uint32_t)(a)), "r"((uint32_t)(b)) : "memory")
#define MBARRIER_WAIT_PARITY(a, par) do {                                        \
    uint32_t _m = (uint32_t)(a); uint32_t _p = (uint32_t)(par); uint32_t _d;     \
    asm volatile("{\n\t.reg .pred p;\n\t"                                        \
        "mbarrier.try_wait.parity.acquire.cta.shared::cta.b64 p, [%1], %2;\n\t"  \
        "selp.b32 %0, 1, 0, p;\n\t}" : "=r"(_d) : "r"(_m), "r"(_p) : "memory");  \
    if (!_d) {                                                                   \
        asm volatile("{\n\t.reg .pred P1;\n\t"                                   \
        "WL_%=:\n\t"                                                             \
        "mbarrier.try_wait.parity.acquire.cta.shared::cta.b64 P1, [%0], %1, 0x989680;\n\t" \
        "@P1 bra.uni WD_%=;\n\t"                                                 \
        "bra.uni WL_%=;\n\t"                                                     \
        "WD_%=:\n\t}" :: "r"(_m), "r"(_p) : "memory");                           \
    } } while (0)
#define BULK_LD(dst, src, size, mbar) \
    asm volatile("cp.async.bulk.shared::cluster.global.mbarrier::complete_tx::bytes [%0], [%1], %2, [%3];" \
                 :: "r"((uint32_t)(dst)), "l"(src), "r"((uint32_t)(size)), "r"((uint32_t)(mbar)) : "memory")

__device__ __forceinline__ void ldsm4(uint32_t* r, uint32_t addr) {
    asm volatile("ldmatrix.sync.aligned.m8n8.x4.shared.b16 {%0,%1,%2,%3}, [%4];"
                 : "=r"(r[0]), "=r"(r[1]), "=r"(r[2]), "=r"(r[3]) : "r"(addr));
}
__device__ __forceinline__ void ldsm4t(uint32_t* r, uint32_t addr) {
    asm volatile("ldmatrix.sync.aligned.m8n8.x4.trans.shared.b16 {%0,%1,%2,%3}, [%4];"
                 : "=r"(r[0]), "=r"(r[1]), "=r"(r[2]), "=r"(r[3]) : "r"(addr));
}
__device__ __forceinline__ void mma_bf16(float* d, const uint32_t* a,
                                         const uint32_t* b) {
    asm volatile(
        "mma.sync.aligned.m16n8k16.row.col.f32.bf16.bf16.f32 "
        "{%0,%1,%2,%3},{%4,%5,%6,%7},{%8,%9},{%0,%1,%2,%3};"
        : "+f"(d[0]), "+f"(d[1]), "+f"(d[2]), "+f"(d[3])
        : "r"(a[0]), "r"(a[1]), "r"(a[2]), "r"(a[3]), "r"(b[0]), "r"(b[1]));
}
// FMA-pipe exp2 (no MUFU). |err| ~3e-6 rel.
__device__ __forceinline__ float fexp2(float x) {
    x = fmaxf(x, -125.0f);
    int i = __float2int_rn(x);
    float f = x - (float)i;
    float p = 0.0013333558f;
    p = fmaf(p, f, 0.0096181291f);
    p = fmaf(p, f, 0.0555041087f);
    p = fmaf(p, f, 0.2402265070f);
    p = fmaf(p, f, 0.6931471806f);
    p = fmaf(p, f, 1.0f);
    return p * __int_as_float((i + 127) << 23);
}
#define LOG2E 1.4426950408889634f

__device__ __forceinline__ void split1(float x, __nv_bfloat16& h, __nv_bfloat16& l) {
    h = __float2bfloat16(x);
    l = __float2bfloat16(x - __bfloat162float(h));
}
__device__ __forceinline__ void split_pack(float a, float b, uint32_t& hw, uint32_t& lw) {
    __nv_bfloat16 ha, la, hb, lb;
    split1(a, ha, la);
    split1(b, hb, lb);
    __nv_bfloat162 h2(ha, hb), l2(la, lb);
    hw = *reinterpret_cast<uint32_t*>(&h2);
    lw = *reinterpret_cast<uint32_t*>(&l2);
}

// ====================== bf16x3 HMMA GEMM: 256x128x32, 512 thr ===============
// 16 warps as 4(m)x4(n); warp tile 64x32. C = A * B^T, B stored [N,K] blocked.
#define ST_STRIDE 80
#define AOP 20480                     // 256*80
#define BOP 10240                     // 128*80
#define GSTAGE (2 * AOP + 2 * BOP)    // 61440: Ah,Al,Bh,Bl
#define GMB (2 * GSTAGE)              // 122880
#define GEMM_SMEM (GMB + 32)

__device__ __forceinline__ void gemm_issue(uint32_t sb, int s,
                                           const char* Ah, const char* Al,
                                           const char* Bh, const char* Bl,
                                           int row0, int col0, int kb) {
    uint32_t mb = sb + GMB + s * 8;
    uint32_t dst = sb + s * GSTAGE;
    MBARRIER_EXPECT_TX(mb, GSTAGE);
    size_t ao = (size_t)kb * ((size_t)MTOT * 80) + (size_t)row0 * 80;
    size_t bo = (size_t)kb * ((size_t)DM * 80) + (size_t)col0 * 80;
    BULK_LD(dst,               Ah + ao, AOP, mb);
    BULK_LD(dst + AOP,         Al + ao, AOP, mb);
    BULK_LD(dst + 2 * AOP,     Bh + bo, BOP, mb);
    BULK_LD(dst + 2 * AOP + BOP, Bl + bo, BOP, mb);
}

// MODE 0: fp32 out [M,DM].  MODE 1: bf16 hi/lo out to padded [bh][t][72] QKV.
template <int MODE>
__device__ __forceinline__ void gemm_body(const char* __restrict__ Ah,
                                          const char* __restrict__ Al,
                                          const char* __restrict__ Bh,
                                          const char* __restrict__ Bl,
                                          float* __restrict__ Cf,
                                          __nv_bfloat16* __restrict__ Chi,
                                          __nv_bfloat16* __restrict__ Clo,
                                          float scale, int row0, int col0) {
    extern __shared__ char sm[];
    const uint32_t sb = smem_u32(sm);
    const int tid = threadIdx.x;
    const int lane = tid & 31;
    const int w = tid >> 5;
    const int wm = w & 3;
    const int wn = w >> 2;

    if (tid == 0) {
        MBARRIER_INIT(sb + GMB, 1);
        MBARRIER_INIT(sb + GMB + 8, 1);
    }
    __syncthreads();
    if (tid == 0) {
        gemm_issue(sb, 0, Ah, Al, Bh, Bl, row0, col0, 0);
        gemm_issue(sb, 1, Ah, Al, Bh, Bl, row0, col0, 1);
    }

    float acc[4][4][4];
#pragma unroll
    for (int mi = 0; mi < 4; mi++)
#pragma unroll
        for (int ni = 0; ni < 4; ni++)
#pragma unroll
            for (int e = 0; e < 4; e++) acc[mi][ni][e] = 0.f;

    const int a_off = (wm * 64 + (lane & 15)) * ST_STRIDE + (lane >> 4) * 16;
    const int b_off = (wn * 32 + (lane & 7) + ((lane >> 4) << 3)) * ST_STRIDE +
                      ((lane >> 3) & 1) * 16;

    int ph0 = 0, ph1 = 0;
    const int NIT = DM / 32;   // 32
    for (int i = 0; i < NIT; i++) {
        const int s = i & 1;
        if (s == 0) { MBARRIER_WAIT_PARITY(sb + GMB, ph0); ph0 ^= 1; }
        else        { MBARRIER_WAIT_PARITY(sb + GMB + 8, ph1); ph1 ^= 1; }
        const uint32_t sbase = sb + s * GSTAGE;
#pragma unroll
        for (int ks = 0; ks < 2; ks++) {
            uint32_t ah[4][4], al[4][4], bh[8], bl[8];
            const uint32_t abase = sbase + a_off + ks * 32;
            const uint32_t bbase = sbase + 2 * AOP + b_off + ks * 32;
#pragma unroll
            for (int mi = 0; mi < 4; mi++) {
                ldsm4(ah[mi], abase + mi * 16 * ST_STRIDE);
                ldsm4(al[mi], abase + mi * 16 * ST_STRIDE + AOP);
            }
#pragma unroll
            for (int p = 0; p < 2; p++) {
                ldsm4(&bh[p * 4], bbase + p * 16 * ST_STRIDE);
                ldsm4(&bl[p * 4], bbase + p * 16 * ST_STRIDE + BOP);
            }
#pragma unroll
            for (int mi = 0; mi < 4; mi++)
#pragma unroll
                for (int ni = 0; ni < 4; ni++) {
                    const uint32_t* fh = &bh[(ni >> 1) * 4 + (ni & 1) * 2];
                    const uint32_t* fl = &bl[(ni >> 1) * 4 + (ni & 1) * 2];
                    mma_bf16(acc[mi][ni], ah[mi], fh);
                    mma_bf16(acc[mi][ni], ah[mi], fl);
                    mma_bf16(acc[mi][ni], al[mi], fh);
                }
        }
        __syncthreads();
        if (i + 2 < NIT && tid == 0)
            gemm_issue(sb, s, Ah, Al, Bh, Bl, row0, col0, i + 2);
    }

    const int grp = lane >> 2;
    const int tig = lane & 3;
#pragma unroll
    for (int mi = 0; mi < 4; mi++) {
#pragma unroll
        for (int ni = 0; ni < 4; ni++) {
            int col = col0 + wn * 32 + ni * 8 + tig * 2;
            int rlo = row0 + wm * 64 + mi * 16 + grp;
            int rhi = rlo + 8;
            if (MODE == 0) {
                *reinterpret_cast<float2*>(Cf + (size_t)rlo * DM + col) =
                    make_float2(acc[mi][ni][0], acc[mi][ni][1]);
                *reinterpret_cast<float2*>(Cf + (size_t)rhi * DM + col) =
                    make_float2(acc[mi][ni][2], acc[mi][ni][3]);
            } else {
                int h = col >> 6, dh = col & (HD - 1);
                int b0 = rlo >> 11, t0 = rlo & (SEQ - 1);
                int b1 = rhi >> 11, t1 = rhi & (SEQ - 1);
                size_t i0 = (((size_t)(b0 * NH + h)) * SEQ + t0) * QKV_ROW + dh;
                size_t i1 = (((size_t)(b1 * NH + h)) * SEQ + t1) * QKV_ROW + dh;
                uint32_t hw, lw;
                split_pack(acc[mi][ni][0] * scale, acc[mi][ni][1] * scale, hw, lw);
                *reinterpret_cast<uint32_t*>(Chi + i0) = hw;
                *reinterpret_cast<uint32_t*>(Clo + i0) = lw;
                split_pack(acc[mi][ni][2] * scale, acc[mi][ni][3] * scale, hw, lw);
                *reinterpret_cast<uint32_t*>(Chi + i1) = hw;
                *reinterpret_cast<uint32_t*>(Clo + i1) = lw;
            }
        }
    }
}

__global__ void __launch_bounds__(512, 1)
gemm_qkv_kernel() {
    int z = blockIdx.z;
    const char* Ah = g_ah + (size_t)z * ABT;
    const char* Al = g_al + (size_t)z * ABT;
    const char* Bh = g_wh + (size_t)z * WBT;
    const char* Bl = g_wl + (size_t)z * WBT;
    __nv_bfloat16* Chi = (z == 0) ? g_qh : (z == 1) ? g_kh : g_vh;
    __nv_bfloat16* Clo = (z == 0) ? g_ql : (z == 1) ? g_kl : g_vl;
    float scale = (z == 0) ? 0.125f : 1.0f;
    gemm_body<1>(Ah, Al, Bh, Bl, nullptr, Chi, Clo, scale,
                 blockIdx.y * 256, blockIdx.x * 128);
}

__global__ void __launch_bounds__(512, 1)
gemm_o_kernel(float* __restrict__ out) {
    gemm_body<0>(g_aoh, g_aol, g_wh + 3 * WBT, g_wl + 3 * WBT,
                 out, nullptr, nullptr, 1.0f,
                 blockIdx.y * 256, blockIdx.x * 128);
}

// ====================== split / transpose kernels ===========================
__global__ void __launch_bounds__(256)
split_act_kernel(const float* __restrict__ q, const float* __restrict__ k,
                 const float* __restrict__ v) {
    int z = blockIdx.z;
    const float* src = (z == 0) ? q : (z == 1) ? k : v;
    size_t i4 = (size_t)blockIdx.x * 256 + threadIdx.x;
    float4 x = reinterpret_cast<const float4*>(src)[i4];
    uint32_t h0, l0, h1, l1;
    split_pack(x.x, x.y, h0, l0);
    split_pack(x.z, x.w, h1, l1);
    size_t e0 = i4 * 4;
    int m = (int)(e0 >> 10);
    int k0 = (int)(e0 & 1023);
    size_t off = (size_t)z * ABT + (size_t)(k0 >> 5) * ((size_t)MTOT * 80) +
                 (size_t)m * 80 + (size_t)(k0 & 31) * 2;
    *reinterpret_cast<uint2*>(g_ah + off) = make_uint2(h0, h1);
    *reinterpret_cast<uint2*>(g_al + off) = make_uint2(l0, l1);
}

__global__ void __launch_bounds__(256)
split_w_kernel(const float* __restrict__ Wq, const float* __restrict__ Wk,
               const float* __restrict__ Wv, const float* __restrict__ Wo) {
    __shared__ float tile[32][33];
    int z = blockIdx.z;
    const float* W = (z == 0) ? Wq : (z == 1) ? Wk : (z == 2) ? Wv : Wo;
    int tx = threadIdx.x & 31, ty = threadIdx.x >> 5;
    int k0 = blockIdx.y * 32, n0 = blockIdx.x * 32;
#pragma unroll
    for (int i = 0; i < 4; i++)
        tile[ty + i * 8][tx] = W[(size_t)(k0 + ty + i * 8) * DM + n0 + tx];
    __syncthreads();
#pragma unroll
    for (int i = 0; i < 4; i++) {
        int n = n0 + ty + i * 8;
        int k = k0 + tx;
        __nv_bfloat16 h, l;
        split1(tile[tx][ty + i * 8], h, l);
        size_t off = (size_t)z * WBT + (size_t)(k >> 5) * ((size_t)DM * 80) +
                     (size_t)n * 80 + (size_t)(k & 31) * 2;
        *reinterpret_cast<__nv_bfloat16*>(g_wh + off) = h;
        *reinterpret_cast<__nv_bfloat16*>(g_wl + off) = l;
    }
}

// ====================== tensorized flash attention ==========================
// Br=128 per CTA (8 warps x 16 rows), 256 threads, 2 CTAs/SM. Bc=64 per iter.
// All tiles via cp.async.bulk; smem layout identical to padded global layout.
#define FSTR 144
#define FOP  (64 * FSTR)              // 9216
#define FSTAGE (4 * FOP)              // 36864: Kh,Kl,Vh,Vl
#define QOFF (2 * FSTAGE)             // 73728
#define QOP  (128 * FSTR)             // 18432
#define FBIAS (QOFF + 2 * QOP)        // 110592
#define FMB (FBIAS + 512)             // 111104
#define FLASH_SMEM (FMB + 32)

__global__ void __launch_bounds__(256, 2)
flash_kernel(const int* __restrict__ qpm, const int* __restrict__ kpm) {
    extern __shared__ char sm[];
    const uint32_t sb = smem_u32(sm);
    float* biasp = reinterpret_cast<float*>(sm + FBIAS);

    const int tid = threadIdx.x;
    const int lane = tid & 31;
    const int w = tid >> 5;                      // 0..7
    const int grp = lane >> 2;
    const int tig = lane & 3;

    const int qt = gridDim.x - 1 - blockIdx.x;   // heavy tiles first
    const int bh = blockIdx.y;
    const int b = bh >> 4;
    const int h = bh & (NH - 1);
    const size_t bbase = (size_t)bh * SEQ * 144; // byte base of this head
    const int qrow0 = qt * 128;
    const int nit = 2 * qt + 2;

    if (tid == 0) {
        MBARRIER_INIT(sb + FMB, 1);
        MBARRIER_INIT(sb + FMB + 8, 1);
        MBARRIER_INIT(sb + FMB + 16, 1);
    }
    __syncthreads();
    if (tid == 0) {
        // Q hi/lo
        MBARRIER_EXPECT_TX(sb + FMB + 16, 2 * QOP);
        BULK_LD(sb + QOFF,       (const char*)g_qh + bbase + (size_t)qrow0 * 144, QOP, sb + FMB + 16);
        BULK_LD(sb + QOFF + QOP, (const char*)g_ql + bbase + (size_t)qrow0 * 144, QOP, sb + FMB + 16);
        // K/V iter 0 -> stage 0
        MBARRIER_EXPECT_TX(sb + FMB, FSTAGE);
        BULK_LD(sb,           (const char*)g_kh + bbase, FOP, sb + FMB);
        BULK_LD(sb + FOP,     (const char*)g_kl + bbase, FOP, sb + FMB);
        BULK_LD(sb + 2 * FOP, (const char*)g_vh + bbase, FOP, sb + FMB);
        BULK_LD(sb + 3 * FOP, (const char*)g_vl + bbase, FOP, sb + FMB);
    }

    // ---- state ----
    float o[8][4];
#pragma unroll
    for (int ni = 0; ni < 8; ni++)
#pragma unroll
        for (int e = 0; e < 4; e++) o[ni][e] = 0.f;
    float m0 = -1e30f, m1 = -1e30f, l0 = 0.f, l1 = 0.f;

    const int a_off = (w * 16 + (lane & 15)) * FSTR + (lane >> 4) * 16;
    const int b_off = ((lane & 7) + ((lane >> 4) << 3)) * FSTR +
                      ((lane >> 3) & 1) * 16;
    const int t_off = (lane & 15) * FSTR + ((lane >> 4) << 3) * 2;  // trans ldsm

    MBARRIER_WAIT_PARITY(sb + FMB + 16, 0);   // Q resident

    int ph0 = 0, ph1 = 0;
    for (int it = 0; it < nit; it++) {
        const int s = it & 1;
        const int krow0 = it * 64;
        const uint32_t stg = sb + s * FSTAGE;

        // issue next stage
        if (it + 1 < nit && tid == 0) {
            const size_t ko = bbase + (size_t)(it + 1) * 64 * 144;
            const uint32_t mb = sb + FMB + (s ^ 1) * 8;
            const uint32_t d = sb + (s ^ 1) * FSTAGE;
            MBARRIER_EXPECT_TX(mb, FSTAGE);
            BULK_LD(d,           (const char*)g_kh + ko, FOP, mb);
            BULK_LD(d + FOP,     (const char*)g_kl + ko, FOP, mb);
            BULK_LD(d + 2 * FOP, (const char*)g_vh + ko, FOP, mb);
            BULK_LD(d + 3 * FOP, (const char*)g_vl + ko, FOP, mb);
        }
        if (tid < 64)
            biasp[s * 64 + tid] =
                (kpm[b * SEQ + krow0 + tid] != 0) ? 0.f : -1e30f;

        if (s == 0) { MBARRIER_WAIT_PARITY(sb + FMB, ph0); ph0 ^= 1; }
        else        { MBARRIER_WAIT_PARITY(sb + FMB + 8, ph1); ph1 ^= 1; }
        __syncthreads();   // bias visible to all

        // ---- S = Q K^T (hi/lo x3), Q fragments reloaded from smem ----
        float sc[8][4];
#pragma unroll
        for (int ni = 0; ni < 8; ni++)
#pragma unroll
            for (int e = 0; e < 4; e++) sc[ni][e] = 0.f;

#pragma unroll
        for (int kd = 0; kd < 4; kd++) {
            uint32_t qfh[4], qfl[4];
            ldsm4(qfh, sb + QOFF + a_off + kd * 32);
            ldsm4(qfl, sb + QOFF + QOP + a_off + kd * 32);
            uint32_t kh[4][4], kl[4][4];
#pragma unroll
            for (int g = 0; g < 4; g++) {
                ldsm4(kh[g], stg + b_off + kd * 32 + g * 16 * FSTR);
                ldsm4(kl[g], stg + FOP + b_off + kd * 32 + g * 16 * FSTR);
            }
#pragma unroll
            for (int ni = 0; ni < 8; ni++) {
                const int g = ni >> 1, sel = (ni & 1) * 2;
                mma_bf16(sc[ni], qfh, &kh[g][sel]);
                mma_bf16(sc[ni], qfh, &kl[g][sel]);
                mma_bf16(sc[ni], qfl, &kh[g][sel]);
            }
        }

        // ---- bias + causal mask ----
#pragma unroll
        for (int ni = 0; ni < 8; ni++) {
            float2 bb = *reinterpret_cast<float2*>(&biasp[s * 64 + ni * 8 + 2 * tig]);
            sc[ni][0] += bb.x; sc[ni][1] += bb.y;
            sc[ni][2] += bb.x; sc[ni][3] += bb.y;
        }
        if (krow0 + 63 > qrow0) {
            const int r0 = qrow0 + w * 16 + grp;
            const int r1 = r0 + 8;
#pragma unroll
            for (int ni = 0; ni < 8; ni++) {
                int c0 = krow0 + ni * 8 + 2 * tig;
                if (c0 > r0) sc[ni][0] = -1e30f;
                if (c0 + 1 > r0) sc[ni][1] = -1e30f;
                if (c0 > r1) sc[ni][2] = -1e30f;
                if (c0 + 1 > r1) sc[ni][3] = -1e30f;
            }
        }

        // ---- online softmax ----
        float mx0 = -1e30f, mx1 = -1e30f;
#pragma unroll
        for (int ni = 0; ni < 8; ni++) {
            mx0 = fmaxf(mx0, fmaxf(sc[ni][0], sc[ni][1]));
            mx1 = fmaxf(mx1, fmaxf(sc[ni][2], sc[ni][3]));
        }
        mx0 = fmaxf(mx0, __shfl_xor_sync(0xffffffffu, mx0, 1));
        mx0 = fmaxf(mx0, __shfl_xor_sync(0xffffffffu, mx0, 2));
        mx1 = fmaxf(mx1, __shfl_xor_sync(0xffffffffu, mx1, 1));
        mx1 = fmaxf(mx1, __shfl_xor_sync(0xffffffffu, mx1, 2));
        float mn0 = fmaxf(m0, mx0), mn1 = fmaxf(m1, mx1);
        float cr0 = fexp2((m0 - mn0) * LOG2E);
        float cr1 = fexp2((m1 - mn1) * LOG2E);
        m0 = mn0; m1 = mn1;

        uint32_t ph[8][2], pl[8][2];
        float rs0 = 0.f, rs1 = 0.f;
#pragma unroll
        for (int ni = 0; ni < 8; ni++) {
            float p0 = fexp2((sc[ni][0] - mn0) * LOG2E);
            float p1 = fexp2((sc[ni][1] - mn0) * LOG2E);
            float p2 = fexp2((sc[ni][2] - mn1) * LOG2E);
            float p3 = fexp2((sc[ni][3] - mn1) * LOG2E);
            rs0 += p0 + p1; rs1 += p2 + p3;
            split_pack(p0, p1, ph[ni][0], pl[ni][0]);
            split_pack(p2, p3, ph[ni][1], pl[ni][1]);
        }
        rs0 += __shfl_xor_sync(0xffffffffu, rs0, 1);
        rs0 += __shfl_xor_sync(0xffffffffu, rs0, 2);
        rs1 += __shfl_xor_sync(0xffffffffu, rs1, 1);
        rs1 += __shfl_xor_sync(0xffffffffu, rs1, 2);
        l0 = l0 * cr0 + rs0;
        l1 = l1 * cr1 + rs1;
#pragma unroll
        for (int ni = 0; ni < 8; ni++) {
            o[ni][0] *= cr0; o[ni][1] *= cr0;
            o[ni][2] *= cr1; o[ni][3] *= cr1;
        }

        // ---- O += P V (hi/lo x3), V in [kv][dh], B-frags via ldsm.trans ----
#pragma unroll
        for (int kc = 0; kc < 4; kc++) {
            uint32_t vh[4][4], vl[4][4];
#pragma unroll
            for (int g = 0; g < 4; g++) {
                uint32_t ta = stg + 2 * FOP + kc * 16 * FSTR + t_off + g * 32;
                ldsm4t(vh[g], ta);
                ldsm4t(vl[g], ta + FOP);
            }
            uint32_t ah[4] = {ph[2 * kc][0], ph[2 * kc][1],
                              ph[2 * kc + 1][0], ph[2 * kc + 1][1]};
            uint32_t al[4] = {pl[2 * kc][0], pl[2 * kc][1],
                              pl[2 * kc + 1][0], pl[2 * kc + 1][1]};
#pragma unroll
            for (int ni = 0; ni < 8; ni++) {
                const int g = ni >> 1, sel = (ni & 1) * 2;
                mma_bf16(o[ni], ah, &vh[g][sel]);
                mma_bf16(o[ni], ah, &vl[g][sel]);
                mma_bf16(o[ni], al, &vh[g][sel]);
            }
        }
        __syncthreads();
    }

    // ---- epilogue: /l, query padding, write bf16 hi/lo k-blocked [kb][m][80B]
    const int r0 = qrow0 + w * 16 + grp;
    const int r1 = r0 + 8;
    float f0 = (l0 > 0.f ? 1.0f / l0 : 0.f) * (float)qpm[b * SEQ + r0];
    float f1 = (l1 > 0.f ? 1.0f / l1 : 0.f) * (float)qpm[b * SEQ + r1];
    const size_t m0r = (size_t)(b * SEQ + r0);
    const size_t m1r = (size_t)(b * SEQ + r1);
#pragma unroll
    for (int ni = 0; ni < 8; ni++) {
        int col = h * HD + ni * 8 + 2 * tig;
        size_t kslab = (size_t)(col >> 5) * ((size_t)MTOT * 80) +
                       (size_t)(col & 31) * 2;
        uint32_t hw, lw;
        split_pack(o[ni][0] * f0, o[ni][1] * f0, hw, lw);
        size_t i0 = kslab + m0r * 80;
        *reinterpret_cast<uint32_t*>(g_aoh + i0) = hw;
        *reinterpret_cast<uint32_t*>(g_aol + i0) = lw;
        split_pack(o[ni][2] * f1, o[ni][3] * f1, hw, lw);
        size_t i1 = kslab + m1r * 80;
        *reinterpret_cast<uint32_t*>(g_aoh + i1) = hw;
        *reinterpret_cast<uint32_t*>(g_aol + i1) = lw;
    }
}

// ---------------- launch -----------------------------------------------------
extern "C" void kernel_launch(void* const* d_in, const int* in_sizes, int n_in,
                              void* d_out, int out_size) {
    const float* q   = (const float*)d_in[0];
    const float* k   = (const float*)d_in[1];
    const float* v   = (const float*)d_in[2];
    const int*   qpm = (const int*)d_in[3];
    const int*   kpm = (const int*)d_in[4];
    const float* Wq  = (const float*)d_in[5];
    const float* Wk  = (const float*)d_in[6];
    const float* Wv  = (const float*)d_in[7];
    const float* Wo  = (const float*)d_in[8];
    float* out = (float*)d_out;

    dim3 gs((MTOT * DM) / (256 * 4), 1, 3);
    split_act_kernel<<<gs, 256>>>(q, k, v);
    split_w_kernel<<<dim3(32, 32, 4), 256>>>(Wq, Wk, Wv, Wo);

    cudaFuncSetAttribute(gemm_qkv_kernel,
                         cudaFuncAttributeMaxDynamicSharedMemorySize, GEMM_SMEM);
    cudaFuncSetAttribute(gemm_o_kernel,
                         cudaFuncAttributeMaxDynamicSharedMemorySize, GEMM_SMEM);
    gemm_qkv_kernel<<<dim3(DM / 128, MTOT / 256, 3), 512, GEMM_SMEM>>>();

    cudaFuncSetAttribute(flash_kernel,
                         cudaFuncAttributeMaxDynamicSharedMemorySize, FLASH_SMEM);
    flash_kernel<<<dim3(SEQ / 128, NB * NH), 256, FLASH_SMEM>>>(qpm, kpm);

    gemm_o_kernel<<<dim3(DM / 128, MTOT / 256), 512, GEMM_SMEM>>>(out);
}

// round 10
// speedup vs baseline: 1.3566x; 1.0486x over previous
#include <cuda_runtime.h>
#include <cuda_bf16.h>
#include <cstdint>
#include <math.h>

#define DM   1024
#define NH   16
#define HD   64
#define SEQ  2048
#define NB   4
#define MTOT (NB * SEQ)   // 8192

// ---------------- global scratch: layouts match smem staging ----------------
#define QKV_ROW 72                         // bf16 elements per padded row (144B)
__device__ __nv_bfloat16 g_qh[(size_t)NB * NH * SEQ * QKV_ROW];
__device__ __nv_bfloat16 g_ql[(size_t)NB * NH * SEQ * QKV_ROW];
__device__ __nv_bfloat16 g_kh[(size_t)NB * NH * SEQ * QKV_ROW];
__device__ __nv_bfloat16 g_kl[(size_t)NB * NH * SEQ * QKV_ROW];
__device__ __nv_bfloat16 g_vh[(size_t)NB * NH * SEQ * QKV_ROW];
__device__ __nv_bfloat16 g_vl[(size_t)NB * NH * SEQ * QKV_ROW];

#define ABT ((size_t)32 * MTOT * 80)       // one activation tensor, k-blocked
#define WBT ((size_t)32 * DM * 80)         // one weight tensor, k-blocked
__device__ char g_ah[3 * ABT];
__device__ char g_al[3 * ABT];
__device__ char g_wh[4 * WBT];
__device__ char g_wl[4 * WBT];
__device__ char g_aoh[ABT];
__device__ char g_aol[ABT];

// ============================ helpers =======================================
__device__ __forceinline__ uint32_t smem_u32(const void* p) {
    uint32_t a;
    asm("{ .reg .u64 t; cvta.to.shared.u64 t, %1; cvt.u32.u64 %0, t; }"
        : "=r"(a) : "l"(p));
    return a;
}
#define MBARRIER_INIT(a, c) \
    asm volatile("mbarrier.init.shared.b64 [%0], %1;" :: "r"((uint32_t)(a)), "r"((uint32_t)(c)) : "memory")
#define MBARRIER_EXPECT_TX(a, b) \
    asm volatile("mbarrier.arrive.expect_tx.shared.b64 _, [%0], %1;" :: "r"((uint32_t)(a)), "r"((uint32_t)(b)) : "memory")
#define MBARRIER_WAIT_PARITY(a, par) do {                                        \
    uint32_t _m = (uint32_t)(a); uint32_t _p = (uint32_t)(par); uint32_t _d;     \
    asm volatile("{\n\t.reg .pred p;\n\t"                                        \
        "mbarrier.try_wait.parity.acquire.cta.shared::cta.b64 p, [%1], %2;\n\t"  \
        "selp.b32 %0, 1, 0, p;\n\t}" : "=r"(_d) : "r"(_m), "r"(_p) : "memory");  \
    if (!_d) {                                                                   \
        asm volatile("{\n\t.reg .pred P1;\n\t"                                   \
        "WL_%=:\n\t"                                                             \
        "mbarrier.try_wait.parity.acquire.cta.shared::cta.b64 P1, [%0], %1, 0x989680;\n\t" \
        "@P1 bra.uni WD_%=;\n\t"                                                 \
        "bra.uni WL_%=;\n\t"                                                     \
        "WD_%=:\n\t}" :: "r"(_m), "r"(_p) : "memory");                           \
    } } while (0)
#define BULK_LD(dst, src, size, mbar) \
    asm volatile("cp.async.bulk.shared::cluster.global.mbarrier::complete_tx::bytes [%0], [%1], %2, [%3];" \
                 :: "r"((uint32_t)(dst)), "l"(src), "r"((uint32_t)(size)), "r"((uint32_t)(mbar)) : "memory")
#define BULK_ST(gd, ss, sz) \
    asm volatile("cp.async.bulk.global.shared::cta.bulk_group [%0], [%1], %2;" \
                 :: "l"(gd), "r"((uint32_t)(ss)), "r"((uint32_t)(sz)) : "memory")
#define BULK_COMMIT() asm volatile("cp.async.bulk.commit_group;" ::: "memory")
#define BULK_WAIT0()  asm volatile("cp.async.bulk.wait_group 0;" ::: "memory")
#define FENCE_ASYNC() asm volatile("fence.proxy.async;" ::: "memory")

__device__ __forceinline__ void ldsm4(uint32_t* r, uint32_t addr) {
    asm volatile("ldmatrix.sync.aligned.m8n8.x4.shared.b16 {%0,%1,%2,%3}, [%4];"
                 : "=r"(r[0]), "=r"(r[1]), "=r"(r[2]), "=r"(r[3]) : "r"(addr));
}
__device__ __forceinline__ void ldsm4t(uint32_t* r, uint32_t addr) {
    asm volatile("ldmatrix.sync.aligned.m8n8.x4.trans.shared.b16 {%0,%1,%2,%3}, [%4];"
                 : "=r"(r[0]), "=r"(r[1]), "=r"(r[2]), "=r"(r[3]) : "r"(addr));
}
__device__ __forceinline__ void mma_bf16(float* d, const uint32_t* a,
                                         const uint32_t* b) {
    asm volatile(
        "mma.sync.aligned.m16n8k16.row.col.f32.bf16.bf16.f32 "
        "{%0,%1,%2,%3},{%4,%5,%6,%7},{%8,%9},{%0,%1,%2,%3};"
        : "+f"(d[0]), "+f"(d[1]), "+f"(d[2]), "+f"(d[3])
        : "r"(a[0]), "r"(a[1]), "r"(a[2]), "r"(a[3]), "r"(b[0]), "r"(b[1]));
}
// FMA-pipe exp2: magic-constant range reduction, no F2I/I2F. x in log2 domain.
__device__ __forceinline__ float fexp2(float x) {
    x = fmaxf(x, -125.0f);
    float y = x + 12582912.0f;               // 1.5 * 2^23, RN integer
    float fi = y - 12582912.0f;
    float f = x - fi;                        // [-0.5, 0.5]
    uint32_t iy = __float_as_uint(y);        // 0x4B400000 + n
    float p = 0.0013333558f;
    p = fmaf(p, f, 0.0096181291f);
    p = fmaf(p, f, 0.0555041087f);
    p = fmaf(p, f, 0.2402265070f);
    p = fmaf(p, f, 0.6931471806f);
    p = fmaf(p, f, 1.0f);
    return p * __uint_as_float((iy + 0xB4C0007Fu) << 23);   // 2^n
}

__device__ __forceinline__ void split1(float x, __nv_bfloat16& h, __nv_bfloat16& l) {
    h = __float2bfloat16(x);
    l = __float2bfloat16(x - __bfloat162float(h));
}
// pair split via bf16x2 converts: hw = (bf16(a), bf16(b)), lw = residuals
__device__ __forceinline__ void split_pack(float a, float b, uint32_t& hw, uint32_t& lw) {
    asm("cvt.rn.bf16x2.f32 %0, %1, %2;" : "=r"(hw) : "f"(b), "f"(a));
    float fa = __uint_as_float(hw << 16);
    float fb = __uint_as_float(hw & 0xffff0000u);
    float la = a - fa, lb = b - fb;
    asm("cvt.rn.bf16x2.f32 %0, %1, %2;" : "=r"(lw) : "f"(lb), "f"(la));
}

// ====================== bf16x3 HMMA GEMM: 256x128x32, 512 thr ===============
#define ST_STRIDE 80
#define AOP 20480
#define BOP 10240
#define GSTAGE (2 * AOP + 2 * BOP)    // 61440
#define GMB (2 * GSTAGE)              // 122880
#define GEMM_SMEM (GMB + 32)

__device__ __forceinline__ void gemm_issue(uint32_t sb, int s,
                                           const char* Ah, const char* Al,
                                           const char* Bh, const char* Bl,
                                           int row0, int col0, int kb) {
    uint32_t mb = sb + GMB + s * 8;
    uint32_t dst = sb + s * GSTAGE;
    MBARRIER_EXPECT_TX(mb, GSTAGE);
    size_t ao = (size_t)kb * ((size_t)MTOT * 80) + (size_t)row0 * 80;
    size_t bo = (size_t)kb * ((size_t)DM * 80) + (size_t)col0 * 80;
    BULK_LD(dst,                 Ah + ao, AOP, mb);
    BULK_LD(dst + AOP,           Al + ao, AOP, mb);
    BULK_LD(dst + 2 * AOP,       Bh + bo, BOP, mb);
    BULK_LD(dst + 2 * AOP + BOP, Bl + bo, BOP, mb);
}

// MODE 0: fp32 out [M,DM].  MODE 1: bf16 hi/lo out to padded QKV via bulk S2G.
template <int MODE>
__device__ __forceinline__ void gemm_body(const char* __restrict__ Ah,
                                          const char* __restrict__ Al,
                                          const char* __restrict__ Bh,
                                          const char* __restrict__ Bl,
                                          float* __restrict__ Cf,
                                          __nv_bfloat16* __restrict__ Chi,
                                          __nv_bfloat16* __restrict__ Clo,
                                          float scale, int row0, int col0) {
    extern __shared__ char sm[];
    const uint32_t sb = smem_u32(sm);
    const int tid = threadIdx.x;
    const int lane = tid & 31;
    const int w = tid >> 5;
    const int wm = w & 3;
    const int wn = w >> 2;

    if (tid == 0) {
        MBARRIER_INIT(sb + GMB, 1);
        MBARRIER_INIT(sb + GMB + 8, 1);
    }
    __syncthreads();
    if (tid == 0) {
        gemm_issue(sb, 0, Ah, Al, Bh, Bl, row0, col0, 0);
        gemm_issue(sb, 1, Ah, Al, Bh, Bl, row0, col0, 1);
    }

    float acc[4][4][4];
#pragma unroll
    for (int mi = 0; mi < 4; mi++)
#pragma unroll
        for (int ni = 0; ni < 4; ni++)
#pragma unroll
            for (int e = 0; e < 4; e++) acc[mi][ni][e] = 0.f;

    const int a_off = (wm * 64 + (lane & 15)) * ST_STRIDE + (lane >> 4) * 16;
    const int b_off = (wn * 32 + (lane & 7) + ((lane >> 4) << 3)) * ST_STRIDE +
                      ((lane >> 3) & 1) * 16;

    int ph0 = 0, ph1 = 0;
    const int NIT = DM / 32;   // 32
    for (int i = 0; i < NIT; i++) {
        const int s = i & 1;
        if (s == 0) { MBARRIER_WAIT_PARITY(sb + GMB, ph0); ph0 ^= 1; }
        else        { MBARRIER_WAIT_PARITY(sb + GMB + 8, ph1); ph1 ^= 1; }
        const uint32_t sbase = sb + s * GSTAGE;
#pragma unroll
        for (int ks = 0; ks < 2; ks++) {
            uint32_t ah[4][4], al[4][4], bh[8], bl[8];
            const uint32_t abase = sbase + a_off + ks * 32;
            const uint32_t bbase = sbase + 2 * AOP + b_off + ks * 32;
#pragma unroll
            for (int mi = 0; mi < 4; mi++) {
                ldsm4(ah[mi], abase + mi * 16 * ST_STRIDE);
                ldsm4(al[mi], abase + mi * 16 * ST_STRIDE + AOP);
            }
#pragma unroll
            for (int p = 0; p < 2; p++) {
                ldsm4(&bh[p * 4], bbase + p * 16 * ST_STRIDE);
                ldsm4(&bl[p * 4], bbase + p * 16 * ST_STRIDE + BOP);
            }
#pragma unroll
            for (int mi = 0; mi < 4; mi++)
#pragma unroll
                for (int ni = 0; ni < 4; ni++) {
                    const uint32_t* fh = &bh[(ni >> 1) * 4 + (ni & 1) * 2];
                    const uint32_t* fl = &bl[(ni >> 1) * 4 + (ni & 1) * 2];
                    mma_bf16(acc[mi][ni], ah[mi], fh);
                    mma_bf16(acc[mi][ni], ah[mi], fl);
                    mma_bf16(acc[mi][ni], al[mi], fh);
                }
        }
        __syncthreads();
        if (i + 2 < NIT && tid == 0)
            gemm_issue(sb, s, Ah, Al, Bh, Bl, row0, col0, i + 2);
    }

    const int grp = lane >> 2;
    const int tig = lane & 3;

    if (MODE == 0) {
#pragma unroll
        for (int mi = 0; mi < 4; mi++)
#pragma unroll
            for (int ni = 0; ni < 4; ni++) {
                int col = col0 + wn * 32 + ni * 8 + tig * 2;
                int rlo = row0 + wm * 64 + mi * 16 + grp;
                *reinterpret_cast<float2*>(Cf + (size_t)rlo * DM + col) =
                    make_float2(acc[mi][ni][0], acc[mi][ni][1]);
                *reinterpret_cast<float2*>(Cf + (size_t)(rlo + 8) * DM + col) =
                    make_float2(acc[mi][ni][2], acc[mi][ni][3]);
            }
    } else {
        // smem-stage one head (hi+lo), bulk-store 36864B each, twice
        const int b0 = row0 >> 11;
        const int t0 = row0 & (SEQ - 1);
#pragma unroll
        for (int hh = 0; hh < 2; hh++) {
            if ((wn >> 1) == hh) {
                const int lcb = (wn & 1) * 32;
#pragma unroll
                for (int mi = 0; mi < 4; mi++)
#pragma unroll
                    for (int ni = 0; ni < 4; ni++) {
                        int lc2 = (lcb + ni * 8 + tig * 2) * 2;
                        int rr = wm * 64 + mi * 16 + grp;
                        uint32_t hw, lw;
                        split_pack(acc[mi][ni][0] * scale, acc[mi][ni][1] * scale, hw, lw);
                        *reinterpret_cast<uint32_t*>(sm + rr * 144 + lc2) = hw;
                        *reinterpret_cast<uint32_t*>(sm + 36864 + rr * 144 + lc2) = lw;
                        split_pack(acc[mi][ni][2] * scale, acc[mi][ni][3] * scale, hw, lw);
                        *reinterpret_cast<uint32_t*>(sm + (rr + 8) * 144 + lc2) = hw;
                        *reinterpret_cast<uint32_t*>(sm + 36864 + (rr + 8) * 144 + lc2) = lw;
                    }
            }
            __syncthreads();
            if (tid == 0) {
                FENCE_ASYNC();
                int h = (col0 >> 6) + hh;
                size_t off = (((size_t)(b0 * NH + h)) * SEQ + t0) * 144;
                BULK_ST((char*)Chi + off, sb, 36864);
                BULK_ST((char*)Clo + off, sb + 36864, 36864);
                BULK_COMMIT();
                BULK_WAIT0();
            }
            __syncthreads();
        }
    }
}

__global__ void __launch_bounds__(512, 1)
gemm_qkv_kernel() {
    int z = blockIdx.z;
    const char* Ah = g_ah + (size_t)z * ABT;
    const char* Al = g_al + (size_t)z * ABT;
    const char* Bh = g_wh + (size_t)z * WBT;
    const char* Bl = g_wl + (size_t)z * WBT;
    __nv_bfloat16* Chi = (z == 0) ? g_qh : (z == 1) ? g_kh : g_vh;
    __nv_bfloat16* Clo = (z == 0) ? g_ql : (z == 1) ? g_kl : g_vl;
    // fold 1/sqrt(64) AND log2(e) into Q so flash works in log2 domain
    float scale = (z == 0) ? 0.125f * 1.4426950408889634f : 1.0f;
    gemm_body<1>(Ah, Al, Bh, Bl, nullptr, Chi, Clo, scale,
                 blockIdx.y * 256, blockIdx.x * 128);
}

__global__ void __launch_bounds__(512, 1)
gemm_o_kernel(float* __restrict__ out) {
    gemm_body<0>(g_aoh, g_aol, g_wh + 3 * WBT, g_wl + 3 * WBT,
                 out, nullptr, nullptr, 1.0f,
                 blockIdx.y * 256, blockIdx.x * 128);
}

// ====================== split / transpose kernels ===========================
__global__ void __launch_bounds__(256)
split_act_kernel(const float* __restrict__ q, const float* __restrict__ k,
                 const float* __restrict__ v) {
    int z = blockIdx.z;
    const float* src = (z == 0) ? q : (z == 1) ? k : v;
    size_t i4 = (size_t)blockIdx.x * 256 + threadIdx.x;
    float4 x = reinterpret_cast<const float4*>(src)[i4];
    uint32_t h0, l0, h1, l1;
    split_pack(x.x, x.y, h0, l0);
    split_pack(x.z, x.w, h1, l1);
    size_t e0 = i4 * 4;
    int m = (int)(e0 >> 10);
    int k0 = (int)(e0 & 1023);
    size_t off = (size_t)z * ABT + (size_t)(k0 >> 5) * ((size_t)MTOT * 80) +
                 (size_t)m * 80 + (size_t)(k0 & 31) * 2;
    *reinterpret_cast<uint2*>(g_ah + off) = make_uint2(h0, h1);
    *reinterpret_cast<uint2*>(g_al + off) = make_uint2(l0, l1);
}

__global__ void __launch_bounds__(256)
split_w_kernel(const float* __restrict__ Wq, const float* __restrict__ Wk,
               const float* __restrict__ Wv, const float* __restrict__ Wo) {
    __shared__ float tile[32][33];
    int z = blockIdx.z;
    const float* W = (z == 0) ? Wq : (z == 1) ? Wk : (z == 2) ? Wv : Wo;
    int tx = threadIdx.x & 31, ty = threadIdx.x >> 5;
    int k0 = blockIdx.y * 32, n0 = blockIdx.x * 32;
#pragma unroll
    for (int i = 0; i < 4; i++)
        tile[ty + i * 8][tx] = W[(size_t)(k0 + ty + i * 8) * DM + n0 + tx];
    __syncthreads();
#pragma unroll
    for (int i = 0; i < 4; i++) {
        int n = n0 + ty + i * 8;
        int k = k0 + tx;
        __nv_bfloat16 h, l;
        split1(tile[tx][ty + i * 8], h, l);
        size_t off = (size_t)z * WBT + (size_t)(k >> 5) * ((size_t)DM * 80) +
                     (size_t)n * 80 + (size_t)(k & 31) * 2;
        *reinterpret_cast<__nv_bfloat16*>(g_wh + off) = h;
        *reinterpret_cast<__nv_bfloat16*>(g_wl + off) = l;
    }
}

// ====================== tensorized flash attention ==========================
// Br=128 per CTA (8 warps x 16 rows), 256 threads, 2 CTAs/SM. Bc=64 per iter.
// Scores already in log2 domain (LOG2E folded into Q scale).
#define FSTR 144
#define FOP  (64 * FSTR)              // 9216
#define FSTAGE (4 * FOP)              // 36864: Kh,Kl,Vh,Vl
#define QOFF (2 * FSTAGE)             // 73728
#define QOP  (128 * FSTR)             // 18432
#define FBIAS (QOFF + 2 * QOP)        // 110592
#define FMB (FBIAS + 512)             // 111104
#define FLASH_SMEM (FMB + 32)

__global__ void __launch_bounds__(256, 2)
flash_kernel(const int* __restrict__ qpm, const int* __restrict__ kpm) {
    extern __shared__ char sm[];
    const uint32_t sb = smem_u32(sm);
    float* biasp = reinterpret_cast<float*>(sm + FBIAS);

    const int tid = threadIdx.x;
    const int lane = tid & 31;
    const int w = tid >> 5;
    const int grp = lane >> 2;
    const int tig = lane & 3;

    const int qt = gridDim.x - 1 - blockIdx.x;
    const int bh = blockIdx.y;
    const int b = bh >> 4;
    const int h = bh & (NH - 1);
    const size_t bbase = (size_t)bh * SEQ * 144;
    const int qrow0 = qt * 128;
    const int nit = 2 * qt + 2;

    if (tid == 0) {
        MBARRIER_INIT(sb + FMB, 1);
        MBARRIER_INIT(sb + FMB + 8, 1);
        MBARRIER_INIT(sb + FMB + 16, 1);
    }
    __syncthreads();
    if (tid == 0) {
        MBARRIER_EXPECT_TX(sb + FMB + 16, 2 * QOP);
        BULK_LD(sb + QOFF,       (const char*)g_qh + bbase + (size_t)qrow0 * 144, QOP, sb + FMB + 16);
        BULK_LD(sb + QOFF + QOP, (const char*)g_ql + bbase + (size_t)qrow0 * 144, QOP, sb + FMB + 16);
        MBARRIER_EXPECT_TX(sb + FMB, FSTAGE);
        BULK_LD(sb,           (const char*)g_kh + bbase, FOP, sb + FMB);
        BULK_LD(sb + FOP,     (const char*)g_kl + bbase, FOP, sb + FMB);
        BULK_LD(sb + 2 * FOP, (const char*)g_vh + bbase, FOP, sb + FMB);
        BULK_LD(sb + 3 * FOP, (const char*)g_vl + bbase, FOP, sb + FMB);
    }

    float o[8][4];
#pragma unroll
    for (int ni = 0; ni < 8; ni++)
#pragma unroll
        for (int e = 0; e < 4; e++) o[ni][e] = 0.f;
    float m0 = -1e30f, m1 = -1e30f, l0 = 0.f, l1 = 0.f;

    const int a_off = (w * 16 + (lane & 15)) * FSTR + (lane >> 4) * 16;
    const int b_off = ((lane & 7) + ((lane >> 4) << 3)) * FSTR +
                      ((lane >> 3) & 1) * 16;
    const int t_off = (lane & 15) * FSTR + ((lane >> 4) << 3) * 2;

    MBARRIER_WAIT_PARITY(sb + FMB + 16, 0);

    int ph0 = 0, ph1 = 0;
    for (int it = 0; it < nit; it++) {
        const int s = it & 1;
        const int krow0 = it * 64;
        const uint32_t stg = sb + s * FSTAGE;

        if (it + 1 < nit && tid == 0) {
            const size_t ko = bbase + (size_t)(it + 1) * 64 * 144;
            const uint32_t mb = sb + FMB + (s ^ 1) * 8;
            const uint32_t d = sb + (s ^ 1) * FSTAGE;
            MBARRIER_EXPECT_TX(mb, FSTAGE);
            BULK_LD(d,           (const char*)g_kh + ko, FOP, mb);
            BULK_LD(d + FOP,     (const char*)g_kl + ko, FOP, mb);
            BULK_LD(d + 2 * FOP, (const char*)g_vh + ko, FOP, mb);
            BULK_LD(d + 3 * FOP, (const char*)g_vl + ko, FOP, mb);
        }
        if (tid < 64)
            biasp[s * 64 + tid] =
                (kpm[b * SEQ + krow0 + tid] != 0) ? 0.f : -1e30f;

        if (s == 0) { MBARRIER_WAIT_PARITY(sb + FMB, ph0); ph0 ^= 1; }
        else        { MBARRIER_WAIT_PARITY(sb + FMB + 8, ph1); ph1 ^= 1; }
        __syncthreads();

        // ---- S = Q K^T (hi/lo x3) ----
        float sc[8][4];
#pragma unroll
        for (int ni = 0; ni < 8; ni++)
#pragma unroll
            for (int e = 0; e < 4; e++) sc[ni][e] = 0.f;

#pragma unroll
        for (int kd = 0; kd < 4; kd++) {
            uint32_t qfh[4], qfl[4];
            ldsm4(qfh, sb + QOFF + a_off + kd * 32);
            ldsm4(qfl, sb + QOFF + QOP + a_off + kd * 32);
            uint32_t kh[4][4], kl[4][4];
#pragma unroll
            for (int g = 0; g < 4; g++) {
                ldsm4(kh[g], stg + b_off + kd * 32 + g * 16 * FSTR);
                ldsm4(kl[g], stg + FOP + b_off + kd * 32 + g * 16 * FSTR);
            }
#pragma unroll
            for (int ni = 0; ni < 8; ni++) {
                const int g = ni >> 1, sel = (ni & 1) * 2;
                mma_bf16(sc[ni], qfh, &kh[g][sel]);
                mma_bf16(sc[ni], qfh, &kl[g][sel]);
                mma_bf16(sc[ni], qfl, &kh[g][sel]);
            }
        }

        // ---- bias + causal mask ----
#pragma unroll
        for (int ni = 0; ni < 8; ni++) {
            float2 bb = *reinterpret_cast<float2*>(&biasp[s * 64 + ni * 8 + 2 * tig]);
            sc[ni][0] += bb.x; sc[ni][1] += bb.y;
            sc[ni][2] += bb.x; sc[ni][3] += bb.y;
        }
        if (krow0 + 63 > qrow0) {
            const int r0 = qrow0 + w * 16 + grp;
            const int r1 = r0 + 8;
#pragma unroll
            for (int ni = 0; ni < 8; ni++) {
                int c0 = krow0 + ni * 8 + 2 * tig;
                if (c0 > r0) sc[ni][0] = -1e30f;
                if (c0 + 1 > r0) sc[ni][1] = -1e30f;
                if (c0 > r1) sc[ni][2] = -1e30f;
                if (c0 + 1 > r1) sc[ni][3] = -1e30f;
            }
        }

        // ---- online softmax (log2 domain) ----
        float mx0 = -1e30f, mx1 = -1e30f;
#pragma unroll
        for (int ni = 0; ni < 8; ni++) {
            mx0 = fmaxf(mx0, fmaxf(sc[ni][0], sc[ni][1]));
            mx1 = fmaxf(mx1, fmaxf(sc[ni][2], sc[ni][3]));
        }
        mx0 = fmaxf(mx0, __shfl_xor_sync(0xffffffffu, mx0, 1));
        mx0 = fmaxf(mx0, __shfl_xor_sync(0xffffffffu, mx0, 2));
        mx1 = fmaxf(mx1, __shfl_xor_sync(0xffffffffu, mx1, 1));
        mx1 = fmaxf(mx1, __shfl_xor_sync(0xffffffffu, mx1, 2));
        float mn0 = fmaxf(m0, mx0), mn1 = fmaxf(m1, mx1);
        float cr0 = fexp2(m0 - mn0);
        float cr1 = fexp2(m1 - mn1);
        m0 = mn0; m1 = mn1;
#pragma unroll
        for (int ni = 0; ni < 8; ni++) {
            o[ni][0] *= cr0; o[ni][1] *= cr0;
            o[ni][2] *= cr1; o[ni][3] *= cr1;
        }

        // ---- exp/pack interleaved with PV MMAs (hi/lo x3) ----
        float rs0 = 0.f, rs1 = 0.f;
        uint32_t pah[2][4], pal[2][4];
#pragma unroll
        for (int kc = 0; kc < 5; kc++) {
            if (kc < 4) {
                const int par = kc & 1;
#pragma unroll
                for (int j = 0; j < 2; j++) {
                    const int ni = 2 * kc + j;
                    float p0 = fexp2(sc[ni][0] - mn0);
                    float p1 = fexp2(sc[ni][1] - mn0);
                    float p2 = fexp2(sc[ni][2] - mn1);
                    float p3 = fexp2(sc[ni][3] - mn1);
                    rs0 += p0 + p1; rs1 += p2 + p3;
                    split_pack(p0, p1, pah[par][j * 2], pal[par][j * 2]);
                    split_pack(p2, p3, pah[par][j * 2 + 1], pal[par][j * 2 + 1]);
                }
            }
            if (kc > 0) {
                const int kcm = kc - 1;
                const int par = kcm & 1;
                uint32_t vh[4][4], vl[4][4];
#pragma unroll
                for (int g = 0; g < 4; g++) {
                    uint32_t ta = stg + 2 * FOP + kcm * 16 * FSTR + t_off + g * 32;
                    ldsm4t(vh[g], ta);
                    ldsm4t(vl[g], ta + FOP);
                }
#pragma unroll
                for (int ni = 0; ni < 8; ni++) {
                    const int g = ni >> 1, sel = (ni & 1) * 2;
                    mma_bf16(o[ni], pah[par], &vh[g][sel]);
                    mma_bf16(o[ni], pah[par], &vl[g][sel]);
                    mma_bf16(o[ni], pal[par], &vh[g][sel]);
                }
            }
        }
        rs0 += __shfl_xor_sync(0xffffffffu, rs0, 1);
        rs0 += __shfl_xor_sync(0xffffffffu, rs0, 2);
        rs1 += __shfl_xor_sync(0xffffffffu, rs1, 1);
        rs1 += __shfl_xor_sync(0xffffffffu, rs1, 2);
        l0 = l0 * cr0 + rs0;
        l1 = l1 * cr1 + rs1;
        __syncthreads();
    }

    // ---- epilogue: /l, query padding, write bf16 hi/lo k-blocked [kb][m][80B]
    const int r0 = qrow0 + w * 16 + grp;
    const int r1 = r0 + 8;
    float f0 = (l0 > 0.f ? 1.0f / l0 : 0.f) * (float)qpm[b * SEQ + r0];
    float f1 = (l1 > 0.f ? 1.0f / l1 : 0.f) * (float)qpm[b * SEQ + r1];
    const size_t m0r = (size_t)(b * SEQ + r0);
    const size_t m1r = (size_t)(b * SEQ + r1);
#pragma unroll
    for (int ni = 0; ni < 8; ni++) {
        int col = h * HD + ni * 8 + 2 * tig;
        size_t kslab = (size_t)(col >> 5) * ((size_t)MTOT * 80) +
                       (size_t)(col & 31) * 2;
        uint32_t hw, lw;
        split_pack(o[ni][0] * f0, o[ni][1] * f0, hw, lw);
        size_t i0 = kslab + m0r * 80;
        *reinterpret_cast<uint32_t*>(g_aoh + i0) = hw;
        *reinterpret_cast<uint32_t*>(g_aol + i0) = lw;
        split_pack(o[ni][2] * f1, o[ni][3] * f1, hw, lw);
        size_t i1 = kslab + m1r * 80;
        *reinterpret_cast<uint32_t*>(g_aoh + i1) = hw;
        *reinterpret_cast<uint32_t*>(g_aol + i1) = lw;
    }
}

// ---------------- launch -----------------------------------------------------
extern "C" void kernel_launch(void* const* d_in, const int* in_sizes, int n_in,
                              void* d_out, int out_size) {
    const float* q   = (const float*)d_in[0];
    const float* k   = (const float*)d_in[1];
    const float* v   = (const float*)d_in[2];
    const int*   qpm = (const int*)d_in[3];
    const int*   kpm = (const int*)d_in[4];
    const float* Wq  = (const float*)d_in[5];
    const float* Wk  = (const float*)d_in[6];
    const float* Wv  = (const float*)d_in[7];
    const float* Wo  = (const float*)d_in[8];
    float* out = (float*)d_out;

    dim3 gs((MTOT * DM) / (256 * 4), 1, 3);
    split_act_kernel<<<gs, 256>>>(q, k, v);
    split_w_kernel<<<dim3(32, 32, 4), 256>>>(Wq, Wk, Wv, Wo);

    cudaFuncSetAttribute(gemm_qkv_kernel,
                         cudaFuncAttributeMaxDynamicSharedMemorySize, GEMM_SMEM);
    cudaFuncSetAttribute(gemm_o_kernel,
                         cudaFuncAttributeMaxDynamicSharedMemorySize, GEMM_SMEM);
    gemm_qkv_kernel<<<dim3(DM / 128, MTOT / 256, 3), 512, GEMM_SMEM>>>();

    cudaFuncSetAttribute(flash_kernel,
                         cudaFuncAttributeMaxDynamicSharedMemorySize, FLASH_SMEM);
    flash_kernel<<<dim3(SEQ / 128, NB * NH), 256, FLASH_SMEM>>>(qpm, kpm);

    gemm_o_kernel<<<dim3(DM / 128, MTOT / 256), 512, GEMM_SMEM>>>(out);
}

// round 11
// speedup vs baseline: 1.4166x; 1.0442x over previous
#include <cuda_runtime.h>
#include <cuda_bf16.h>
#include <cuda_fp16.h>
#include <cstdint>
#include <math.h>

#define DM   1024
#define NH   16
#define HD   64
#define SEQ  2048
#define NB   4
#define MTOT (NB * SEQ)   // 8192

// ---------------- global scratch: layouts match smem staging ----------------
#define QKV_ROW 72                         // fp16 elements per padded row (144B)
__device__ __half g_qh[(size_t)NB * NH * SEQ * QKV_ROW];
__device__ __half g_ql[(size_t)NB * NH * SEQ * QKV_ROW];
__device__ __half g_kh[(size_t)NB * NH * SEQ * QKV_ROW];
__device__ __half g_kl[(size_t)NB * NH * SEQ * QKV_ROW];
__device__ __half g_vh[(size_t)NB * NH * SEQ * QKV_ROW];
__device__ __half g_vl[(size_t)NB * NH * SEQ * QKV_ROW];

#define ABT ((size_t)32 * MTOT * 80)       // one activation tensor, k-blocked
#define WBT ((size_t)32 * DM * 80)         // one weight tensor, k-blocked
__device__ char g_ah[3 * ABT];
__device__ char g_al[3 * ABT];
__device__ char g_wh[4 * WBT];
__device__ char g_wl[4 * WBT];
__device__ char g_aoh[ABT];
__device__ char g_aol[ABT];

// ============================ helpers =======================================
__device__ __forceinline__ uint32_t smem_u32(const void* p) {
    uint32_t a;
    asm("{ .reg .u64 t; cvta.to.shared.u64 t, %1; cvt.u32.u64 %0, t; }"
        : "=r"(a) : "l"(p));
    return a;
}
#define MBARRIER_INIT(a, c) \
    asm volatile("mbarrier.init.shared.b64 [%0], %1;" :: "r"((uint32_t)(a)), "r"((uint32_t)(c)) : "memory")
#define MBARRIER_EXPECT_TX(a, b) \
    asm volatile("mbarrier.arrive.expect_tx.shared.b64 _, [%0], %1;" :: "r"((uint32_t)(a)), "r"((uint32_t)(b)) : "memory")
#define MBARRIER_WAIT_PARITY(a, par) do {                                        \
    uint32_t _m = (uint32_t)(a); uint32_t _p = (uint32_t)(par); uint32_t _d;     \
    asm volatile("{\n\t.reg .pred p;\n\t"                                        \
        "mbarrier.try_wait.parity.acquire.cta.shared::cta.b64 p, [%1], %2;\n\t"  \
        "selp.b32 %0, 1, 0, p;\n\t}" : "=r"(_d) : "r"(_m), "r"(_p) : "memory");  \
    if (!_d) {                                                                   \
        asm volatile("{\n\t.reg .pred P1;\n\t"                                   \
        "WL_%=:\n\t"                                                             \
        "mbarrier.try_wait.parity.acquire.cta.shared::cta.b64 P1, [%0], %1, 0x989680;\n\t" \
        "@P1 bra.uni WD_%=;\n\t"                                                 \
        "bra.uni WL_%=;\n\t"                                                     \
        "WD_%=:\n\t}" :: "r"(_m), "r"(_p) : "memory");                           \
    } } while (0)
#define BULK_LD(dst, src, size, mbar) \
    asm volatile("cp.async.bulk.shared::cluster.global.mbarrier::complete_tx::bytes [%0], [%1], %2, [%3];" \
                 :: "r"((uint32_t)(dst)), "l"(src), "r"((uint32_t)(size)), "r"((uint32_t)(mbar)) : "memory")
#define BULK_ST(gd, ss, sz) \
    asm volatile("cp.async.bulk.global.shared::cta.bulk_group [%0], [%1], %2;" \
                 :: "l"(gd), "r"((uint32_t)(ss)), "r"((uint32_t)(sz)) : "memory")
#define BULK_COMMIT() asm volatile("cp.async.bulk.commit_group;" ::: "memory")
#define BULK_WAIT0()  asm volatile("cp.async.bulk.wait_group 0;" ::: "memory")
#define FENCE_ASYNC() asm volatile("fence.proxy.async;" ::: "memory")

__device__ __forceinline__ void ldsm4(uint32_t* r, uint32_t addr) {
    asm volatile("ldmatrix.sync.aligned.m8n8.x4.shared.b16 {%0,%1,%2,%3}, [%4];"
                 : "=r"(r[0]), "=r"(r[1]), "=r"(r[2]), "=r"(r[3]) : "r"(addr));
}
__device__ __forceinline__ void ldsm4t(uint32_t* r, uint32_t addr) {
    asm volatile("ldmatrix.sync.aligned.m8n8.x4.trans.shared.b16 {%0,%1,%2,%3}, [%4];"
                 : "=r"(r[0]), "=r"(r[1]), "=r"(r[2]), "=r"(r[3]) : "r"(addr));
}
__device__ __forceinline__ void mma_f16(float* d, const uint32_t* a,
                                        const uint32_t* b) {
    asm volatile(
        "mma.sync.aligned.m16n8k16.row.col.f32.f16.f16.f32 "
        "{%0,%1,%2,%3},{%4,%5,%6,%7},{%8,%9},{%0,%1,%2,%3};"
        : "+f"(d[0]), "+f"(d[1]), "+f"(d[2]), "+f"(d[3])
        : "r"(a[0]), "r"(a[1]), "r"(a[2]), "r"(a[3]), "r"(b[0]), "r"(b[1]));
}
// FMA-pipe exp2: magic-constant range reduction, no F2I/I2F. x in log2 domain.
__device__ __forceinline__ float fexp2(float x) {
    x = fmaxf(x, -125.0f);
    float y = x + 12582912.0f;
    float fi = y - 12582912.0f;
    float f = x - fi;
    uint32_t iy = __float_as_uint(y);
    float p = 0.0013333558f;
    p = fmaf(p, f, 0.0096181291f);
    p = fmaf(p, f, 0.0555041087f);
    p = fmaf(p, f, 0.2402265070f);
    p = fmaf(p, f, 0.6931471806f);
    p = fmaf(p, f, 1.0f);
    return p * __uint_as_float((iy + 0xB4C0007Fu) << 23);
}

__device__ __forceinline__ void split1h(float x, __half& h, __half& l) {
    h = __float2half_rn(x);
    l = __float2half_rn(x - __half2float(h));
}
// pair pack: w = (f16(a) low, f16(b) high)
__device__ __forceinline__ uint32_t pack_f16(float a, float b) {
    uint32_t w;
    asm("cvt.rn.f16x2.f32 %0, %1, %2;" : "=r"(w) : "f"(b), "f"(a));
    return w;
}
// pair split: hw = (f16(a), f16(b)), lw = fp16 residuals
__device__ __forceinline__ void split_pack(float a, float b, uint32_t& hw, uint32_t& lw) {
    hw = pack_f16(a, b);
    __half2 h2 = *reinterpret_cast<__half2*>(&hw);
    float la = a - __low2float(h2);
    float lb = b - __high2float(h2);
    lw = pack_f16(la, lb);
}

// ====================== fp16x3 HMMA GEMM: 256x128x32, 512 thr, 3-stage ======
#define ST_STRIDE 80
#define AOP 20480
#define BOP 10240
#define GSTAGE (2 * AOP + 2 * BOP)    // 61440
#define GMB (3 * GSTAGE)              // 184320
#define GEMM_SMEM (GMB + 64)

__device__ __forceinline__ void gemm_issue(uint32_t sb, int s,
                                           const char* Ah, const char* Al,
                                           const char* Bh, const char* Bl,
                                           int row0, int col0, int kb) {
    uint32_t mb = sb + GMB + s * 8;
    uint32_t dst = sb + s * GSTAGE;
    MBARRIER_EXPECT_TX(mb, GSTAGE);
    size_t ao = (size_t)kb * ((size_t)MTOT * 80) + (size_t)row0 * 80;
    size_t bo = (size_t)kb * ((size_t)DM * 80) + (size_t)col0 * 80;
    BULK_LD(dst,                 Ah + ao, AOP, mb);
    BULK_LD(dst + AOP,           Al + ao, AOP, mb);
    BULK_LD(dst + 2 * AOP,       Bh + bo, BOP, mb);
    BULK_LD(dst + 2 * AOP + BOP, Bl + bo, BOP, mb);
}

// MODE 0: fp32 out [M,DM].  MODE 1: fp16 hi/lo out to padded QKV via bulk S2G.
template <int MODE>
__device__ __forceinline__ void gemm_body(const char* __restrict__ Ah,
                                          const char* __restrict__ Al,
                                          const char* __restrict__ Bh,
                                          const char* __restrict__ Bl,
                                          float* __restrict__ Cf,
                                          __half* __restrict__ Chi,
                                          __half* __restrict__ Clo,
                                          float scale, int row0, int col0) {
    extern __shared__ char sm[];
    const uint32_t sb = smem_u32(sm);
    const int tid = threadIdx.x;
    const int lane = tid & 31;
    const int w = tid >> 5;
    const int wm = w & 3;
    const int wn = w >> 2;

    if (tid == 0) {
        MBARRIER_INIT(sb + GMB, 1);
        MBARRIER_INIT(sb + GMB + 8, 1);
        MBARRIER_INIT(sb + GMB + 16, 1);
    }
    __syncthreads();
    if (tid == 0) {
        gemm_issue(sb, 0, Ah, Al, Bh, Bl, row0, col0, 0);
        gemm_issue(sb, 1, Ah, Al, Bh, Bl, row0, col0, 1);
        gemm_issue(sb, 2, Ah, Al, Bh, Bl, row0, col0, 2);
    }

    float acc[4][4][4];
#pragma unroll
    for (int mi = 0; mi < 4; mi++)
#pragma unroll
        for (int ni = 0; ni < 4; ni++)
#pragma unroll
            for (int e = 0; e < 4; e++) acc[mi][ni][e] = 0.f;

    const int a_off = (wm * 64 + (lane & 15)) * ST_STRIDE + (lane >> 4) * 16;
    const int b_off = (wn * 32 + (lane & 7) + ((lane >> 4) << 3)) * ST_STRIDE +
                      ((lane >> 3) & 1) * 16;

    int ph0 = 0, ph1 = 0, ph2 = 0;
    int s = 0;
    const int NIT = DM / 32;   // 32
    for (int i = 0; i < NIT; i++) {
        if (s == 0)      { MBARRIER_WAIT_PARITY(sb + GMB,      ph0); ph0 ^= 1; }
        else if (s == 1) { MBARRIER_WAIT_PARITY(sb + GMB + 8,  ph1); ph1 ^= 1; }
        else             { MBARRIER_WAIT_PARITY(sb + GMB + 16, ph2); ph2 ^= 1; }
        const uint32_t sbase = sb + s * GSTAGE;
#pragma unroll
        for (int ks = 0; ks < 2; ks++) {
            uint32_t ah[4][4], al[4][4], bh[8], bl[8];
            const uint32_t abase = sbase + a_off + ks * 32;
            const uint32_t bbase = sbase + 2 * AOP + b_off + ks * 32;
#pragma unroll
            for (int mi = 0; mi < 4; mi++) {
                ldsm4(ah[mi], abase + mi * 16 * ST_STRIDE);
                ldsm4(al[mi], abase + mi * 16 * ST_STRIDE + AOP);
            }
#pragma unroll
            for (int p = 0; p < 2; p++) {
                ldsm4(&bh[p * 4], bbase + p * 16 * ST_STRIDE);
                ldsm4(&bl[p * 4], bbase + p * 16 * ST_STRIDE + BOP);
            }
#pragma unroll
            for (int mi = 0; mi < 4; mi++)
#pragma unroll
                for (int ni = 0; ni < 4; ni++) {
                    const uint32_t* fh = &bh[(ni >> 1) * 4 + (ni & 1) * 2];
                    const uint32_t* fl = &bl[(ni >> 1) * 4 + (ni & 1) * 2];
                    mma_f16(acc[mi][ni], ah[mi], fh);
                    mma_f16(acc[mi][ni], ah[mi], fl);
                    mma_f16(acc[mi][ni], al[mi], fh);
                }
        }
        __syncthreads();
        if (i + 3 < NIT && tid == 0)
            gemm_issue(sb, s, Ah, Al, Bh, Bl, row0, col0, i + 3);
        s = (s == 2) ? 0 : s + 1;
    }

    const int grp = lane >> 2;
    const int tig = lane & 3;

    if (MODE == 0) {
#pragma unroll
        for (int mi = 0; mi < 4; mi++)
#pragma unroll
            for (int ni = 0; ni < 4; ni++) {
                int col = col0 + wn * 32 + ni * 8 + tig * 2;
                int rlo = row0 + wm * 64 + mi * 16 + grp;
                *reinterpret_cast<float2*>(Cf + (size_t)rlo * DM + col) =
                    make_float2(acc[mi][ni][0], acc[mi][ni][1]);
                *reinterpret_cast<float2*>(Cf + (size_t)(rlo + 8) * DM + col) =
                    make_float2(acc[mi][ni][2], acc[mi][ni][3]);
            }
    } else {
        // smem-stage one head (hi+lo), bulk-store 36864B each, twice
        const int b0 = row0 >> 11;
        const int t0 = row0 & (SEQ - 1);
#pragma unroll
        for (int hh = 0; hh < 2; hh++) {
            if ((wn >> 1) == hh) {
                const int lcb = (wn & 1) * 32;
#pragma unroll
                for (int mi = 0; mi < 4; mi++)
#pragma unroll
                    for (int ni = 0; ni < 4; ni++) {
                        int lc2 = (lcb + ni * 8 + tig * 2) * 2;
                        int rr = wm * 64 + mi * 16 + grp;
                        uint32_t hw, lw;
                        split_pack(acc[mi][ni][0] * scale, acc[mi][ni][1] * scale, hw, lw);
                        *reinterpret_cast<uint32_t*>(sm + rr * 144 + lc2) = hw;
                        *reinterpret_cast<uint32_t*>(sm + 36864 + rr * 144 + lc2) = lw;
                        split_pack(acc[mi][ni][2] * scale, acc[mi][ni][3] * scale, hw, lw);
                        *reinterpret_cast<uint32_t*>(sm + (rr + 8) * 144 + lc2) = hw;
                        *reinterpret_cast<uint32_t*>(sm + 36864 + (rr + 8) * 144 + lc2) = lw;
                    }
            }
            __syncthreads();
            if (tid == 0) {
                FENCE_ASYNC();
                int h = (col0 >> 6) + hh;
                size_t off = (((size_t)(b0 * NH + h)) * SEQ + t0) * 144;
                BULK_ST((char*)Chi + off, sb, 36864);
                BULK_ST((char*)Clo + off, sb + 36864, 36864);
                BULK_COMMIT();
                BULK_WAIT0();
            }
            __syncthreads();
        }
    }
}

__global__ void __launch_bounds__(512, 1)
gemm_qkv_kernel() {
    int z = blockIdx.z;
    const char* Ah = g_ah + (size_t)z * ABT;
    const char* Al = g_al + (size_t)z * ABT;
    const char* Bh = g_wh + (size_t)z * WBT;
    const char* Bl = g_wl + (size_t)z * WBT;
    __half* Chi = (z == 0) ? g_qh : (z == 1) ? g_kh : g_vh;
    __half* Clo = (z == 0) ? g_ql : (z == 1) ? g_kl : g_vl;
    float scale = (z == 0) ? 0.125f * 1.4426950408889634f : 1.0f;
    gemm_body<1>(Ah, Al, Bh, Bl, nullptr, Chi, Clo, scale,
                 blockIdx.y * 256, blockIdx.x * 128);
}

__global__ void __launch_bounds__(512, 1)
gemm_o_kernel(float* __restrict__ out) {
    gemm_body<0>(g_aoh, g_aol, g_wh + 3 * WBT, g_wl + 3 * WBT,
                 out, nullptr, nullptr, 1.0f,
                 blockIdx.y * 256, blockIdx.x * 128);
}

// ====================== split / transpose kernels ===========================
__global__ void __launch_bounds__(256)
split_act_kernel(const float* __restrict__ q, const float* __restrict__ k,
                 const float* __restrict__ v) {
    int z = blockIdx.z;
    const float* src = (z == 0) ? q : (z == 1) ? k : v;
    size_t i4 = (size_t)blockIdx.x * 256 + threadIdx.x;
    float4 x = reinterpret_cast<const float4*>(src)[i4];
    uint32_t h0, l0, h1, l1;
    split_pack(x.x, x.y, h0, l0);
    split_pack(x.z, x.w, h1, l1);
    size_t e0 = i4 * 4;
    int m = (int)(e0 >> 10);
    int k0 = (int)(e0 & 1023);
    size_t off = (size_t)z * ABT + (size_t)(k0 >> 5) * ((size_t)MTOT * 80) +
                 (size_t)m * 80 + (size_t)(k0 & 31) * 2;
    *reinterpret_cast<uint2*>(g_ah + off) = make_uint2(h0, h1);
    *reinterpret_cast<uint2*>(g_al + off) = make_uint2(l0, l1);
}

__global__ void __launch_bounds__(256)
split_w_kernel(const float* __restrict__ Wq, const float* __restrict__ Wk,
               const float* __restrict__ Wv, const float* __restrict__ Wo) {
    __shared__ float tile[32][33];
    int z = blockIdx.z;
    const float* W = (z == 0) ? Wq : (z == 1) ? Wk : (z == 2) ? Wv : Wo;
    int tx = threadIdx.x & 31, ty = threadIdx.x >> 5;
    int k0 = blockIdx.y * 32, n0 = blockIdx.x * 32;
#pragma unroll
    for (int i = 0; i < 4; i++)
        tile[ty + i * 8][tx] = W[(size_t)(k0 + ty + i * 8) * DM + n0 + tx];
    __syncthreads();
#pragma unroll
    for (int i = 0; i < 4; i++) {
        int n = n0 + ty + i * 8;
        int k = k0 + tx;
        __half h, l;
        split1h(tile[tx][ty + i * 8], h, l);
        size_t off = (size_t)z * WBT + (size_t)(k >> 5) * ((size_t)DM * 80) +
                     (size_t)n * 80 + (size_t)(k & 31) * 2;
        *reinterpret_cast<__half*>(g_wh + off) = h;
        *reinterpret_cast<__half*>(g_wl + off) = l;
    }
}

// ====================== tensorized flash attention ==========================
// Br=128 per CTA (8 warps x 16 rows), 256 threads, 2 CTAs/SM. Bc=64 per iter.
// Scores in log2 domain. QK: fp16 hi/lo x3. PV: single-fp16 P x (Vh + Vl).
#define FSTR 144
#define FOP  (64 * FSTR)              // 9216
#define FSTAGE (4 * FOP)              // 36864: Kh,Kl,Vh,Vl
#define QOFF (2 * FSTAGE)             // 73728
#define QOP  (128 * FSTR)             // 18432
#define FBIAS (QOFF + 2 * QOP)        // 110592
#define FMB (FBIAS + 512)             // 111104
#define FLASH_SMEM (FMB + 32)

__global__ void __launch_bounds__(256, 2)
flash_kernel(const int* __restrict__ qpm, const int* __restrict__ kpm) {
    extern __shared__ char sm[];
    const uint32_t sb = smem_u32(sm);
    float* biasp = reinterpret_cast<float*>(sm + FBIAS);

    const int tid = threadIdx.x;
    const int lane = tid & 31;
    const int w = tid >> 5;
    const int grp = lane >> 2;
    const int tig = lane & 3;

    const int qt = gridDim.x - 1 - blockIdx.x;
    const int bh = blockIdx.y;
    const int b = bh >> 4;
    const int h = bh & (NH - 1);
    const size_t bbase = (size_t)bh * SEQ * 144;
    const int qrow0 = qt * 128;
    const int nit = 2 * qt + 2;

    if (tid == 0) {
        MBARRIER_INIT(sb + FMB, 1);
        MBARRIER_INIT(sb + FMB + 8, 1);
        MBARRIER_INIT(sb + FMB + 16, 1);
    }
    __syncthreads();
    if (tid == 0) {
        MBARRIER_EXPECT_TX(sb + FMB + 16, 2 * QOP);
        BULK_LD(sb + QOFF,       (const char*)g_qh + bbase + (size_t)qrow0 * 144, QOP, sb + FMB + 16);
        BULK_LD(sb + QOFF + QOP, (const char*)g_ql + bbase + (size_t)qrow0 * 144, QOP, sb + FMB + 16);
        MBARRIER_EXPECT_TX(sb + FMB, FSTAGE);
        BULK_LD(sb,           (const char*)g_kh + bbase, FOP, sb + FMB);
        BULK_LD(sb + FOP,     (const char*)g_kl + bbase, FOP, sb + FMB);
        BULK_LD(sb + 2 * FOP, (const char*)g_vh + bbase, FOP, sb + FMB);
        BULK_LD(sb + 3 * FOP, (const char*)g_vl + bbase, FOP, sb + FMB);
    }

    float o[8][4];
#pragma unroll
    for (int ni = 0; ni < 8; ni++)
#pragma unroll
        for (int e = 0; e < 4; e++) o[ni][e] = 0.f;
    float m0 = -1e30f, m1 = -1e30f, l0 = 0.f, l1 = 0.f;

    const int a_off = (w * 16 + (lane & 15)) * FSTR + (lane >> 4) * 16;
    const int b_off = ((lane & 7) + ((lane >> 4) << 3)) * FSTR +
                      ((lane >> 3) & 1) * 16;
    const int t_off = (lane & 15) * FSTR + ((lane >> 4) << 3) * 2;

    MBARRIER_WAIT_PARITY(sb + FMB + 16, 0);

    int ph0 = 0, ph1 = 0;
    for (int it = 0; it < nit; it++) {
        const int s = it & 1;
        const int krow0 = it * 64;
        const uint32_t stg = sb + s * FSTAGE;

        if (it + 1 < nit && tid == 0) {
            const size_t ko = bbase + (size_t)(it + 1) * 64 * 144;
            const uint32_t mb = sb + FMB + (s ^ 1) * 8;
            const uint32_t d = sb + (s ^ 1) * FSTAGE;
            MBARRIER_EXPECT_TX(mb, FSTAGE);
            BULK_LD(d,           (const char*)g_kh + ko, FOP, mb);
            BULK_LD(d + FOP,     (const char*)g_kl + ko, FOP, mb);
            BULK_LD(d + 2 * FOP, (const char*)g_vh + ko, FOP, mb);
            BULK_LD(d + 3 * FOP, (const char*)g_vl + ko, FOP, mb);
        }
        if (tid < 64)
            biasp[s * 64 + tid] =
                (kpm[b * SEQ + krow0 + tid] != 0) ? 0.f : -1e30f;

        if (s == 0) { MBARRIER_WAIT_PARITY(sb + FMB, ph0); ph0 ^= 1; }
        else        { MBARRIER_WAIT_PARITY(sb + FMB + 8, ph1); ph1 ^= 1; }
        __syncthreads();

        // ---- S = Q K^T (fp16 hi/lo x3) ----
        float sc[8][4];
#pragma unroll
        for (int ni = 0; ni < 8; ni++)
#pragma unroll
            for (int e = 0; e < 4; e++) sc[ni][e] = 0.f;

#pragma unroll
        for (int kd = 0; kd < 4; kd++) {
            uint32_t qfh[4], qfl[4];
            ldsm4(qfh, sb + QOFF + a_off + kd * 32);
            ldsm4(qfl, sb + QOFF + QOP + a_off + kd * 32);
            uint32_t kh[4][4], kl[4][4];
#pragma unroll
            for (int g = 0; g < 4; g++) {
                ldsm4(kh[g], stg + b_off + kd * 32 + g * 16 * FSTR);
                ldsm4(kl[g], stg + FOP + b_off + kd * 32 + g * 16 * FSTR);
            }
#pragma unroll
            for (int ni = 0; ni < 8; ni++) {
                const int g = ni >> 1, sel = (ni & 1) * 2;
                mma_f16(sc[ni], qfh, &kh[g][sel]);
                mma_f16(sc[ni], qfh, &kl[g][sel]);
                mma_f16(sc[ni], qfl, &kh[g][sel]);
            }
        }

        // ---- bias + causal mask ----
#pragma unroll
        for (int ni = 0; ni < 8; ni++) {
            float2 bb = *reinterpret_cast<float2*>(&biasp[s * 64 + ni * 8 + 2 * tig]);
            sc[ni][0] += bb.x; sc[ni][1] += bb.y;
            sc[ni][2] += bb.x; sc[ni][3] += bb.y;
        }
        if (krow0 + 63 > qrow0) {
            const int r0 = qrow0 + w * 16 + grp;
            const int r1 = r0 + 8;
#pragma unroll
            for (int ni = 0; ni < 8; ni++) {
                int c0 = krow0 + ni * 8 + 2 * tig;
                if (c0 > r0) sc[ni][0] = -1e30f;
                if (c0 + 1 > r0) sc[ni][1] = -1e30f;
                if (c0 > r1) sc[ni][2] = -1e30f;
                if (c0 + 1 > r1) sc[ni][3] = -1e30f;
            }
        }

        // ---- online softmax (log2 domain) ----
        float mx0 = -1e30f, mx1 = -1e30f;
#pragma unroll
        for (int ni = 0; ni < 8; ni++) {
            mx0 = fmaxf(mx0, fmaxf(sc[ni][0], sc[ni][1]));
            mx1 = fmaxf(mx1, fmaxf(sc[ni][2], sc[ni][3]));
        }
        mx0 = fmaxf(mx0, __shfl_xor_sync(0xffffffffu, mx0, 1));
        mx0 = fmaxf(mx0, __shfl_xor_sync(0xffffffffu, mx0, 2));
        mx1 = fmaxf(mx1, __shfl_xor_sync(0xffffffffu, mx1, 1));
        mx1 = fmaxf(mx1, __shfl_xor_sync(0xffffffffu, mx1, 2));
        float mn0 = fmaxf(m0, mx0), mn1 = fmaxf(m1, mx1);
        float cr0 = fexp2(m0 - mn0);
        float cr1 = fexp2(m1 - mn1);
        m0 = mn0; m1 = mn1;
#pragma unroll
        for (int ni = 0; ni < 8; ni++) {
            o[ni][0] *= cr0; o[ni][1] *= cr0;
            o[ni][2] *= cr1; o[ni][3] *= cr1;
        }

        // ---- exp/pack (single-fp16 P) interleaved with PV MMAs (x2) ----
        float rs0 = 0.f, rs1 = 0.f;
        uint32_t pa[2][4];
#pragma unroll
        for (int kc = 0; kc < 5; kc++) {
            if (kc < 4) {
                const int par = kc & 1;
#pragma unroll
                for (int j = 0; j < 2; j++) {
                    const int ni = 2 * kc + j;
                    float p0 = fexp2(sc[ni][0] - mn0);
                    float p1 = fexp2(sc[ni][1] - mn0);
                    float p2 = fexp2(sc[ni][2] - mn1);
                    float p3 = fexp2(sc[ni][3] - mn1);
                    rs0 += p0 + p1; rs1 += p2 + p3;
                    pa[par][j * 2]     = pack_f16(p0, p1);
                    pa[par][j * 2 + 1] = pack_f16(p2, p3);
                }
            }
            if (kc > 0) {
                const int kcm = kc - 1;
                const int par = kcm & 1;
                uint32_t vh[4][4], vl[4][4];
#pragma unroll
                for (int g = 0; g < 4; g++) {
                    uint32_t ta = stg + 2 * FOP + kcm * 16 * FSTR + t_off + g * 32;
                    ldsm4t(vh[g], ta);
                    ldsm4t(vl[g], ta + FOP);
                }
#pragma unroll
                for (int ni = 0; ni < 8; ni++) {
                    const int g = ni >> 1, sel = (ni & 1) * 2;
                    mma_f16(o[ni], pa[par], &vh[g][sel]);
                    mma_f16(o[ni], pa[par], &vl[g][sel]);
                }
            }
        }
        rs0 += __shfl_xor_sync(0xffffffffu, rs0, 1);
        rs0 += __shfl_xor_sync(0xffffffffu, rs0, 2);
        rs1 += __shfl_xor_sync(0xffffffffu, rs1, 1);
        rs1 += __shfl_xor_sync(0xffffffffu, rs1, 2);
        l0 = l0 * cr0 + rs0;
        l1 = l1 * cr1 + rs1;
        __syncthreads();
    }

    // ---- epilogue: /l, query padding, write fp16 hi/lo k-blocked [kb][m][80B]
    const int r0 = qrow0 + w * 16 + grp;
    const int r1 = r0 + 8;
    float f0 = (l0 > 0.f ? 1.0f / l0 : 0.f) * (float)qpm[b * SEQ + r0];
    float f1 = (l1 > 0.f ? 1.0f / l1 : 0.f) * (float)qpm[b * SEQ + r1];
    const size_t m0r = (size_t)(b * SEQ + r0);
    const size_t m1r = (size_t)(b * SEQ + r1);
#pragma unroll
    for (int ni = 0; ni < 8; ni++) {
        int col = h * HD + ni * 8 + 2 * tig;
        size_t kslab = (size_t)(col >> 5) * ((size_t)MTOT * 80) +
                       (size_t)(col & 31) * 2;
        uint32_t hw, lw;
        split_pack(o[ni][0] * f0, o[ni][1] * f0, hw, lw);
        size_t i0 = kslab + m0r * 80;
        *reinterpret_cast<uint32_t*>(g_aoh + i0) = hw;
        *reinterpret_cast<uint32_t*>(g_aol + i0) = lw;
        split_pack(o[ni][2] * f1, o[ni][3] * f1, hw, lw);
        size_t i1 = kslab + m1r * 80;
        *reinterpret_cast<uint32_t*>(g_aoh + i1) = hw;
        *reinterpret_cast<uint32_t*>(g_aol + i1) = lw;
    }
}

// ---------------- launch -----------------------------------------------------
extern "C" void kernel_launch(void* const* d_in, const int* in_sizes, int n_in,
                              void* d_out, int out_size) {
    const float* q   = (const float*)d_in[0];
    const float* k   = (const float*)d_in[1];
    const float* v   = (const float*)d_in[2];
    const int*   qpm = (const int*)d_in[3];
    const int*   kpm = (const int*)d_in[4];
    const float* Wq  = (const float*)d_in[5];
    const float* Wk  = (const float*)d_in[6];
    const float* Wv  = (const float*)d_in[7];
    const float* Wo  = (const float*)d_in[8];
    float* out = (float*)d_out;

    dim3 gs((MTOT * DM) / (256 * 4), 1, 3);
    split_act_kernel<<<gs, 256>>>(q, k, v);
    split_w_kernel<<<dim3(32, 32, 4), 256>>>(Wq, Wk, Wv, Wo);

    cudaFuncSetAttribute(gemm_qkv_kernel,
                         cudaFuncAttributeMaxDynamicSharedMemorySize, GEMM_SMEM);
    cudaFuncSetAttribute(gemm_o_kernel,
                         cudaFuncAttributeMaxDynamicSharedMemorySize, GEMM_SMEM);
    gemm_qkv_kernel<<<dim3(DM / 128, MTOT / 256, 3), 512, GEMM_SMEM>>>();

    cudaFuncSetAttribute(flash_kernel,
                         cudaFuncAttributeMaxDynamicSharedMemorySize, FLASH_SMEM);
    flash_kernel<<<dim3(SEQ / 128, NB * NH), 256, FLASH_SMEM>>>(qpm, kpm);

    gemm_o_kernel<<<dim3(DM / 128, MTOT / 256), 512, GEMM_SMEM>>>(out);
}

// round 12
// speedup vs baseline: 1.5512x; 1.0951x over previous
#include <cuda_runtime.h>
#include <cuda_bf16.h>
#include <cuda_fp16.h>
#include <cstdint>
#include <math.h>

#define DM   1024
#define NH   16
#define HD   64
#define SEQ  2048
#define NB   4
#define MTOT (NB * SEQ)   // 8192

// ---------------- global scratch: layouts match smem staging ----------------
#define QKV_ROW 72                         // fp16 elements per padded row (144B)
__device__ __half g_qh[(size_t)NB * NH * SEQ * QKV_ROW];
__device__ __half g_ql[(size_t)NB * NH * SEQ * QKV_ROW];
__device__ __half g_kh[(size_t)NB * NH * SEQ * QKV_ROW];   // K single fp16
__device__ __half g_vh[(size_t)NB * NH * SEQ * QKV_ROW];   // V single fp16

#define ABT ((size_t)32 * MTOT * 80)       // one activation tensor, k-blocked
#define WBT ((size_t)32 * DM * 80)         // one weight tensor, k-blocked
__device__ char g_ah[3 * ABT];
__device__ char g_al[3 * ABT];
__device__ char g_wh[4 * WBT];
__device__ char g_wl[4 * WBT];
__device__ char g_aoh[ABT];
__device__ char g_aol[ABT];

// ============================ helpers =======================================
__device__ __forceinline__ uint32_t smem_u32(const void* p) {
    uint32_t a;
    asm("{ .reg .u64 t; cvta.to.shared.u64 t, %1; cvt.u32.u64 %0, t; }"
        : "=r"(a) : "l"(p));
    return a;
}
#define MBARRIER_INIT(a, c) \
    asm volatile("mbarrier.init.shared.b64 [%0], %1;" :: "r"((uint32_t)(a)), "r"((uint32_t)(c)) : "memory")
#define MBARRIER_EXPECT_TX(a, b) \
    asm volatile("mbarrier.arrive.expect_tx.shared.b64 _, [%0], %1;" :: "r"((uint32_t)(a)), "r"((uint32_t)(b)) : "memory")
#define MBARRIER_WAIT_PARITY(a, par) do {                                        \
    uint32_t _m = (uint32_t)(a); uint32_t _p = (uint32_t)(par); uint32_t _d;     \
    asm volatile("{\n\t.reg .pred p;\n\t"                                        \
        "mbarrier.try_wait.parity.acquire.cta.shared::cta.b64 p, [%1], %2;\n\t"  \
        "selp.b32 %0, 1, 0, p;\n\t}" : "=r"(_d) : "r"(_m), "r"(_p) : "memory");  \
    if (!_d) {                                                                   \
        asm volatile("{\n\t.reg .pred P1;\n\t"                                   \
        "WL_%=:\n\t"                                                             \
        "mbarrier.try_wait.parity.acquire.cta.shared::cta.b64 P1, [%0], %1, 0x989680;\n\t" \
        "@P1 bra.uni WD_%=;\n\t"                                                 \
        "bra.uni WL_%=;\n\t"                                                     \
        "WD_%=:\n\t}" :: "r"(_m), "r"(_p) : "memory");                           \
    } } while (0)
#define BULK_LD(dst, src, size, mbar) \
    asm volatile("cp.async.bulk.shared::cluster.global.mbarrier::complete_tx::bytes [%0], [%1], %2, [%3];" \
                 :: "r"((uint32_t)(dst)), "l"(src), "r"((uint32_t)(size)), "r"((uint32_t)(mbar)) : "memory")
#define BULK_ST(gd, ss, sz) \
    asm volatile("cp.async.bulk.global.shared::cta.bulk_group [%0], [%1], %2;" \
                 :: "l"(gd), "r"((uint32_t)(ss)), "r"((uint32_t)(sz)) : "memory")
#define BULK_COMMIT() asm volatile("cp.async.bulk.commit_group;" ::: "memory")
#define BULK_WAIT0()  asm volatile("cp.async.bulk.wait_group 0;" ::: "memory")
#define FENCE_ASYNC() asm volatile("fence.proxy.async;" ::: "memory")

__device__ __forceinline__ void ldsm4(uint32_t* r, uint32_t addr) {
    asm volatile("ldmatrix.sync.aligned.m8n8.x4.shared.b16 {%0,%1,%2,%3}, [%4];"
                 : "=r"(r[0]), "=r"(r[1]), "=r"(r[2]), "=r"(r[3]) : "r"(addr));
}
__device__ __forceinline__ void ldsm4t(uint32_t* r, uint32_t addr) {
    asm volatile("ldmatrix.sync.aligned.m8n8.x4.trans.shared.b16 {%0,%1,%2,%3}, [%4];"
                 : "=r"(r[0]), "=r"(r[1]), "=r"(r[2]), "=r"(r[3]) : "r"(addr));
}
__device__ __forceinline__ void mma_f16(float* d, const uint32_t* a,
                                        const uint32_t* b) {
    asm volatile(
        "mma.sync.aligned.m16n8k16.row.col.f32.f16.f16.f32 "
        "{%0,%1,%2,%3},{%4,%5,%6,%7},{%8,%9},{%0,%1,%2,%3};"
        : "+f"(d[0]), "+f"(d[1]), "+f"(d[2]), "+f"(d[3])
        : "r"(a[0]), "r"(a[1]), "r"(a[2]), "r"(a[3]), "r"(b[0]), "r"(b[1]));
}
// FMA-pipe exp2: magic-constant range reduction, no F2I/I2F. x in log2 domain.
__device__ __forceinline__ float fexp2(float x) {
    x = fmaxf(x, -125.0f);
    float y = x + 12582912.0f;
    float fi = y - 12582912.0f;
    float f = x - fi;
    uint32_t iy = __float_as_uint(y);
    float p = 0.0013333558f;
    p = fmaf(p, f, 0.0096181291f);
    p = fmaf(p, f, 0.0555041087f);
    p = fmaf(p, f, 0.2402265070f);
    p = fmaf(p, f, 0.6931471806f);
    p = fmaf(p, f, 1.0f);
    return p * __uint_as_float((iy + 0xB4C0007Fu) << 23);
}

__device__ __forceinline__ void split1h(float x, __half& h, __half& l) {
    h = __float2half_rn(x);
    l = __float2half_rn(x - __half2float(h));
}
__device__ __forceinline__ uint32_t pack_f16(float a, float b) {
    uint32_t w;
    asm("cvt.rn.f16x2.f32 %0, %1, %2;" : "=r"(w) : "f"(b), "f"(a));
    return w;
}
__device__ __forceinline__ void split_pack(float a, float b, uint32_t& hw, uint32_t& lw) {
    hw = pack_f16(a, b);
    __half2 h2 = *reinterpret_cast<__half2*>(&hw);
    float la = a - __low2float(h2);
    float lb = b - __high2float(h2);
    lw = pack_f16(la, lb);
}

// ====================== fp16x3 HMMA GEMM: 256x128x32, 512 thr, 3-stage ======
#define ST_STRIDE 80
#define AOP 20480
#define BOP 10240
#define GSTAGE (2 * AOP + 2 * BOP)    // 61440
#define GMB (3 * GSTAGE)              // 184320
#define GEMM_SMEM (GMB + 64)

__device__ __forceinline__ void gemm_issue(uint32_t sb, int s,
                                           const char* Ah, const char* Al,
                                           const char* Bh, const char* Bl,
                                           int row0, int col0, int kb) {
    uint32_t mb = sb + GMB + s * 8;
    uint32_t dst = sb + s * GSTAGE;
    MBARRIER_EXPECT_TX(mb, GSTAGE);
    size_t ao = (size_t)kb * ((size_t)MTOT * 80) + (size_t)row0 * 80;
    size_t bo = (size_t)kb * ((size_t)DM * 80) + (size_t)col0 * 80;
    BULK_LD(dst,                 Ah + ao, AOP, mb);
    BULK_LD(dst + AOP,           Al + ao, AOP, mb);
    BULK_LD(dst + 2 * AOP,       Bh + bo, BOP, mb);
    BULK_LD(dst + 2 * AOP + BOP, Bl + bo, BOP, mb);
}

// MODE 0: fp32 out [M,DM].  MODE 1: fp16 hi+lo out (Q).  MODE 2: fp16 hi only.
template <int MODE>
__device__ __forceinline__ void gemm_body(const char* __restrict__ Ah,
                                          const char* __restrict__ Al,
                                          const char* __restrict__ Bh,
                                          const char* __restrict__ Bl,
                                          float* __restrict__ Cf,
                                          __half* __restrict__ Chi,
                                          __half* __restrict__ Clo,
                                          float scale, int row0, int col0) {
    extern __shared__ char sm[];
    const uint32_t sb = smem_u32(sm);
    const int tid = threadIdx.x;
    const int lane = tid & 31;
    const int w = tid >> 5;
    const int wm = w & 3;
    const int wn = w >> 2;

    if (tid == 0) {
        MBARRIER_INIT(sb + GMB, 1);
        MBARRIER_INIT(sb + GMB + 8, 1);
        MBARRIER_INIT(sb + GMB + 16, 1);
    }
    __syncthreads();
    if (tid == 0) {
        gemm_issue(sb, 0, Ah, Al, Bh, Bl, row0, col0, 0);
        gemm_issue(sb, 1, Ah, Al, Bh, Bl, row0, col0, 1);
        gemm_issue(sb, 2, Ah, Al, Bh, Bl, row0, col0, 2);
    }

    float acc[4][4][4];
#pragma unroll
    for (int mi = 0; mi < 4; mi++)
#pragma unroll
        for (int ni = 0; ni < 4; ni++)
#pragma unroll
            for (int e = 0; e < 4; e++) acc[mi][ni][e] = 0.f;

    const int a_off = (wm * 64 + (lane & 15)) * ST_STRIDE + (lane >> 4) * 16;
    const int b_off = (wn * 32 + (lane & 7) + ((lane >> 4) << 3)) * ST_STRIDE +
                      ((lane >> 3) & 1) * 16;

    int ph0 = 0, ph1 = 0, ph2 = 0;
    int s = 0;
    const int NIT = DM / 32;   // 32
    for (int i = 0; i < NIT; i++) {
        if (s == 0)      { MBARRIER_WAIT_PARITY(sb + GMB,      ph0); ph0 ^= 1; }
        else if (s == 1) { MBARRIER_WAIT_PARITY(sb + GMB + 8,  ph1); ph1 ^= 1; }
        else             { MBARRIER_WAIT_PARITY(sb + GMB + 16, ph2); ph2 ^= 1; }
        const uint32_t sbase = sb + s * GSTAGE;
#pragma unroll
        for (int ks = 0; ks < 2; ks++) {
            uint32_t ah[4][4], al[4][4], bh[8], bl[8];
            const uint32_t abase = sbase + a_off + ks * 32;
            const uint32_t bbase = sbase + 2 * AOP + b_off + ks * 32;
#pragma unroll
            for (int mi = 0; mi < 4; mi++) {
                ldsm4(ah[mi], abase + mi * 16 * ST_STRIDE);
                ldsm4(al[mi], abase + mi * 16 * ST_STRIDE + AOP);
            }
#pragma unroll
            for (int p = 0; p < 2; p++) {
                ldsm4(&bh[p * 4], bbase + p * 16 * ST_STRIDE);
                ldsm4(&bl[p * 4], bbase + p * 16 * ST_STRIDE + BOP);
            }
#pragma unroll
            for (int mi = 0; mi < 4; mi++)
#pragma unroll
                for (int ni = 0; ni < 4; ni++) {
                    const uint32_t* fh = &bh[(ni >> 1) * 4 + (ni & 1) * 2];
                    const uint32_t* fl = &bl[(ni >> 1) * 4 + (ni & 1) * 2];
                    mma_f16(acc[mi][ni], ah[mi], fh);
                    mma_f16(acc[mi][ni], ah[mi], fl);
                    mma_f16(acc[mi][ni], al[mi], fh);
                }
        }
        __syncthreads();
        if (i + 3 < NIT && tid == 0)
            gemm_issue(sb, s, Ah, Al, Bh, Bl, row0, col0, i + 3);
        s = (s == 2) ? 0 : s + 1;
    }

    const int grp = lane >> 2;
    const int tig = lane & 3;

    if (MODE == 0) {
#pragma unroll
        for (int mi = 0; mi < 4; mi++)
#pragma unroll
            for (int ni = 0; ni < 4; ni++) {
                int col = col0 + wn * 32 + ni * 8 + tig * 2;
                int rlo = row0 + wm * 64 + mi * 16 + grp;
                *reinterpret_cast<float2*>(Cf + (size_t)rlo * DM + col) =
                    make_float2(acc[mi][ni][0], acc[mi][ni][1]);
                *reinterpret_cast<float2*>(Cf + (size_t)(rlo + 8) * DM + col) =
                    make_float2(acc[mi][ni][2], acc[mi][ni][3]);
            }
    } else {
        // smem-stage one head (hi [+lo]), bulk-store 36864B blocks, twice
        const int b0 = row0 >> 11;
        const int t0 = row0 & (SEQ - 1);
#pragma unroll
        for (int hh = 0; hh < 2; hh++) {
            if ((wn >> 1) == hh) {
                const int lcb = (wn & 1) * 32;
#pragma unroll
                for (int mi = 0; mi < 4; mi++)
#pragma unroll
                    for (int ni = 0; ni < 4; ni++) {
                        int lc2 = (lcb + ni * 8 + tig * 2) * 2;
                        int rr = wm * 64 + mi * 16 + grp;
                        uint32_t hw, lw;
                        split_pack(acc[mi][ni][0] * scale, acc[mi][ni][1] * scale, hw, lw);
                        *reinterpret_cast<uint32_t*>(sm + rr * 144 + lc2) = hw;
                        if (MODE == 1)
                            *reinterpret_cast<uint32_t*>(sm + 36864 + rr * 144 + lc2) = lw;
                        split_pack(acc[mi][ni][2] * scale, acc[mi][ni][3] * scale, hw, lw);
                        *reinterpret_cast<uint32_t*>(sm + (rr + 8) * 144 + lc2) = hw;
                        if (MODE == 1)
                            *reinterpret_cast<uint32_t*>(sm + 36864 + (rr + 8) * 144 + lc2) = lw;
                    }
            }
            __syncthreads();
            if (tid == 0) {
                FENCE_ASYNC();
                int h = (col0 >> 6) + hh;
                size_t off = (((size_t)(b0 * NH + h)) * SEQ + t0) * 144;
                BULK_ST((char*)Chi + off, sb, 36864);
                if (MODE == 1)
                    BULK_ST((char*)Clo + off, sb + 36864, 36864);
                BULK_COMMIT();
                BULK_WAIT0();
            }
            __syncthreads();
        }
    }
}

__global__ void __launch_bounds__(512, 1)
gemm_qkv_kernel() {
    int z = blockIdx.z;
    const char* Ah = g_ah + (size_t)z * ABT;
    const char* Al = g_al + (size_t)z * ABT;
    const char* Bh = g_wh + (size_t)z * WBT;
    const char* Bl = g_wl + (size_t)z * WBT;
    if (z == 0) {
        gemm_body<1>(Ah, Al, Bh, Bl, nullptr, g_qh, g_ql,
                     0.125f * 1.4426950408889634f,
                     blockIdx.y * 256, blockIdx.x * 128);
    } else {
        __half* Chi = (z == 1) ? g_kh : g_vh;
        gemm_body<2>(Ah, Al, Bh, Bl, nullptr, Chi, nullptr, 1.0f,
                     blockIdx.y * 256, blockIdx.x * 128);
    }
}

__global__ void __launch_bounds__(512, 1)
gemm_o_kernel(float* __restrict__ out) {
    gemm_body<0>(g_aoh, g_aol, g_wh + 3 * WBT, g_wl + 3 * WBT,
                 out, nullptr, nullptr, 1.0f,
                 blockIdx.y * 256, blockIdx.x * 128);
}

// ====================== split / transpose kernels ===========================
__global__ void __launch_bounds__(256)
split_act_kernel(const float* __restrict__ q, const float* __restrict__ k,
                 const float* __restrict__ v) {
    int z = blockIdx.z;
    const float* src = (z == 0) ? q : (z == 1) ? k : v;
    size_t i4 = (size_t)blockIdx.x * 256 + threadIdx.x;
    float4 x = reinterpret_cast<const float4*>(src)[i4];
    uint32_t h0, l0, h1, l1;
    split_pack(x.x, x.y, h0, l0);
    split_pack(x.z, x.w, h1, l1);
    size_t e0 = i4 * 4;
    int m = (int)(e0 >> 10);
    int k0 = (int)(e0 & 1023);
    size_t off = (size_t)z * ABT + (size_t)(k0 >> 5) * ((size_t)MTOT * 80) +
                 (size_t)m * 80 + (size_t)(k0 & 31) * 2;
    *reinterpret_cast<uint2*>(g_ah + off) = make_uint2(h0, h1);
    *reinterpret_cast<uint2*>(g_al + off) = make_uint2(l0, l1);
}

__global__ void __launch_bounds__(256)
split_w_kernel(const float* __restrict__ Wq, const float* __restrict__ Wk,
               const float* __restrict__ Wv, const float* __restrict__ Wo) {
    __shared__ float tile[32][33];
    int z = blockIdx.z;
    const float* W = (z == 0) ? Wq : (z == 1) ? Wk : (z == 2) ? Wv : Wo;
    int tx = threadIdx.x & 31, ty = threadIdx.x >> 5;
    int k0 = blockIdx.y * 32, n0 = blockIdx.x * 32;
#pragma unroll
    for (int i = 0; i < 4; i++)
        tile[ty + i * 8][tx] = W[(size_t)(k0 + ty + i * 8) * DM + n0 + tx];
    __syncthreads();
#pragma unroll
    for (int i = 0; i < 4; i++) {
        int n = n0 + ty + i * 8;
        int k = k0 + tx;
        __half h, l;
        split1h(tile[tx][ty + i * 8], h, l);
        size_t off = (size_t)z * WBT + (size_t)(k >> 5) * ((size_t)DM * 80) +
                     (size_t)n * 80 + (size_t)(k & 31) * 2;
        *reinterpret_cast<__half*>(g_wh + off) = h;
        *reinterpret_cast<__half*>(g_wl + off) = l;
    }
}

// ====================== tensorized flash attention ==========================
// Br=128 per CTA (8 warps x 16 rows), 256 threads, 2 CTAs/SM. Bc=64 per iter.
// log2 domain. QK: (Qh+Ql)·Kh = 2 MMAs. PV: P·Vh = 1 MMA. K,V single fp16.
#define FSTR 144
#define FOP  (64 * FSTR)              // 9216
#define FSTAGE (2 * FOP)              // 18432: Kh,Vh
#define QOFF (2 * FSTAGE)             // 36864
#define QOP  (128 * FSTR)             // 18432
#define FBIAS (QOFF + 2 * QOP)        // 73728
#define FMB (FBIAS + 512)             // 74240
#define FLASH_SMEM (FMB + 32)

__global__ void __launch_bounds__(256, 2)
flash_kernel(const int* __restrict__ qpm, const int* __restrict__ kpm) {
    extern __shared__ char sm[];
    const uint32_t sb = smem_u32(sm);
    float* biasp = reinterpret_cast<float*>(sm + FBIAS);

    const int tid = threadIdx.x;
    const int lane = tid & 31;
    const int w = tid >> 5;
    const int grp = lane >> 2;
    const int tig = lane & 3;

    const int qt = gridDim.x - 1 - blockIdx.x;
    const int bh = blockIdx.y;
    const int b = bh >> 4;
    const int h = bh & (NH - 1);
    const size_t bbase = (size_t)bh * SEQ * 144;
    const int qrow0 = qt * 128;
    const int nit = 2 * qt + 2;

    if (tid == 0) {
        MBARRIER_INIT(sb + FMB, 1);
        MBARRIER_INIT(sb + FMB + 8, 1);
        MBARRIER_INIT(sb + FMB + 16, 1);
    }
    __syncthreads();
    if (tid == 0) {
        MBARRIER_EXPECT_TX(sb + FMB + 16, 2 * QOP);
        BULK_LD(sb + QOFF,       (const char*)g_qh + bbase + (size_t)qrow0 * 144, QOP, sb + FMB + 16);
        BULK_LD(sb + QOFF + QOP, (const char*)g_ql + bbase + (size_t)qrow0 * 144, QOP, sb + FMB + 16);
        MBARRIER_EXPECT_TX(sb + FMB, FSTAGE);
        BULK_LD(sb,       (const char*)g_kh + bbase, FOP, sb + FMB);
        BULK_LD(sb + FOP, (const char*)g_vh + bbase, FOP, sb + FMB);
    }

    float o[8][4];
#pragma unroll
    for (int ni = 0; ni < 8; ni++)
#pragma unroll
        for (int e = 0; e < 4; e++) o[ni][e] = 0.f;
    float m0 = -1e30f, m1 = -1e30f, l0 = 0.f, l1 = 0.f;

    const int a_off = (w * 16 + (lane & 15)) * FSTR + (lane >> 4) * 16;
    const int b_off = ((lane & 7) + ((lane >> 4) << 3)) * FSTR +
                      ((lane >> 3) & 1) * 16;
    const int t_off = (lane & 15) * FSTR + ((lane >> 4) << 3) * 2;

    MBARRIER_WAIT_PARITY(sb + FMB + 16, 0);

    int ph0 = 0, ph1 = 0;
    for (int it = 0; it < nit; it++) {
        const int s = it & 1;
        const int krow0 = it * 64;
        const uint32_t stg = sb + s * FSTAGE;

        if (it + 1 < nit && tid == 0) {
            const size_t ko = bbase + (size_t)(it + 1) * 64 * 144;
            const uint32_t mb = sb + FMB + (s ^ 1) * 8;
            const uint32_t d = sb + (s ^ 1) * FSTAGE;
            MBARRIER_EXPECT_TX(mb, FSTAGE);
            BULK_LD(d,       (const char*)g_kh + ko, FOP, mb);
            BULK_LD(d + FOP, (const char*)g_vh + ko, FOP, mb);
        }
        if (tid < 64)
            biasp[s * 64 + tid] =
                (kpm[b * SEQ + krow0 + tid] != 0) ? 0.f : -1e30f;

        if (s == 0) { MBARRIER_WAIT_PARITY(sb + FMB, ph0); ph0 ^= 1; }
        else        { MBARRIER_WAIT_PARITY(sb + FMB + 8, ph1); ph1 ^= 1; }
        __syncthreads();

        // ---- S = Q K^T: (Qh + Ql) · Kh, 2 MMAs per fragment ----
        float sc[8][4];
#pragma unroll
        for (int ni = 0; ni < 8; ni++)
#pragma unroll
            for (int e = 0; e < 4; e++) sc[ni][e] = 0.f;

#pragma unroll
        for (int kd = 0; kd < 4; kd++) {
            uint32_t qfh[4], qfl[4];
            ldsm4(qfh, sb + QOFF + a_off + kd * 32);
            ldsm4(qfl, sb + QOFF + QOP + a_off + kd * 32);
            uint32_t kh[4][4];
#pragma unroll
            for (int g = 0; g < 4; g++)
                ldsm4(kh[g], stg + b_off + kd * 32 + g * 16 * FSTR);
#pragma unroll
            for (int ni = 0; ni < 8; ni++) {
                const int g = ni >> 1, sel = (ni & 1) * 2;
                mma_f16(sc[ni], qfh, &kh[g][sel]);
                mma_f16(sc[ni], qfl, &kh[g][sel]);
            }
        }

        // ---- bias + causal mask ----
#pragma unroll
        for (int ni = 0; ni < 8; ni++) {
            float2 bb = *reinterpret_cast<float2*>(&biasp[s * 64 + ni * 8 + 2 * tig]);
            sc[ni][0] += bb.x; sc[ni][1] += bb.y;
            sc[ni][2] += bb.x; sc[ni][3] += bb.y;
        }
        if (krow0 + 63 > qrow0) {
            const int r0 = qrow0 + w * 16 + grp;
            const int r1 = r0 + 8;
#pragma unroll
            for (int ni = 0; ni < 8; ni++) {
                int c0 = krow0 + ni * 8 + 2 * tig;
                if (c0 > r0) sc[ni][0] = -1e30f;
                if (c0 + 1 > r0) sc[ni][1] = -1e30f;
                if (c0 > r1) sc[ni][2] = -1e30f;
                if (c0 + 1 > r1) sc[ni][3] = -1e30f;
            }
        }

        // ---- online softmax (log2 domain) ----
        float mx0 = -1e30f, mx1 = -1e30f;
#pragma unroll
        for (int ni = 0; ni < 8; ni++) {
            mx0 = fmaxf(mx0, fmaxf(sc[ni][0], sc[ni][1]));
            mx1 = fmaxf(mx1, fmaxf(sc[ni][2], sc[ni][3]));
        }
        mx0 = fmaxf(mx0, __shfl_xor_sync(0xffffffffu, mx0, 1));
        mx0 = fmaxf(mx0, __shfl_xor_sync(0xffffffffu, mx0, 2));
        mx1 = fmaxf(mx1, __shfl_xor_sync(0xffffffffu, mx1, 1));
        mx1 = fmaxf(mx1, __shfl_xor_sync(0xffffffffu, mx1, 2));
        float mn0 = fmaxf(m0, mx0), mn1 = fmaxf(m1, mx1);
        float cr0 = fexp2(m0 - mn0);
        float cr1 = fexp2(m1 - mn1);
        m0 = mn0; m1 = mn1;
#pragma unroll
        for (int ni = 0; ni < 8; ni++) {
            o[ni][0] *= cr0; o[ni][1] *= cr0;
            o[ni][2] *= cr1; o[ni][3] *= cr1;
        }

        // ---- exp/pack interleaved with PV MMAs (single-fp16 P, single V) ----
        float rs0 = 0.f, rs1 = 0.f;
        uint32_t pa[2][4];
#pragma unroll
        for (int kc = 0; kc < 5; kc++) {
            if (kc < 4) {
                const int par = kc & 1;
#pragma unroll
                for (int j = 0; j < 2; j++) {
                    const int ni = 2 * kc + j;
                    float p0 = fexp2(sc[ni][0] - mn0);
                    float p1 = fexp2(sc[ni][1] - mn0);
                    float p2 = fexp2(sc[ni][2] - mn1);
                    float p3 = fexp2(sc[ni][3] - mn1);
                    rs0 += p0 + p1; rs1 += p2 + p3;
                    pa[par][j * 2]     = pack_f16(p0, p1);
                    pa[par][j * 2 + 1] = pack_f16(p2, p3);
                }
            }
            if (kc > 0) {
                const int kcm = kc - 1;
                const int par = kcm & 1;
                uint32_t vh[4][4];
#pragma unroll
                for (int g = 0; g < 4; g++)
                    ldsm4t(vh[g], stg + FOP + kcm * 16 * FSTR + t_off + g * 32);
#pragma unroll
                for (int ni = 0; ni < 8; ni++) {
                    const int g = ni >> 1, sel = (ni & 1) * 2;
                    mma_f16(o[ni], pa[par], &vh[g][sel]);
                }
            }
        }
        rs0 += __shfl_xor_sync(0xffffffffu, rs0, 1);
        rs0 += __shfl_xor_sync(0xffffffffu, rs0, 2);
        rs1 += __shfl_xor_sync(0xffffffffu, rs1, 1);
        rs1 += __shfl_xor_sync(0xffffffffu, rs1, 2);
        l0 = l0 * cr0 + rs0;
        l1 = l1 * cr1 + rs1;
        __syncthreads();
    }

    // ---- epilogue: /l, query padding, write fp16 hi/lo k-blocked [kb][m][80B]
    const int r0 = qrow0 + w * 16 + grp;
    const int r1 = r0 + 8;
    float f0 = (l0 > 0.f ? 1.0f / l0 : 0.f) * (float)qpm[b * SEQ + r0];
    float f1 = (l1 > 0.f ? 1.0f / l1 : 0.f) * (float)qpm[b * SEQ + r1];
    const size_t m0r = (size_t)(b * SEQ + r0);
    const size_t m1r = (size_t)(b * SEQ + r1);
#pragma unroll
    for (int ni = 0; ni < 8; ni++) {
        int col = h * HD + ni * 8 + 2 * tig;
        size_t kslab = (size_t)(col >> 5) * ((size_t)MTOT * 80) +
                       (size_t)(col & 31) * 2;
        uint32_t hw, lw;
        split_pack(o[ni][0] * f0, o[ni][1] * f0, hw, lw);
        size_t i0 = kslab + m0r * 80;
        *reinterpret_cast<uint32_t*>(g_aoh + i0) = hw;
        *reinterpret_cast<uint32_t*>(g_aol + i0) = lw;
        split_pack(o[ni][2] * f1, o[ni][3] * f1, hw, lw);
        size_t i1 = kslab + m1r * 80;
        *reinterpret_cast<uint32_t*>(g_aoh + i1) = hw;
        *reinterpret_cast<uint32_t*>(g_aol + i1) = lw;
    }
}

// ---------------- launch -----------------------------------------------------
extern "C" void kernel_launch(void* const* d_in, const int* in_sizes, int n_in,
                              void* d_out, int out_size) {
    const float* q   = (const float*)d_in[0];
    const float* k   = (const float*)d_in[1];
    const float* v   = (const float*)d_in[2];
    const int*   qpm = (const int*)d_in[3];
    const int*   kpm = (const int*)d_in[4];
    const float* Wq  = (const float*)d_in[5];
    const float* Wk  = (const float*)d_in[6];
    const float* Wv  = (const float*)d_in[7];
    const float* Wo  = (const float*)d_in[8];
    float* out = (float*)d_out;

    dim3 gs((MTOT * DM) / (256 * 4), 1, 3);
    split_act_kernel<<<gs, 256>>>(q, k, v);
    split_w_kernel<<<dim3(32, 32, 4), 256>>>(Wq, Wk, Wv, Wo);

    cudaFuncSetAttribute(gemm_qkv_kernel,
                         cudaFuncAttributeMaxDynamicSharedMemorySize, GEMM_SMEM);
    cudaFuncSetAttribute(gemm_o_kernel,
                         cudaFuncAttributeMaxDynamicSharedMemorySize, GEMM_SMEM);
    gemm_qkv_kernel<<<dim3(DM / 128, MTOT / 256, 3), 512, GEMM_SMEM>>>();

    cudaFuncSetAttribute(flash_kernel,
                         cudaFuncAttributeMaxDynamicSharedMemorySize, FLASH_SMEM);
    flash_kernel<<<dim3(SEQ / 128, NB * NH), 256, FLASH_SMEM>>>(qpm, kpm);

    gemm_o_kernel<<<dim3(DM / 128, MTOT / 256), 512, GEMM_SMEM>>>(out);
}

// round 13
// speedup vs baseline: 1.6980x; 1.0946x over previous
#include <cuda_runtime.h>
#include <cuda_bf16.h>
#include <cuda_fp16.h>
#include <cstdint>
#include <math.h>

#define DM   1024
#define NH   16
#define HD   64
#define SEQ  2048
#define NB   4
#define MTOT (NB * SEQ)   // 8192

// ---------------- global scratch: layouts match smem staging ----------------
#define QKV_ROW 72                         // fp16 elements per padded row (144B)
__device__ __half g_qh[(size_t)NB * NH * SEQ * QKV_ROW];
__device__ __half g_ql[(size_t)NB * NH * SEQ * QKV_ROW];
__device__ __half g_kh[(size_t)NB * NH * SEQ * QKV_ROW];   // K single fp16
__device__ __half g_vh[(size_t)NB * NH * SEQ * QKV_ROW];   // V single fp16

#define ABT ((size_t)32 * MTOT * 80)       // one activation tensor, k-blocked
#define WBT ((size_t)32 * DM * 80)         // one weight tensor, k-blocked
__device__ char g_ah[3 * ABT];
__device__ char g_al[3 * ABT];
__device__ char g_wh[4 * WBT];
__device__ char g_wl[4 * WBT];
__device__ char g_aoh[ABT];
__device__ char g_aol[ABT];

// ============================ helpers =======================================
__device__ __forceinline__ uint32_t smem_u32(const void* p) {
    uint32_t a;
    asm("{ .reg .u64 t; cvta.to.shared.u64 t, %1; cvt.u32.u64 %0, t; }"
        : "=r"(a) : "l"(p));
    return a;
}
#define MBARRIER_INIT(a, c) \
    asm volatile("mbarrier.init.shared.b64 [%0], %1;" :: "r"((uint32_t)(a)), "r"((uint32_t)(c)) : "memory")
#define MBARRIER_EXPECT_TX(a, b) \
    asm volatile("mbarrier.arrive.expect_tx.shared.b64 _, [%0], %1;" :: "r"((uint32_t)(a)), "r"((uint32_t)(b)) : "memory")
#define MBARRIER_WAIT_PARITY(a, par) do {                                        \
    uint32_t _m = (uint32_t)(a); uint32_t _p = (uint32_t)(par); uint32_t _d;     \
    asm volatile("{\n\t.reg .pred p;\n\t"                                        \
        "mbarrier.try_wait.parity.acquire.cta.shared::cta.b64 p, [%1], %2;\n\t"  \
        "selp.b32 %0, 1, 0, p;\n\t}" : "=r"(_d) : "r"(_m), "r"(_p) : "memory");  \
    if (!_d) {                                                                   \
        asm volatile("{\n\t.reg .pred P1;\n\t"                                   \
        "WL_%=:\n\t"                                                             \
        "mbarrier.try_wait.parity.acquire.cta.shared::cta.b64 P1, [%0], %1, 0x989680;\n\t" \
        "@P1 bra.uni WD_%=;\n\t"                                                 \
        "bra.uni WL_%=;\n\t"                                                     \
        "WD_%=:\n\t}" :: "r"(_m), "r"(_p) : "memory");                           \
    } } while (0)
#define BULK_LD(dst, src, size, mbar) \
    asm volatile("cp.async.bulk.shared::cluster.global.mbarrier::complete_tx::bytes [%0], [%1], %2, [%3];" \
                 :: "r"((uint32_t)(dst)), "l"(src), "r"((uint32_t)(size)), "r"((uint32_t)(mbar)) : "memory")
#define BULK_ST(gd, ss, sz) \
    asm volatile("cp.async.bulk.global.shared::cta.bulk_group [%0], [%1], %2;" \
                 :: "l"(gd), "r"((uint32_t)(ss)), "r"((uint32_t)(sz)) : "memory")
#define BULK_COMMIT() asm volatile("cp.async.bulk.commit_group;" ::: "memory")
#define BULK_WAIT0()  asm volatile("cp.async.bulk.wait_group 0;" ::: "memory")
#define FENCE_ASYNC() asm volatile("fence.proxy.async;" ::: "memory")

__device__ __forceinline__ void ldsm4(uint32_t* r, uint32_t addr) {
    asm volatile("ldmatrix.sync.aligned.m8n8.x4.shared.b16 {%0,%1,%2,%3}, [%4];"
                 : "=r"(r[0]), "=r"(r[1]), "=r"(r[2]), "=r"(r[3]) : "r"(addr));
}
__device__ __forceinline__ void ldsm4t(uint32_t* r, uint32_t addr) {
    asm volatile("ldmatrix.sync.aligned.m8n8.x4.trans.shared.b16 {%0,%1,%2,%3}, [%4];"
                 : "=r"(r[0]), "=r"(r[1]), "=r"(r[2]), "=r"(r[3]) : "r"(addr));
}
__device__ __forceinline__ void mma_f16(float* d, const uint32_t* a,
                                        const uint32_t* b) {
    asm volatile(
        "mma.sync.aligned.m16n8k16.row.col.f32.f16.f16.f32 "
        "{%0,%1,%2,%3},{%4,%5,%6,%7},{%8,%9},{%0,%1,%2,%3};"
        : "+f"(d[0]), "+f"(d[1]), "+f"(d[2]), "+f"(d[3])
        : "r"(a[0]), "r"(a[1]), "r"(a[2]), "r"(a[3]), "r"(b[0]), "r"(b[1]));
}
// FMA-pipe exp2: magic-constant range reduction, no F2I/I2F. x in log2 domain.
__device__ __forceinline__ float fexp2(float x) {
    x = fmaxf(x, -125.0f);
    float y = x + 12582912.0f;
    float fi = y - 12582912.0f;
    float f = x - fi;
    uint32_t iy = __float_as_uint(y);
    float p = 0.0013333558f;
    p = fmaf(p, f, 0.0096181291f);
    p = fmaf(p, f, 0.0555041087f);
    p = fmaf(p, f, 0.2402265070f);
    p = fmaf(p, f, 0.6931471806f);
    p = fmaf(p, f, 1.0f);
    return p * __uint_as_float((iy + 0xB4C0007Fu) << 23);
}

__device__ __forceinline__ void split1h(float x, __half& h, __half& l) {
    h = __float2half_rn(x);
    l = __float2half_rn(x - __half2float(h));
}
__device__ __forceinline__ uint32_t pack_f16(float a, float b) {
    uint32_t w;
    asm("cvt.rn.f16x2.f32 %0, %1, %2;" : "=r"(w) : "f"(b), "f"(a));
    return w;
}
__device__ __forceinline__ void split_pack(float a, float b, uint32_t& hw, uint32_t& lw) {
    hw = pack_f16(a, b);
    __half2 h2 = *reinterpret_cast<__half2*>(&hw);
    float la = a - __low2float(h2);
    float lb = b - __high2float(h2);
    lw = pack_f16(la, lb);
}

// ============ fp16x3 HMMA GEMM: 128x128x32, 256 thr, 2-stage, 2 CTA/SM ======
#define ST_STRIDE 80
#define GOP 10240                     // 128*80 per operand
#define GSTAGE (4 * GOP)              // 40960: Ah,Al,Bh,Bl
#define GMB (2 * GSTAGE)              // 81920
#define GEMM_SMEM (GMB + 64)

__device__ __forceinline__ void gemm_issue(uint32_t sb, int s,
                                           const char* Ah, const char* Al,
                                           const char* Bh, const char* Bl,
                                           int row0, int col0, int kb) {
    uint32_t mb = sb + GMB + s * 8;
    uint32_t dst = sb + s * GSTAGE;
    MBARRIER_EXPECT_TX(mb, GSTAGE);
    size_t ao = (size_t)kb * ((size_t)MTOT * 80) + (size_t)row0 * 80;
    size_t bo = (size_t)kb * ((size_t)DM * 80) + (size_t)col0 * 80;
    BULK_LD(dst,           Ah + ao, GOP, mb);
    BULK_LD(dst + GOP,     Al + ao, GOP, mb);
    BULK_LD(dst + 2 * GOP, Bh + bo, GOP, mb);
    BULK_LD(dst + 3 * GOP, Bl + bo, GOP, mb);
}

// MODE 0: fp32 out [M,DM].  MODE 1: fp16 hi+lo out (Q).  MODE 2: fp16 hi only.
template <int MODE>
__device__ __forceinline__ void gemm_body(const char* __restrict__ Ah,
                                          const char* __restrict__ Al,
                                          const char* __restrict__ Bh,
                                          const char* __restrict__ Bl,
                                          float* __restrict__ Cf,
                                          __half* __restrict__ Chi,
                                          __half* __restrict__ Clo,
                                          float scale, int row0, int col0) {
    extern __shared__ char sm[];
    const uint32_t sb = smem_u32(sm);
    const int tid = threadIdx.x;
    const int lane = tid & 31;
    const int w = tid >> 5;          // 0..7
    const int wm = w & 1;            // 2 m-warps (64 rows each)
    const int wn = w >> 1;           // 4 n-warps (32 cols each)

    if (tid == 0) {
        MBARRIER_INIT(sb + GMB, 1);
        MBARRIER_INIT(sb + GMB + 8, 1);
    }
    __syncthreads();
    if (tid == 0) {
        gemm_issue(sb, 0, Ah, Al, Bh, Bl, row0, col0, 0);
        gemm_issue(sb, 1, Ah, Al, Bh, Bl, row0, col0, 1);
    }

    float acc[4][4][4];
#pragma unroll
    for (int mi = 0; mi < 4; mi++)
#pragma unroll
        for (int ni = 0; ni < 4; ni++)
#pragma unroll
            for (int e = 0; e < 4; e++) acc[mi][ni][e] = 0.f;

    const int a_off = (wm * 64 + (lane & 15)) * ST_STRIDE + (lane >> 4) * 16;
    const int b_off = (wn * 32 + (lane & 7) + ((lane >> 4) << 3)) * ST_STRIDE +
                      ((lane >> 3) & 1) * 16;

    int ph0 = 0, ph1 = 0;
    const int NIT = DM / 32;   // 32
    for (int i = 0; i < NIT; i++) {
        const int s = i & 1;
        if (s == 0) { MBARRIER_WAIT_PARITY(sb + GMB,     ph0); ph0 ^= 1; }
        else        { MBARRIER_WAIT_PARITY(sb + GMB + 8, ph1); ph1 ^= 1; }
        const uint32_t sbase = sb + s * GSTAGE;
#pragma unroll
        for (int ks = 0; ks < 2; ks++) {
            uint32_t ah[4][4], al[4][4], bh[8], bl[8];
            const uint32_t abase = sbase + a_off + ks * 32;
            const uint32_t bbase = sbase + 2 * GOP + b_off + ks * 32;
#pragma unroll
            for (int mi = 0; mi < 4; mi++) {
                ldsm4(ah[mi], abase + mi * 16 * ST_STRIDE);
                ldsm4(al[mi], abase + mi * 16 * ST_STRIDE + GOP);
            }
#pragma unroll
            for (int p = 0; p < 2; p++) {
                ldsm4(&bh[p * 4], bbase + p * 16 * ST_STRIDE);
                ldsm4(&bl[p * 4], bbase + p * 16 * ST_STRIDE + GOP);
            }
#pragma unroll
            for (int mi = 0; mi < 4; mi++)
#pragma unroll
                for (int ni = 0; ni < 4; ni++) {
                    const uint32_t* fh = &bh[(ni >> 1) * 4 + (ni & 1) * 2];
                    const uint32_t* fl = &bl[(ni >> 1) * 4 + (ni & 1) * 2];
                    mma_f16(acc[mi][ni], ah[mi], fh);
                    mma_f16(acc[mi][ni], ah[mi], fl);
                    mma_f16(acc[mi][ni], al[mi], fh);
                }
        }
        __syncthreads();
        if (i + 2 < NIT && tid == 0)
            gemm_issue(sb, s, Ah, Al, Bh, Bl, row0, col0, i + 2);
    }

    const int grp = lane >> 2;
    const int tig = lane & 3;

    if (MODE == 0) {
#pragma unroll
        for (int mi = 0; mi < 4; mi++)
#pragma unroll
            for (int ni = 0; ni < 4; ni++) {
                int col = col0 + wn * 32 + ni * 8 + tig * 2;
                int rlo = row0 + wm * 64 + mi * 16 + grp;
                *reinterpret_cast<float2*>(Cf + (size_t)rlo * DM + col) =
                    make_float2(acc[mi][ni][0], acc[mi][ni][1]);
                *reinterpret_cast<float2*>(Cf + (size_t)(rlo + 8) * DM + col) =
                    make_float2(acc[mi][ni][2], acc[mi][ni][3]);
            }
    } else {
        // smem-stage one head (hi [+lo]), 18432B blocks, two heads sequentially
        const int b0 = row0 >> 11;
        const int t0 = row0 & (SEQ - 1);
#pragma unroll
        for (int hh = 0; hh < 2; hh++) {
            if ((wn >> 1) == hh) {
                const int lcb = (wn & 1) * 32;
#pragma unroll
                for (int mi = 0; mi < 4; mi++)
#pragma unroll
                    for (int ni = 0; ni < 4; ni++) {
                        int lc2 = (lcb + ni * 8 + tig * 2) * 2;
                        int rr = wm * 64 + mi * 16 + grp;
                        uint32_t hw, lw;
                        split_pack(acc[mi][ni][0] * scale, acc[mi][ni][1] * scale, hw, lw);
                        *reinterpret_cast<uint32_t*>(sm + rr * 144 + lc2) = hw;
                        if (MODE == 1)
                            *reinterpret_cast<uint32_t*>(sm + 18432 + rr * 144 + lc2) = lw;
                        split_pack(acc[mi][ni][2] * scale, acc[mi][ni][3] * scale, hw, lw);
                        *reinterpret_cast<uint32_t*>(sm + (rr + 8) * 144 + lc2) = hw;
                        if (MODE == 1)
                            *reinterpret_cast<uint32_t*>(sm + 18432 + (rr + 8) * 144 + lc2) = lw;
                    }
            }
            __syncthreads();
            if (tid == 0) {
                FENCE_ASYNC();
                int h = (col0 >> 6) + hh;
                size_t off = (((size_t)(b0 * NH + h)) * SEQ + t0) * 144;
                BULK_ST((char*)Chi + off, sb, 18432);
                if (MODE == 1)
                    BULK_ST((char*)Clo + off, sb + 18432, 18432);
                BULK_COMMIT();
                BULK_WAIT0();
            }
            __syncthreads();
        }
    }
}

__global__ void __launch_bounds__(256, 2)
gemm_qkv_kernel() {
    int z = blockIdx.z;
    const char* Ah = g_ah + (size_t)z * ABT;
    const char* Al = g_al + (size_t)z * ABT;
    const char* Bh = g_wh + (size_t)z * WBT;
    const char* Bl = g_wl + (size_t)z * WBT;
    if (z == 0) {
        gemm_body<1>(Ah, Al, Bh, Bl, nullptr, g_qh, g_ql,
                     0.125f * 1.4426950408889634f,
                     blockIdx.y * 128, blockIdx.x * 128);
    } else {
        __half* Chi = (z == 1) ? g_kh : g_vh;
        gemm_body<2>(Ah, Al, Bh, Bl, nullptr, Chi, nullptr, 1.0f,
                     blockIdx.y * 128, blockIdx.x * 128);
    }
}

__global__ void __launch_bounds__(256, 2)
gemm_o_kernel(float* __restrict__ out) {
    gemm_body<0>(g_aoh, g_aol, g_wh + 3 * WBT, g_wl + 3 * WBT,
                 out, nullptr, nullptr, 1.0f,
                 blockIdx.y * 128, blockIdx.x * 128);
}

// ====================== split / transpose kernels ===========================
__global__ void __launch_bounds__(256)
split_act_kernel(const float* __restrict__ q, const float* __restrict__ k,
                 const float* __restrict__ v) {
    int z = blockIdx.z;
    const float* src = (z == 0) ? q : (z == 1) ? k : v;
    size_t i4 = (size_t)blockIdx.x * 256 + threadIdx.x;
    float4 x = reinterpret_cast<const float4*>(src)[i4];
    uint32_t h0, l0, h1, l1;
    split_pack(x.x, x.y, h0, l0);
    split_pack(x.z, x.w, h1, l1);
    size_t e0 = i4 * 4;
    int m = (int)(e0 >> 10);
    int k0 = (int)(e0 & 1023);
    size_t off = (size_t)z * ABT + (size_t)(k0 >> 5) * ((size_t)MTOT * 80) +
                 (size_t)m * 80 + (size_t)(k0 & 31) * 2;
    *reinterpret_cast<uint2*>(g_ah + off) = make_uint2(h0, h1);
    *reinterpret_cast<uint2*>(g_al + off) = make_uint2(l0, l1);
}

__global__ void __launch_bounds__(256)
split_w_kernel(const float* __restrict__ Wq, const float* __restrict__ Wk,
               const float* __restrict__ Wv, const float* __restrict__ Wo) {
    __shared__ float tile[32][33];
    int z = blockIdx.z;
    const float* W = (z == 0) ? Wq : (z == 1) ? Wk : (z == 2) ? Wv : Wo;
    int tx = threadIdx.x & 31, ty = threadIdx.x >> 5;
    int k0 = blockIdx.y * 32, n0 = blockIdx.x * 32;
#pragma unroll
    for (int i = 0; i < 4; i++)
        tile[ty + i * 8][tx] = W[(size_t)(k0 + ty + i * 8) * DM + n0 + tx];
    __syncthreads();
#pragma unroll
    for (int i = 0; i < 4; i++) {
        int n = n0 + ty + i * 8;
        int k = k0 + tx;
        __half h, l;
        split1h(tile[tx][ty + i * 8], h, l);
        size_t off = (size_t)z * WBT + (size_t)(k >> 5) * ((size_t)DM * 80) +
                     (size_t)n * 80 + (size_t)(k & 31) * 2;
        *reinterpret_cast<__half*>(g_wh + off) = h;
        *reinterpret_cast<__half*>(g_wl + off) = l;
    }
}

// ====================== tensorized flash attention ==========================
// Br=128 per CTA (8 warps x 16 rows), 256 threads, 2 CTAs/SM. Bc=64 per iter.
// log2 domain. QK: (Qh+Ql)·Kh = 2 MMAs. PV: P·Vh = 1 MMA. K,V single fp16.
#define FSTR 144
#define FOP  (64 * FSTR)              // 9216
#define FSTAGE (2 * FOP)              // 18432: Kh,Vh
#define QOFF (2 * FSTAGE)             // 36864
#define QOP  (128 * FSTR)             // 18432
#define FBIAS (QOFF + 2 * QOP)        // 73728
#define FMB (FBIAS + 512)             // 74240
#define FLASH_SMEM (FMB + 32)

__global__ void __launch_bounds__(256, 2)
flash_kernel(const int* __restrict__ qpm, const int* __restrict__ kpm) {
    extern __shared__ char sm[];
    const uint32_t sb = smem_u32(sm);
    float* biasp = reinterpret_cast<float*>(sm + FBIAS);

    const int tid = threadIdx.x;
    const int lane = tid & 31;
    const int w = tid >> 5;
    const int grp = lane >> 2;
    const int tig = lane & 3;

    const int qt = gridDim.x - 1 - blockIdx.x;
    const int bh = blockIdx.y;
    const int b = bh >> 4;
    const int h = bh & (NH - 1);
    const size_t bbase = (size_t)bh * SEQ * 144;
    const int qrow0 = qt * 128;
    const int nit = 2 * qt + 2;

    if (tid == 0) {
        MBARRIER_INIT(sb + FMB, 1);
        MBARRIER_INIT(sb + FMB + 8, 1);
        MBARRIER_INIT(sb + FMB + 16, 1);
    }
    __syncthreads();
    if (tid == 0) {
        MBARRIER_EXPECT_TX(sb + FMB + 16, 2 * QOP);
        BULK_LD(sb + QOFF,       (const char*)g_qh + bbase + (size_t)qrow0 * 144, QOP, sb + FMB + 16);
        BULK_LD(sb + QOFF + QOP, (const char*)g_ql + bbase + (size_t)qrow0 * 144, QOP, sb + FMB + 16);
        MBARRIER_EXPECT_TX(sb + FMB, FSTAGE);
        BULK_LD(sb,       (const char*)g_kh + bbase, FOP, sb + FMB);
        BULK_LD(sb + FOP, (const char*)g_vh + bbase, FOP, sb + FMB);
    }

    float o[8][4];
#pragma unroll
    for (int ni = 0; ni < 8; ni++)
#pragma unroll
        for (int e = 0; e < 4; e++) o[ni][e] = 0.f;
    float m0 = -1e30f, m1 = -1e30f, l0 = 0.f, l1 = 0.f;

    const int a_off = (w * 16 + (lane & 15)) * FSTR + (lane >> 4) * 16;
    const int b_off = ((lane & 7) + ((lane >> 4) << 3)) * FSTR +
                      ((lane >> 3) & 1) * 16;
    const int t_off = (lane & 15) * FSTR + ((lane >> 4) << 3) * 2;

    MBARRIER_WAIT_PARITY(sb + FMB + 16, 0);

    int ph0 = 0, ph1 = 0;
    for (int it = 0; it < nit; it++) {
        const int s = it & 1;
        const int krow0 = it * 64;
        const uint32_t stg = sb + s * FSTAGE;

        if (it + 1 < nit && tid == 0) {
            const size_t ko = bbase + (size_t)(it + 1) * 64 * 144;
            const uint32_t mb = sb + FMB + (s ^ 1) * 8;
            const uint32_t d = sb + (s ^ 1) * FSTAGE;
            MBARRIER_EXPECT_TX(mb, FSTAGE);
            BULK_LD(d,       (const char*)g_kh + ko, FOP, mb);
            BULK_LD(d + FOP, (const char*)g_vh + ko, FOP, mb);
        }
        if (tid < 64)
            biasp[s * 64 + tid] =
                (kpm[b * SEQ + krow0 + tid] != 0) ? 0.f : -1e30f;

        if (s == 0) { MBARRIER_WAIT_PARITY(sb + FMB, ph0); ph0 ^= 1; }
        else        { MBARRIER_WAIT_PARITY(sb + FMB + 8, ph1); ph1 ^= 1; }
        __syncthreads();

        // ---- S = Q K^T: (Qh + Ql) · Kh ----
        float sc[8][4];
#pragma unroll
        for (int ni = 0; ni < 8; ni++)
#pragma unroll
            for (int e = 0; e < 4; e++) sc[ni][e] = 0.f;

#pragma unroll
        for (int kd = 0; kd < 4; kd++) {
            uint32_t qfh[4], qfl[4];
            ldsm4(qfh, sb + QOFF + a_off + kd * 32);
            ldsm4(qfl, sb + QOFF + QOP + a_off + kd * 32);
            uint32_t kh[4][4];
#pragma unroll
            for (int g = 0; g < 4; g++)
                ldsm4(kh[g], stg + b_off + kd * 32 + g * 16 * FSTR);
#pragma unroll
            for (int ni = 0; ni < 8; ni++) {
                const int g = ni >> 1, sel = (ni & 1) * 2;
                mma_f16(sc[ni], qfh, &kh[g][sel]);
                mma_f16(sc[ni], qfl, &kh[g][sel]);
            }
        }

        // ---- bias + causal mask ----
#pragma unroll
        for (int ni = 0; ni < 8; ni++) {
            float2 bb = *reinterpret_cast<float2*>(&biasp[s * 64 + ni * 8 + 2 * tig]);
            sc[ni][0] += bb.x; sc[ni][1] += bb.y;
            sc[ni][2] += bb.x; sc[ni][3] += bb.y;
        }
        if (krow0 + 63 > qrow0) {
            const int r0 = qrow0 + w * 16 + grp;
            const int r1 = r0 + 8;
#pragma unroll
            for (int ni = 0; ni < 8; ni++) {
                int c0 = krow0 + ni * 8 + 2 * tig;
                if (c0 > r0) sc[ni][0] = -1e30f;
                if (c0 + 1 > r0) sc[ni][1] = -1e30f;
                if (c0 > r1) sc[ni][2] = -1e30f;
                if (c0 + 1 > r1) sc[ni][3] = -1e30f;
            }
        }

        // ---- online softmax (log2 domain) ----
        float mx0 = -1e30f, mx1 = -1e30f;
#pragma unroll
        for (int ni = 0; ni < 8; ni++) {
            mx0 = fmaxf(mx0, fmaxf(sc[ni][0], sc[ni][1]));
            mx1 = fmaxf(mx1, fmaxf(sc[ni][2], sc[ni][3]));
        }
        mx0 = fmaxf(mx0, __shfl_xor_sync(0xffffffffu, mx0, 1));
        mx0 = fmaxf(mx0, __shfl_xor_sync(0xffffffffu, mx0, 2));
        mx1 = fmaxf(mx1, __shfl_xor_sync(0xffffffffu, mx1, 1));
        mx1 = fmaxf(mx1, __shfl_xor_sync(0xffffffffu, mx1, 2));
        float mn0 = fmaxf(m0, mx0), mn1 = fmaxf(m1, mx1);
        float cr0 = fexp2(m0 - mn0);
        float cr1 = fexp2(m1 - mn1);
        m0 = mn0; m1 = mn1;
#pragma unroll
        for (int ni = 0; ni < 8; ni++) {
            o[ni][0] *= cr0; o[ni][1] *= cr0;
            o[ni][2] *= cr1; o[ni][3] *= cr1;
        }

        // ---- exp/pack interleaved with PV MMAs ----
        float rs0 = 0.f, rs1 = 0.f;
        uint32_t pa[2][4];
#pragma unroll
        for (int kc = 0; kc < 5; kc++) {
            if (kc < 4) {
                const int par = kc & 1;
#pragma unroll
                for (int j = 0; j < 2; j++) {
                    const int ni = 2 * kc + j;
                    float p0 = fexp2(sc[ni][0] - mn0);
                    float p1 = fexp2(sc[ni][1] - mn0);
                    float p2 = fexp2(sc[ni][2] - mn1);
                    float p3 = fexp2(sc[ni][3] - mn1);
                    rs0 += p0 + p1; rs1 += p2 + p3;
                    pa[par][j * 2]     = pack_f16(p0, p1);
                    pa[par][j * 2 + 1] = pack_f16(p2, p3);
                }
            }
            if (kc > 0) {
                const int kcm = kc - 1;
                const int par = kcm & 1;
                uint32_t vh[4][4];
#pragma unroll
                for (int g = 0; g < 4; g++)
                    ldsm4t(vh[g], stg + FOP + kcm * 16 * FSTR + t_off + g * 32);
#pragma unroll
                for (int ni = 0; ni < 8; ni++) {
                    const int g = ni >> 1, sel = (ni & 1) * 2;
                    mma_f16(o[ni], pa[par], &vh[g][sel]);
                }
            }
        }
        rs0 += __shfl_xor_sync(0xffffffffu, rs0, 1);
        rs0 += __shfl_xor_sync(0xffffffffu, rs0, 2);
        rs1 += __shfl_xor_sync(0xffffffffu, rs1, 1);
        rs1 += __shfl_xor_sync(0xffffffffu, rs1, 2);
        l0 = l0 * cr0 + rs0;
        l1 = l1 * cr1 + rs1;
        __syncthreads();
    }

    // ---- epilogue: /l, query padding, write fp16 hi/lo k-blocked [kb][m][80B]
    const int r0 = qrow0 + w * 16 + grp;
    const int r1 = r0 + 8;
    float f0 = (l0 > 0.f ? 1.0f / l0 : 0.f) * (float)qpm[b * SEQ + r0];
    float f1 = (l1 > 0.f ? 1.0f / l1 : 0.f) * (float)qpm[b * SEQ + r1];
    const size_t m0r = (size_t)(b * SEQ + r0);
    const size_t m1r = (size_t)(b * SEQ + r1);
#pragma unroll
    for (int ni = 0; ni < 8; ni++) {
        int col = h * HD + ni * 8 + 2 * tig;
        size_t kslab = (size_t)(col >> 5) * ((size_t)MTOT * 80) +
                       (size_t)(col & 31) * 2;
        uint32_t hw, lw;
        split_pack(o[ni][0] * f0, o[ni][1] * f0, hw, lw);
        size_t i0 = kslab + m0r * 80;
        *reinterpret_cast<uint32_t*>(g_aoh + i0) = hw;
        *reinterpret_cast<uint32_t*>(g_aol + i0) = lw;
        split_pack(o[ni][2] * f1, o[ni][3] * f1, hw, lw);
        size_t i1 = kslab + m1r * 80;
        *reinterpret_cast<uint32_t*>(g_aoh + i1) = hw;
        *reinterpret_cast<uint32_t*>(g_aol + i1) = lw;
    }
}

// ---------------- launch -----------------------------------------------------
extern "C" void kernel_launch(void* const* d_in, const int* in_sizes, int n_in,
                              void* d_out, int out_size) {
    const float* q   = (const float*)d_in[0];
    const float* k   = (const float*)d_in[1];
    const float* v   = (const float*)d_in[2];
    const int*   qpm = (const int*)d_in[3];
    const int*   kpm = (const int*)d_in[4];
    const float* Wq  = (const float*)d_in[5];
    const float* Wk  = (const float*)d_in[6];
    const float* Wv  = (const float*)d_in[7];
    const float* Wo  = (const float*)d_in[8];
    float* out = (float*)d_out;

    dim3 gs((MTOT * DM) / (256 * 4), 1, 3);
    split_act_kernel<<<gs, 256>>>(q, k, v);
    split_w_kernel<<<dim3(32, 32, 4), 256>>>(Wq, Wk, Wv, Wo);

    cudaFuncSetAttribute(gemm_qkv_kernel,
                         cudaFuncAttributeMaxDynamicSharedMemorySize, GEMM_SMEM);
    cudaFuncSetAttribute(gemm_o_kernel,
                         cudaFuncAttributeMaxDynamicSharedMemorySize, GEMM_SMEM);
    gemm_qkv_kernel<<<dim3(DM / 128, MTOT / 128, 3), 256, GEMM_SMEM>>>();

    cudaFuncSetAttribute(flash_kernel,
                         cudaFuncAttributeMaxDynamicSharedMemorySize, FLASH_SMEM);
    flash_kernel<<<dim3(SEQ / 128, NB * NH), 256, FLASH_SMEM>>>(qpm, kpm);

    gemm_o_kernel<<<dim3(DM / 128, MTOT / 128), 256, GEMM_SMEM>>>(out);
}

// round 14
// speedup vs baseline: 1.8761x; 1.1049x over previous
#include <cuda_runtime.h>
#include <cuda_bf16.h>
#include <cuda_fp16.h>
#include <cstdint>
#include <math.h>

#define DM   1024
#define NH   16
#define HD   64
#define SEQ  2048
#define NB   4
#define MTOT (NB * SEQ)   // 8192

// ---------------- global scratch: layouts match smem staging ----------------
#define QKV_ROW 72                         // fp16 elements per padded row (144B)
__device__ __half g_qh[(size_t)NB * NH * SEQ * QKV_ROW];   // Q single fp16
__device__ __half g_kh[(size_t)NB * NH * SEQ * QKV_ROW];   // K single fp16
__device__ __half g_vh[(size_t)NB * NH * SEQ * QKV_ROW];   // V single fp16

#define ABT ((size_t)32 * MTOT * 80)       // one activation tensor, k-blocked
#define WBT ((size_t)32 * DM * 80)         // one weight tensor, k-blocked
__device__ char g_ah[3 * ABT];
__device__ char g_al[3 * ABT];
__device__ char g_wh[4 * WBT];
__device__ char g_wl[4 * WBT];
__device__ char g_aoh[ABT];                // attn-out single fp16, k-blocked

// ============================ helpers =======================================
__device__ __forceinline__ uint32_t smem_u32(const void* p) {
    uint32_t a;
    asm("{ .reg .u64 t; cvta.to.shared.u64 t, %1; cvt.u32.u64 %0, t; }"
        : "=r"(a) : "l"(p));
    return a;
}
#define MBARRIER_INIT(a, c) \
    asm volatile("mbarrier.init.shared.b64 [%0], %1;" :: "r"((uint32_t)(a)), "r"((uint32_t)(c)) : "memory")
#define MBARRIER_EXPECT_TX(a, b) \
    asm volatile("mbarrier.arrive.expect_tx.shared.b64 _, [%0], %1;" :: "r"((uint32_t)(a)), "r"((uint32_t)(b)) : "memory")
#define MBARRIER_WAIT_PARITY(a, par) do {                                        \
    uint32_t _m = (uint32_t)(a); uint32_t _p = (uint32_t)(par); uint32_t _d;     \
    asm volatile("{\n\t.reg .pred p;\n\t"                                        \
        "mbarrier.try_wait.parity.acquire.cta.shared::cta.b64 p, [%1], %2;\n\t"  \
        "selp.b32 %0, 1, 0, p;\n\t}" : "=r"(_d) : "r"(_m), "r"(_p) : "memory");  \
    if (!_d) {                                                                   \
        asm volatile("{\n\t.reg .pred P1;\n\t"                                   \
        "WL_%=:\n\t"                                                             \
        "mbarrier.try_wait.parity.acquire.cta.shared::cta.b64 P1, [%0], %1, 0x989680;\n\t" \
        "@P1 bra.uni WD_%=;\n\t"                                                 \
        "bra.uni WL_%=;\n\t"                                                     \
        "WD_%=:\n\t}" :: "r"(_m), "r"(_p) : "memory");                           \
    } } while (0)
#define BULK_LD(dst, src, size, mbar) \
    asm volatile("cp.async.bulk.shared::cluster.global.mbarrier::complete_tx::bytes [%0], [%1], %2, [%3];" \
                 :: "r"((uint32_t)(dst)), "l"(src), "r"((uint32_t)(size)), "r"((uint32_t)(mbar)) : "memory")
#define BULK_ST(gd, ss, sz) \
    asm volatile("cp.async.bulk.global.shared::cta.bulk_group [%0], [%1], %2;" \
                 :: "l"(gd), "r"((uint32_t)(ss)), "r"((uint32_t)(sz)) : "memory")
#define BULK_COMMIT() asm volatile("cp.async.bulk.commit_group;" ::: "memory")
#define BULK_WAIT0()  asm volatile("cp.async.bulk.wait_group 0;" ::: "memory")
#define FENCE_ASYNC() asm volatile("fence.proxy.async;" ::: "memory")

__device__ __forceinline__ void ldsm4(uint32_t* r, uint32_t addr) {
    asm volatile("ldmatrix.sync.aligned.m8n8.x4.shared.b16 {%0,%1,%2,%3}, [%4];"
                 : "=r"(r[0]), "=r"(r[1]), "=r"(r[2]), "=r"(r[3]) : "r"(addr));
}
__device__ __forceinline__ void ldsm4t(uint32_t* r, uint32_t addr) {
    asm volatile("ldmatrix.sync.aligned.m8n8.x4.trans.shared.b16 {%0,%1,%2,%3}, [%4];"
                 : "=r"(r[0]), "=r"(r[1]), "=r"(r[2]), "=r"(r[3]) : "r"(addr));
}
__device__ __forceinline__ void mma_f16(float* d, const uint32_t* a,
                                        const uint32_t* b) {
    asm volatile(
        "mma.sync.aligned.m16n8k16.row.col.f32.f16.f16.f32 "
        "{%0,%1,%2,%3},{%4,%5,%6,%7},{%8,%9},{%0,%1,%2,%3};"
        : "+f"(d[0]), "+f"(d[1]), "+f"(d[2]), "+f"(d[3])
        : "r"(a[0]), "r"(a[1]), "r"(a[2]), "r"(a[3]), "r"(b[0]), "r"(b[1]));
}
// FMA-pipe exp2: magic-constant range reduction, no F2I/I2F. x in log2 domain.
__device__ __forceinline__ float fexp2(float x) {
    x = fmaxf(x, -125.0f);
    float y = x + 12582912.0f;
    float fi = y - 12582912.0f;
    float f = x - fi;
    uint32_t iy = __float_as_uint(y);
    float p = 0.0013333558f;
    p = fmaf(p, f, 0.0096181291f);
    p = fmaf(p, f, 0.0555041087f);
    p = fmaf(p, f, 0.2402265070f);
    p = fmaf(p, f, 0.6931471806f);
    p = fmaf(p, f, 1.0f);
    return p * __uint_as_float((iy + 0xB4C0007Fu) << 23);
}

__device__ __forceinline__ void split1h(float x, __half& h, __half& l) {
    h = __float2half_rn(x);
    l = __float2half_rn(x - __half2float(h));
}
__device__ __forceinline__ uint32_t pack_f16(float a, float b) {
    uint32_t w;
    asm("cvt.rn.f16x2.f32 %0, %1, %2;" : "=r"(w) : "f"(b), "f"(a));
    return w;
}
__device__ __forceinline__ void split_pack(float a, float b, uint32_t& hw, uint32_t& lw) {
    hw = pack_f16(a, b);
    __half2 h2 = *reinterpret_cast<__half2*>(&hw);
    float la = a - __low2float(h2);
    float lb = b - __high2float(h2);
    lw = pack_f16(la, lb);
}

// ===== fp16 HMMA GEMM: 128x128x32, 256 thr, 2-stage, 2 CTA/SM ==============
// ASPLIT: A has hi+lo (3 MMAs). Else A single (2 MMAs: Ah·Bh + Ah·Bl).
#define ST_STRIDE 80
#define GOP 10240                     // 128*80 per operand
#define GSTAGE (4 * GOP)              // 40960 (layout fixed; Al slot may be unused)
#define GMB (2 * GSTAGE)              // 81920
#define GEMM_SMEM (GMB + 64)

template <bool ASPLIT>
__device__ __forceinline__ void gemm_issue(uint32_t sb, int s,
                                           const char* Ah, const char* Al,
                                           const char* Bh, const char* Bl,
                                           int row0, int col0, int kb) {
    uint32_t mb = sb + GMB + s * 8;
    uint32_t dst = sb + s * GSTAGE;
    MBARRIER_EXPECT_TX(mb, ASPLIT ? GSTAGE : 3 * GOP);
    size_t ao = (size_t)kb * ((size_t)MTOT * 80) + (size_t)row0 * 80;
    size_t bo = (size_t)kb * ((size_t)DM * 80) + (size_t)col0 * 80;
    BULK_LD(dst,           Ah + ao, GOP, mb);
    if (ASPLIT) BULK_LD(dst + GOP, Al + ao, GOP, mb);
    BULK_LD(dst + 2 * GOP, Bh + bo, GOP, mb);
    BULK_LD(dst + 3 * GOP, Bl + bo, GOP, mb);
}

// MODE 0: fp32 out [M,DM].  MODE 2: fp16 hi out to padded QKV via bulk S2G.
template <int MODE, bool ASPLIT>
__device__ __forceinline__ void gemm_body(const char* __restrict__ Ah,
                                          const char* __restrict__ Al,
                                          const char* __restrict__ Bh,
                                          const char* __restrict__ Bl,
                                          float* __restrict__ Cf,
                                          __half* __restrict__ Chi,
                                          float scale, int row0, int col0) {
    extern __shared__ char sm[];
    const uint32_t sb = smem_u32(sm);
    const int tid = threadIdx.x;
    const int lane = tid & 31;
    const int w = tid >> 5;          // 0..7
    const int wm = w & 1;            // 2 m-warps (64 rows each)
    const int wn = w >> 1;           // 4 n-warps (32 cols each)

    if (tid == 0) {
        MBARRIER_INIT(sb + GMB, 1);
        MBARRIER_INIT(sb + GMB + 8, 1);
    }
    __syncthreads();
    if (tid == 0) {
        gemm_issue<ASPLIT>(sb, 0, Ah, Al, Bh, Bl, row0, col0, 0);
        gemm_issue<ASPLIT>(sb, 1, Ah, Al, Bh, Bl, row0, col0, 1);
    }

    float acc[4][4][4];
#pragma unroll
    for (int mi = 0; mi < 4; mi++)
#pragma unroll
        for (int ni = 0; ni < 4; ni++)
#pragma unroll
            for (int e = 0; e < 4; e++) acc[mi][ni][e] = 0.f;

    const int a_off = (wm * 64 + (lane & 15)) * ST_STRIDE + (lane >> 4) * 16;
    const int b_off = (wn * 32 + (lane & 7) + ((lane >> 4) << 3)) * ST_STRIDE +
                      ((lane >> 3) & 1) * 16;

    int ph0 = 0, ph1 = 0;
    const int NIT = DM / 32;   // 32
    for (int i = 0; i < NIT; i++) {
        const int s = i & 1;
        if (s == 0) { MBARRIER_WAIT_PARITY(sb + GMB,     ph0); ph0 ^= 1; }
        else        { MBARRIER_WAIT_PARITY(sb + GMB + 8, ph1); ph1 ^= 1; }
        const uint32_t sbase = sb + s * GSTAGE;
#pragma unroll
        for (int ks = 0; ks < 2; ks++) {
            uint32_t ah[4][4], al[4][4], bh[8], bl[8];
            const uint32_t abase = sbase + a_off + ks * 32;
            const uint32_t bbase = sbase + 2 * GOP + b_off + ks * 32;
#pragma unroll
            for (int mi = 0; mi < 4; mi++) {
                ldsm4(ah[mi], abase + mi * 16 * ST_STRIDE);
                if (ASPLIT) ldsm4(al[mi], abase + mi * 16 * ST_STRIDE + GOP);
            }
#pragma unroll
            for (int p = 0; p < 2; p++) {
                ldsm4(&bh[p * 4], bbase + p * 16 * ST_STRIDE);
                ldsm4(&bl[p * 4], bbase + p * 16 * ST_STRIDE + GOP);
            }
#pragma unroll
            for (int mi = 0; mi < 4; mi++)
#pragma unroll
                for (int ni = 0; ni < 4; ni++) {
                    const uint32_t* fh = &bh[(ni >> 1) * 4 + (ni & 1) * 2];
                    const uint32_t* fl = &bl[(ni >> 1) * 4 + (ni & 1) * 2];
                    mma_f16(acc[mi][ni], ah[mi], fh);
                    mma_f16(acc[mi][ni], ah[mi], fl);
                    if (ASPLIT) mma_f16(acc[mi][ni], al[mi], fh);
                }
        }
        __syncthreads();
        if (i + 2 < NIT && tid == 0)
            gemm_issue<ASPLIT>(sb, s, Ah, Al, Bh, Bl, row0, col0, i + 2);
    }

    const int grp = lane >> 2;
    const int tig = lane & 3;

    if (MODE == 0) {
#pragma unroll
        for (int mi = 0; mi < 4; mi++)
#pragma unroll
            for (int ni = 0; ni < 4; ni++) {
                int col = col0 + wn * 32 + ni * 8 + tig * 2;
                int rlo = row0 + wm * 64 + mi * 16 + grp;
                *reinterpret_cast<float2*>(Cf + (size_t)rlo * DM + col) =
                    make_float2(acc[mi][ni][0], acc[mi][ni][1]);
                *reinterpret_cast<float2*>(Cf + (size_t)(rlo + 8) * DM + col) =
                    make_float2(acc[mi][ni][2], acc[mi][ni][3]);
            }
    } else {
        // smem-stage one head (hi only), 18432B blocks, two heads sequentially
        const int b0 = row0 >> 11;
        const int t0 = row0 & (SEQ - 1);
#pragma unroll
        for (int hh = 0; hh < 2; hh++) {
            if ((wn >> 1) == hh) {
                const int lcb = (wn & 1) * 32;
#pragma unroll
                for (int mi = 0; mi < 4; mi++)
#pragma unroll
                    for (int ni = 0; ni < 4; ni++) {
                        int lc2 = (lcb + ni * 8 + tig * 2) * 2;
                        int rr = wm * 64 + mi * 16 + grp;
                        *reinterpret_cast<uint32_t*>(sm + rr * 144 + lc2) =
                            pack_f16(acc[mi][ni][0] * scale, acc[mi][ni][1] * scale);
                        *reinterpret_cast<uint32_t*>(sm + (rr + 8) * 144 + lc2) =
                            pack_f16(acc[mi][ni][2] * scale, acc[mi][ni][3] * scale);
                    }
            }
            __syncthreads();
            if (tid == 0) {
                FENCE_ASYNC();
                int h = (col0 >> 6) + hh;
                size_t off = (((size_t)(b0 * NH + h)) * SEQ + t0) * 144;
                BULK_ST((char*)Chi + off, sb, 18432);
                BULK_COMMIT();
                BULK_WAIT0();
            }
            __syncthreads();
        }
    }
}

__global__ void __launch_bounds__(256, 2)
gemm_qkv_kernel() {
    int z = blockIdx.z;
    const char* Ah = g_ah + (size_t)z * ABT;
    const char* Al = g_al + (size_t)z * ABT;
    const char* Bh = g_wh + (size_t)z * WBT;
    const char* Bl = g_wl + (size_t)z * WBT;
    __half* Chi = (z == 0) ? g_qh : (z == 1) ? g_kh : g_vh;
    float scale = (z == 0) ? 0.125f * 1.4426950408889634f : 1.0f;
    gemm_body<2, true>(Ah, Al, Bh, Bl, nullptr, Chi, scale,
                       blockIdx.y * 128, blockIdx.x * 128);
}

__global__ void __launch_bounds__(256, 2)
gemm_o_kernel(float* __restrict__ out) {
    gemm_body<0, false>(g_aoh, g_aoh, g_wh + 3 * WBT, g_wl + 3 * WBT,
                        out, nullptr, 1.0f,
                        blockIdx.y * 128, blockIdx.x * 128);
}

// ====================== split / transpose kernels ===========================
__global__ void __launch_bounds__(256)
split_act_kernel(const float* __restrict__ q, const float* __restrict__ k,
                 const float* __restrict__ v) {
    int z = blockIdx.z;
    const float* src = (z == 0) ? q : (z == 1) ? k : v;
    size_t i4 = (size_t)blockIdx.x * 256 + threadIdx.x;
    float4 x = reinterpret_cast<const float4*>(src)[i4];
    uint32_t h0, l0, h1, l1;
    split_pack(x.x, x.y, h0, l0);
    split_pack(x.z, x.w, h1, l1);
    size_t e0 = i4 * 4;
    int m = (int)(e0 >> 10);
    int k0 = (int)(e0 & 1023);
    size_t off = (size_t)z * ABT + (size_t)(k0 >> 5) * ((size_t)MTOT * 80) +
                 (size_t)m * 80 + (size_t)(k0 & 31) * 2;
    *reinterpret_cast<uint2*>(g_ah + off) = make_uint2(h0, h1);
    *reinterpret_cast<uint2*>(g_al + off) = make_uint2(l0, l1);
}

__global__ void __launch_bounds__(256)
split_w_kernel(const float* __restrict__ Wq, const float* __restrict__ Wk,
               const float* __restrict__ Wv, const float* __restrict__ Wo) {
    __shared__ float tile[32][33];
    int z = blockIdx.z;
    const float* W = (z == 0) ? Wq : (z == 1) ? Wk : (z == 2) ? Wv : Wo;
    int tx = threadIdx.x & 31, ty = threadIdx.x >> 5;
    int k0 = blockIdx.y * 32, n0 = blockIdx.x * 32;
#pragma unroll
    for (int i = 0; i < 4; i++)
        tile[ty + i * 8][tx] = W[(size_t)(k0 + ty + i * 8) * DM + n0 + tx];
    __syncthreads();
#pragma unroll
    for (int i = 0; i < 4; i++) {
        int n = n0 + ty + i * 8;
        int k = k0 + tx;
        __half h, l;
        split1h(tile[tx][ty + i * 8], h, l);
        size_t off = (size_t)z * WBT + (size_t)(k >> 5) * ((size_t)DM * 80) +
                     (size_t)n * 80 + (size_t)(k & 31) * 2;
        *reinterpret_cast<__half*>(g_wh + off) = h;
        *reinterpret_cast<__half*>(g_wl + off) = l;
    }
}

// ====================== tensorized flash attention ==========================
// Br=128 per CTA (8 warps x 16 rows), 256 threads, 2 CTAs/SM. Bc=64 per iter.
// log2 domain. Q,K,V all single fp16: QK 1 MMA, PV 1 MMA per fragment.
#define FSTR 144
#define FOP  (64 * FSTR)              // 9216
#define FSTAGE (2 * FOP)              // 18432: Kh,Vh
#define QOFF (2 * FSTAGE)             // 36864
#define QOP  (128 * FSTR)             // 18432
#define FBIAS (QOFF + QOP)            // 55296
#define FMB (FBIAS + 512)             // 55808
#define FLASH_SMEM (FMB + 32)

__global__ void __launch_bounds__(256, 2)
flash_kernel(const int* __restrict__ qpm, const int* __restrict__ kpm) {
    extern __shared__ char sm[];
    const uint32_t sb = smem_u32(sm);
    float* biasp = reinterpret_cast<float*>(sm + FBIAS);

    const int tid = threadIdx.x;
    const int lane = tid & 31;
    const int w = tid >> 5;
    const int grp = lane >> 2;
    const int tig = lane & 3;

    const int qt = gridDim.x - 1 - blockIdx.x;
    const int bh = blockIdx.y;
    const int b = bh >> 4;
    const int h = bh & (NH - 1);
    const size_t bbase = (size_t)bh * SEQ * 144;
    const int qrow0 = qt * 128;
    const int nit = 2 * qt + 2;

    if (tid == 0) {
        MBARRIER_INIT(sb + FMB, 1);
        MBARRIER_INIT(sb + FMB + 8, 1);
        MBARRIER_INIT(sb + FMB + 16, 1);
    }
    __syncthreads();
    if (tid == 0) {
        MBARRIER_EXPECT_TX(sb + FMB + 16, QOP);
        BULK_LD(sb + QOFF, (const char*)g_qh + bbase + (size_t)qrow0 * 144, QOP, sb + FMB + 16);
        MBARRIER_EXPECT_TX(sb + FMB, FSTAGE);
        BULK_LD(sb,       (const char*)g_kh + bbase, FOP, sb + FMB);
        BULK_LD(sb + FOP, (const char*)g_vh + bbase, FOP, sb + FMB);
    }

    float o[8][4];
#pragma unroll
    for (int ni = 0; ni < 8; ni++)
#pragma unroll
        for (int e = 0; e < 4; e++) o[ni][e] = 0.f;
    float m0 = -1e30f, m1 = -1e30f, l0 = 0.f, l1 = 0.f;

    const int a_off = (w * 16 + (lane & 15)) * FSTR + (lane >> 4) * 16;
    const int b_off = ((lane & 7) + ((lane >> 4) << 3)) * FSTR +
                      ((lane >> 3) & 1) * 16;
    const int t_off = (lane & 15) * FSTR + ((lane >> 4) << 3) * 2;

    MBARRIER_WAIT_PARITY(sb + FMB + 16, 0);

    int ph0 = 0, ph1 = 0;
    for (int it = 0; it < nit; it++) {
        const int s = it & 1;
        const int krow0 = it * 64;
        const uint32_t stg = sb + s * FSTAGE;

        if (it + 1 < nit && tid == 0) {
            const size_t ko = bbase + (size_t)(it + 1) * 64 * 144;
            const uint32_t mb = sb + FMB + (s ^ 1) * 8;
            const uint32_t d = sb + (s ^ 1) * FSTAGE;
            MBARRIER_EXPECT_TX(mb, FSTAGE);
            BULK_LD(d,       (const char*)g_kh + ko, FOP, mb);
            BULK_LD(d + FOP, (const char*)g_vh + ko, FOP, mb);
        }
        if (tid < 64)
            biasp[s * 64 + tid] =
                (kpm[b * SEQ + krow0 + tid] != 0) ? 0.f : -1e30f;

        if (s == 0) { MBARRIER_WAIT_PARITY(sb + FMB, ph0); ph0 ^= 1; }
        else        { MBARRIER_WAIT_PARITY(sb + FMB + 8, ph1); ph1 ^= 1; }
        __syncthreads();

        // ---- S = Q K^T: 1 MMA per fragment ----
        float sc[8][4];
#pragma unroll
        for (int ni = 0; ni < 8; ni++)
#pragma unroll
            for (int e = 0; e < 4; e++) sc[ni][e] = 0.f;

#pragma unroll
        for (int kd = 0; kd < 4; kd++) {
            uint32_t qfh[4];
            ldsm4(qfh, sb + QOFF + a_off + kd * 32);
            uint32_t kh[4][4];
#pragma unroll
            for (int g = 0; g < 4; g++)
                ldsm4(kh[g], stg + b_off + kd * 32 + g * 16 * FSTR);
#pragma unroll
            for (int ni = 0; ni < 8; ni++) {
                const int g = ni >> 1, sel = (ni & 1) * 2;
                mma_f16(sc[ni], qfh, &kh[g][sel]);
            }
        }

        // ---- bias + causal mask ----
#pragma unroll
        for (int ni = 0; ni < 8; ni++) {
            float2 bb = *reinterpret_cast<float2*>(&biasp[s * 64 + ni * 8 + 2 * tig]);
            sc[ni][0] += bb.x; sc[ni][1] += bb.y;
            sc[ni][2] += bb.x; sc[ni][3] += bb.y;
        }
        if (krow0 + 63 > qrow0) {
            const int r0 = qrow0 + w * 16 + grp;
            const int r1 = r0 + 8;
#pragma unroll
            for (int ni = 0; ni < 8; ni++) {
                int c0 = krow0 + ni * 8 + 2 * tig;
                if (c0 > r0) sc[ni][0] = -1e30f;
                if (c0 + 1 > r0) sc[ni][1] = -1e30f;
                if (c0 > r1) sc[ni][2] = -1e30f;
                if (c0 + 1 > r1) sc[ni][3] = -1e30f;
            }
        }

        // ---- online softmax (log2 domain) ----
        float mx0 = -1e30f, mx1 = -1e30f;
#pragma unroll
        for (int ni = 0; ni < 8; ni++) {
            mx0 = fmaxf(mx0, fmaxf(sc[ni][0], sc[ni][1]));
            mx1 = fmaxf(mx1, fmaxf(sc[ni][2], sc[ni][3]));
        }
        mx0 = fmaxf(mx0, __shfl_xor_sync(0xffffffffu, mx0, 1));
        mx0 = fmaxf(mx0, __shfl_xor_sync(0xffffffffu, mx0, 2));
        mx1 = fmaxf(mx1, __shfl_xor_sync(0xffffffffu, mx1, 1));
        mx1 = fmaxf(mx1, __shfl_xor_sync(0xffffffffu, mx1, 2));
        float mn0 = fmaxf(m0, mx0), mn1 = fmaxf(m1, mx1);
        float cr0 = fexp2(m0 - mn0);
        float cr1 = fexp2(m1 - mn1);
        m0 = mn0; m1 = mn1;
#pragma unroll
        for (int ni = 0; ni < 8; ni++) {
            o[ni][0] *= cr0; o[ni][1] *= cr0;
            o[ni][2] *= cr1; o[ni][3] *= cr1;
        }

        // ---- exp/pack interleaved with PV MMAs ----
        float rs0 = 0.f, rs1 = 0.f;
        uint32_t pa[2][4];
#pragma unroll
        for (int kc = 0; kc < 5; kc++) {
            if (kc < 4) {
                const int par = kc & 1;
#pragma unroll
                for (int j = 0; j < 2; j++) {
                    const int ni = 2 * kc + j;
                    float p0 = fexp2(sc[ni][0] - mn0);
                    float p1 = fexp2(sc[ni][1] - mn0);
                    float p2 = fexp2(sc[ni][2] - mn1);
                    float p3 = fexp2(sc[ni][3] - mn1);
                    rs0 += p0 + p1; rs1 += p2 + p3;
                    pa[par][j * 2]     = pack_f16(p0, p1);
                    pa[par][j * 2 + 1] = pack_f16(p2, p3);
                }
            }
            if (kc > 0) {
                const int kcm = kc - 1;
                const int par = kcm & 1;
                uint32_t vh[4][4];
#pragma unroll
                for (int g = 0; g < 4; g++)
                    ldsm4t(vh[g], stg + FOP + kcm * 16 * FSTR + t_off + g * 32);
#pragma unroll
                for (int ni = 0; ni < 8; ni++) {
                    const int g = ni >> 1, sel = (ni & 1) * 2;
                    mma_f16(o[ni], pa[par], &vh[g][sel]);
                }
            }
        }
        rs0 += __shfl_xor_sync(0xffffffffu, rs0, 1);
        rs0 += __shfl_xor_sync(0xffffffffu, rs0, 2);
        rs1 += __shfl_xor_sync(0xffffffffu, rs1, 1);
        rs1 += __shfl_xor_sync(0xffffffffu, rs1, 2);
        l0 = l0 * cr0 + rs0;
        l1 = l1 * cr1 + rs1;
        __syncthreads();
    }

    // ---- epilogue: /l, query padding, fp16 hi k-blocked [kb][m][80B] ----
    const int r0 = qrow0 + w * 16 + grp;
    const int r1 = r0 + 8;
    float f0 = (l0 > 0.f ? 1.0f / l0 : 0.f) * (float)qpm[b * SEQ + r0];
    float f1 = (l1 > 0.f ? 1.0f / l1 : 0.f) * (float)qpm[b * SEQ + r1];
    const size_t m0r = (size_t)(b * SEQ + r0);
    const size_t m1r = (size_t)(b * SEQ + r1);
#pragma unroll
    for (int ni = 0; ni < 8; ni++) {
        int col = h * HD + ni * 8 + 2 * tig;
        size_t kslab = (size_t)(col >> 5) * ((size_t)MTOT * 80) +
                       (size_t)(col & 31) * 2;
        *reinterpret_cast<uint32_t*>(g_aoh + kslab + m0r * 80) =
            pack_f16(o[ni][0] * f0, o[ni][1] * f0);
        *reinterpret_cast<uint32_t*>(g_aoh + kslab + m1r * 80) =
            pack_f16(o[ni][2] * f1, o[ni][3] * f1);
    }
}

// ---------------- launch -----------------------------------------------------
extern "C" void kernel_launch(void* const* d_in, const int* in_sizes, int n_in,
                              void* d_out, int out_size) {
    const float* q   = (const float*)d_in[0];
    const float* k   = (const float*)d_in[1];
    const float* v   = (const float*)d_in[2];
    const int*   qpm = (const int*)d_in[3];
    const int*   kpm = (const int*)d_in[4];
    const float* Wq  = (const float*)d_in[5];
    const float* Wk  = (const float*)d_in[6];
    const float* Wv  = (const float*)d_in[7];
    const float* Wo  = (const float*)d_in[8];
    float* out = (float*)d_out;

    dim3 gs((MTOT * DM) / (256 * 4), 1, 3);
    split_act_kernel<<<gs, 256>>>(q, k, v);
    split_w_kernel<<<dim3(32, 32, 4), 256>>>(Wq, Wk, Wv, Wo);

    cudaFuncSetAttribute(gemm_qkv_kernel,
                         cudaFuncAttributeMaxDynamicSharedMemorySize, GEMM_SMEM);
    cudaFuncSetAttribute(gemm_o_kernel,
                         cudaFuncAttributeMaxDynamicSharedMemorySize, GEMM_SMEM);
    gemm_qkv_kernel<<<dim3(DM / 128, MTOT / 128, 3), 256, GEMM_SMEM>>>();

    cudaFuncSetAttribute(flash_kernel,
                         cudaFuncAttributeMaxDynamicSharedMemorySize, FLASH_SMEM);
    flash_kernel<<<dim3(SEQ / 128, NB * NH), 256, FLASH_SMEM>>>(qpm, kpm);

    gemm_o_kernel<<<dim3(DM / 128, MTOT / 128), 256, GEMM_SMEM>>>(out);
}